// round 6
// baseline (speedup 1.0000x reference)
#include <cuda_runtime.h>
#include <cuda_bf16.h>

#define NN   2048
#define TT   32
#define FIN  5
#define HH   64
#define NB   16
#define NBLK 128
#define NWRD 64

// ---- smem byte offsets ----
#define ZROWB    272
#define STAGE_HI 0                      // 256x128 bf16 = 65536 (permuted rows)
#define STAGE_LO 65536
#define Z0HI     131072                 // 16 x 272 = 4352 each
#define Z0LO     135424
#define Z1HI     139776
#define Z1LO     144128
#define BIAS_OFF 148480                 // 256 f32
#define XS_OFF   149504                 // layer0 xs: 32x5x16 f32 = 10240
#define HFIN_OFF 159744                 // layer1: 64x16 f32 = 4096
#define SMEM_REQ 164096

// -------- scratch (device globals) --------
__device__ unsigned long long g_h0hi[(size_t)TT * NBLK * 256]; // [t][blk][nb*16+q] 4 bf16
__device__ unsigned long long g_h0lo[(size_t)TT * NBLK * 256];
__device__ unsigned g_adjT[NN * NWRD];
__device__ float g_h1[NN * 16];
__device__ float g_s1[NN], g_d1[NN];
__device__ float g_h2[NN * HH];
__device__ float g_s2[NN], g_d2[NN];

// -------- helpers --------
__device__ __forceinline__ unsigned smem_u32(const void* p) {
    unsigned a;
    asm("{ .reg .u64 t; cvta.to.shared.u64 t, %1; cvt.u32.u64 %0, t; }" : "=r"(a) : "l"(p));
    return a;
}
__device__ __forceinline__ float sigm(float x)   { return 1.f / (1.f + __expf(-x)); }
__device__ __forceinline__ float tanh_f(float x) { return 1.f - 2.f / (__expf(2.f * x) + 1.f); }
__device__ __forceinline__ float lrelu(float x)  { return x >= 0.f ? x : 0.2f * x; }

__device__ __forceinline__ void split_bf(float v, unsigned short& hi, unsigned short& lo) {
    __nv_bfloat16 h = __float2bfloat16(v);
    __nv_bfloat16 l = __float2bfloat16(v - __bfloat162float(h));
    hi = __bfloat16_as_ushort(h);
    lo = __bfloat16_as_ushort(l);
}
__device__ __forceinline__ void mma_bf16(float* d, const unsigned* a, unsigned b0, unsigned b1) {
    asm volatile(
        "mma.sync.aligned.m16n8k16.row.col.f32.bf16.bf16.f32 "
        "{%0,%1,%2,%3}, {%4,%5,%6,%7}, {%8,%9}, {%0,%1,%2,%3};"
        : "+f"(d[0]), "+f"(d[1]), "+f"(d[2]), "+f"(d[3])
        : "r"(a[0]), "r"(a[1]), "r"(a[2]), "r"(a[3]), "r"(b0), "r"(b1));
}
__device__ __forceinline__ void ldmx4(unsigned addr, unsigned* r) {
    asm volatile("ldmatrix.sync.aligned.m8n8.x4.shared.b16 {%0,%1,%2,%3}, [%4];"
                 : "=r"(r[0]), "=r"(r[1]), "=r"(r[2]), "=r"(r[3]) : "r"(addr));
}

extern __shared__ float4 smemv[];

// ================= HMMA LSTM layer, gate-permuted, transpose-free =================
// 512 threads = 16 warps. Warp w's m16 tile rows r: gate = (r>>2)*64 + 4w + (r&3)
// so rows 0-3 = i, 4-7 = f, 8-11 = g, 12-15 = o for j in [4w, 4w+4).
__global__ void __launch_bounds__(512, 1) k_lstm_mma(
    int layer,
    const float* __restrict__ inputs,
    const float* __restrict__ w_ih, const float* __restrict__ w_hh,
    const float* __restrict__ b_ih, const float* __restrict__ b_hh,
    const float* __restrict__ gat1_W, const float* __restrict__ gat1_as,
    const float* __restrict__ gat1_ad)
{
    char* smp = (char*)smemv;
    unsigned sbu = smem_u32(smemv);

    int tid  = threadIdx.x;
    int wid  = tid >> 5;
    int lane = tid & 31;
    int blk  = blockIdx.x;
    int n0   = blk * NB;

    // zero staging + both Z buffers
    {
        float4 z4 = make_float4(0.f, 0.f, 0.f, 0.f);
        float4* dst = (float4*)smp;
        for (int i = tid; i < 148480 / 16; i += 512) dst[i] = z4;
    }
    __syncthreads();

    // ---- stage W hi/lo with gate-row permutation ----
    // srow(gate) = ((gate & 63) >> 2) * 16 + (gate >> 6) * 4 + (gate & 3)
    int kw = (layer == 0) ? FIN : HH;
    for (int idx = tid; idx < 256 * kw; idx += 512) {
        int gate = idx / kw, k = idx % kw;
        int srow = ((gate & 63) >> 2) * 16 + (gate >> 6) * 4 + (gate & 3);
        unsigned short hi, lo;
        split_bf(w_ih[idx], hi, lo);
        *(unsigned short*)(smp + STAGE_HI + (srow * 128 + k) * 2) = hi;
        *(unsigned short*)(smp + STAGE_LO + (srow * 128 + k) * 2) = lo;
    }
    for (int idx = tid; idx < 256 * HH; idx += 512) {
        int gate = idx >> 6, k = idx & 63;
        int srow = ((gate & 63) >> 2) * 16 + (gate >> 6) * 4 + (gate & 3);
        unsigned short hi, lo;
        split_bf(w_hh[idx], hi, lo);
        *(unsigned short*)(smp + STAGE_HI + (srow * 128 + 64 + k) * 2) = hi;
        *(unsigned short*)(smp + STAGE_LO + (srow * 128 + 64 + k) * 2) = lo;
    }
    float* bias_s = (float*)(smp + BIAS_OFF);
    if (tid < 256) bias_s[tid] = b_ih[tid] + b_hh[tid];

    float* xs = (float*)(smp + XS_OFF);
    uint2 pf = make_uint2(0u, 0u);
    if (layer == 0) {
        for (int idx = tid; idx < NB * TT * FIN; idx += 512) {
            int nb = idx / (TT * FIN);
            int r  = idx % (TT * FIN);
            int t  = r / FIN, f = r % FIN;
            xs[t * 80 + f * 16 + nb] = inputs[(size_t)(n0 + nb) * (TT * FIN) + t * FIN + f];
        }
        if (tid < 80) {
            int f = tid >> 4, nb = tid & 15;
            unsigned short hi, lo;
            split_bf(inputs[(size_t)(n0 + nb) * (TT * FIN) + f], hi, lo);
            *(unsigned short*)(smp + Z0HI + nb * ZROWB + f * 2) = hi;
            *(unsigned short*)(smp + Z0LO + nb * ZROWB + f * 2) = lo;
        }
    } else {
        int half = tid >> 8, r = tid & 255;
        int nb = r >> 4, q = r & 15;
        const uint2* src = (const uint2*)(half ? (void*)g_h0lo : (void*)g_h0hi);
        uint2 v0 = src[(size_t)blk * 256 + r];
        *(uint2*)(smp + (half ? Z0LO : Z0HI) + nb * ZROWB + q * 8) = v0;
        pf = src[((size_t)NBLK + blk) * 256 + r];
    }
    __syncthreads();

    // ---- load W fragments (permuted rows already) ----
    unsigned whi[8][4], wlo[8][4];
    {
        int g0 = wid * 16 + (lane >> 2);
        int kp = (lane & 3) * 2;
        #pragma unroll
        for (int kt = 0; kt < 8; ++kt) {
            const char* bh = smp + STAGE_HI + (g0 * 128 + kt * 16 + kp) * 2;
            whi[kt][0] = *(const unsigned*)(bh);
            whi[kt][1] = *(const unsigned*)(bh + 2048);
            whi[kt][2] = *(const unsigned*)(bh + 16);
            whi[kt][3] = *(const unsigned*)(bh + 2048 + 16);
            const char* bl = smp + STAGE_LO + (g0 * 128 + kt * 16 + kp) * 2;
            wlo[kt][0] = *(const unsigned*)(bl);
            wlo[kt][1] = *(const unsigned*)(bl + 2048);
            wlo[kt][2] = *(const unsigned*)(bl + 16);
            wlo[kt][3] = *(const unsigned*)(bl + 2048 + 16);
        }
    }
    int q = lane >> 2, s = lane & 3;
    // bias for my rows q and q+8 (permuted gates)
    float bv0 = bias_s[(q < 4 ? 0 : 64)  + 4 * wid + (q & 3)];
    float bv1 = bias_s[(q < 4 ? 128 : 192) + 4 * wid + (q & 3)];

    // ldmatrix lane addressing within a Z tile
    int nrow  = (lane & 7) + ((lane >> 4) << 3);
    int khalf = (lane >> 3) & 1;
    unsigned zrel = nrow * ZROWB + khalf * 16;

    float* hfin = (float*)(smp + HFIN_OFF);
    int jp = 4 * wid + (q & 3);
    int nbA = (q < 4) ? 2 * s : 8 + 2 * s;
    int nbB = nbA + 1;
    float c0 = 0.f, c1 = 0.f;
    __syncthreads();

    #pragma unroll 1
    for (int t = 0; t < TT; ++t) {
        int p = t & 1;
        unsigned zhiB = sbu + (p ? Z1HI : Z0HI);
        unsigned zloB = sbu + (p ? Z1LO : Z0LO);
        unsigned zhiN = sbu + (p ? Z0HI : Z1HI);
        unsigned zloN = sbu + (p ? Z0LO : Z1LO);

        // layer0: export h(t-1) from current read buffer (concurrent with MMA reads)
        if (layer == 0 && t > 0) {
            int half = tid >> 8, r = tid & 255;
            int nb = r >> 4, qq = r & 15;
            uint2 v = *(const uint2*)(smp + ((half ? (p ? Z1LO : Z0LO) : (p ? Z1HI : Z0HI)))
                                      + nb * ZROWB + 128 + qq * 8);
            ((uint2*)(half ? (void*)g_h0lo : (void*)g_h0hi))
                [((size_t)(t - 1) * NBLK + blk) * 256 + r] = v;
        }

        float accA[2][4], accB[2][4];
        #pragma unroll
        for (int nt = 0; nt < 2; ++nt) {
            accA[nt][0] = bv0; accA[nt][1] = bv0; accA[nt][2] = bv1; accA[nt][3] = bv1;
            accB[nt][0] = 0.f; accB[nt][1] = 0.f; accB[nt][2] = 0.f; accB[nt][3] = 0.f;
        }
        #pragma unroll
        for (int kt = 0; kt < 8; ++kt) {
            unsigned bh[4], bl[4];
            ldmx4(zhiB + zrel + kt * 32, bh);
            ldmx4(zloB + zrel + kt * 32, bl);
            mma_bf16(accA[0], whi[kt], bh[0], bh[1]);
            mma_bf16(accA[1], whi[kt], bh[2], bh[3]);
            mma_bf16(accB[0], wlo[kt], bh[0], bh[1]);
            mma_bf16(accB[1], wlo[kt], bh[2], bh[3]);
            mma_bf16(accB[0], whi[kt], bl[0], bl[1]);
            mma_bf16(accB[1], whi[kt], bl[2], bl[3]);
        }

        // in-warp gate gather: pair (q) <-> (q+4) via shfl.xor 16
        float accS[8], pp[8];
        #pragma unroll
        for (int i = 0; i < 4; ++i) {
            accS[i]     = accA[0][i] + accB[0][i];
            accS[4 + i] = accA[1][i] + accB[1][i];
        }
        #pragma unroll
        for (int i = 0; i < 8; ++i) pp[i] = __shfl_xor_sync(~0u, accS[i], 16);

        float iA, fA, gA, oA, iB, fB, gB, oB;
        if (q < 4) {
            iA = accS[0]; gA = accS[2]; fA = pp[0]; oA = pp[2];
            iB = accS[1]; gB = accS[3]; fB = pp[1]; oB = pp[3];
        } else {
            iA = pp[4]; gA = pp[6]; fA = accS[4]; oA = accS[6];
            iB = pp[5]; gB = pp[7]; fB = accS[5]; oB = accS[7];
        }
        c0 = sigm(fA) * c0 + sigm(iA) * tanh_f(gA);
        c1 = sigm(fB) * c1 + sigm(iB) * tanh_f(gB);
        float h0v = sigm(oA) * tanh_f(c0);
        float h1v = sigm(oB) * tanh_f(c1);

        if (layer == 1 && t == TT - 1) {
            hfin[jp * 16 + nbA] = h0v;
            hfin[jp * 16 + nbB] = h1v;
        } else {
            unsigned short h0h, h0l, h1h, h1l;
            split_bf(h0v, h0h, h0l);
            split_bf(h1v, h1h, h1l);
            *(unsigned short*)((char*)smemv + (zhiN - sbu) + nbA * ZROWB + (64 + jp) * 2) = h0h;
            *(unsigned short*)((char*)smemv + (zloN - sbu) + nbA * ZROWB + (64 + jp) * 2) = h0l;
            *(unsigned short*)((char*)smemv + (zhiN - sbu) + nbB * ZROWB + (64 + jp) * 2) = h1h;
            *(unsigned short*)((char*)smemv + (zloN - sbu) + nbB * ZROWB + (64 + jp) * 2) = h1l;
        }

        if (layer == 0) {
            if (t + 1 < TT && tid < 80) {
                int f = tid >> 4, nb = tid & 15;
                unsigned short hi, lo;
                split_bf(xs[(t + 1) * 80 + f * 16 + nb], hi, lo);
                *(unsigned short*)((char*)smemv + (zhiN - sbu) + nb * ZROWB + f * 2) = hi;
                *(unsigned short*)((char*)smemv + (zloN - sbu) + nb * ZROWB + f * 2) = lo;
            }
        } else if (t + 1 < TT) {
            int half = tid >> 8, r = tid & 255;
            int nb = r >> 4, qq = r & 15;
            *(uint2*)((char*)smemv + ((half ? zloN : zhiN) - sbu) + nb * ZROWB + qq * 8) = pf;
            if (t + 2 < TT)
                pf = ((const uint2*)(half ? (void*)g_h0lo : (void*)g_h0hi))
                         [((size_t)(t + 2) * NBLK + blk) * 256 + r];
        }
        __syncthreads();
    }

    if (layer == 0) {
        // final export: h(TT-1) lives in buf (TT & 1) = 0
        int half = tid >> 8, r = tid & 255;
        int nb = r >> 4, qq = r & 15;
        uint2 v = *(const uint2*)(smp + (half ? Z0LO : Z0HI) + nb * ZROWB + 128 + qq * 8);
        ((uint2*)(half ? (void*)g_h0lo : (void*)g_h0hi))
            [((size_t)(TT - 1) * NBLK + blk) * 256 + r] = v;
    } else {
        // fused GAT1 projection
        float* W1s = (float*)(smp + STAGE_HI);   // staging dead, reuse
        float* asv = W1s + HH * 16;
        float* adv = asv + 16;
        float* h1b = adv + 16;
        for (int idx = tid; idx < HH * 16; idx += 512) W1s[idx] = gat1_W[idx];
        if (tid < 32) {
            if (tid < 16) asv[tid] = gat1_as[tid];
            else          adv[tid - 16] = gat1_ad[tid - 16];
        }
        __syncthreads();
        if (tid < 256) {
            int nb = tid & 15, jj = tid >> 4;
            float hv = 0.f;
            #pragma unroll
            for (int k = 0; k < HH; ++k) hv += hfin[k * 16 + nb] * W1s[k * 16 + jj];
            h1b[nb * 16 + jj] = hv;
            g_h1[(size_t)(n0 + nb) * 16 + jj] = hv;
        }
        __syncthreads();
        if (tid < 32) {
            int nb = tid & 15;
            const float* av = (tid < 16) ? asv : adv;
            float sv = 0.f;
            #pragma unroll
            for (int jj = 0; jj < 16; ++jj) sv += h1b[nb * 16 + jj] * av[jj];
            if (tid < 16) g_s1[n0 + nb] = sv; else g_d1[n0 + nb] = sv;
        }
    }
}

// ================= adjacency bitmask =================
__global__ void k_adj(const float* __restrict__ rel_mask) {
    int j  = blockIdx.x * 256 + threadIdx.x;
    int c0 = blockIdx.y * 4;
    for (int c = c0; c < c0 + 4; ++c) {
        unsigned w = 0;
        #pragma unroll 8
        for (int b = 0; b < 32; ++b) {
            int i = c * 32 + b;
            float v = rel_mask[(size_t)i * NN + j];
            if (v > -1.f || i == j) w |= (1u << b);
        }
        g_adjT[j * NWRD + c] = w;
    }
}

// ================= GAT1 aggregate + fused GAT2 projection =================
__global__ void __launch_bounds__(256) k_gmain1(const float* __restrict__ b1,
                                                const float* __restrict__ W2,
                                                const float* __restrict__ as2,
                                                const float* __restrict__ ad2)
{
    __shared__ float W2s[16 * 64], a2s[64], a2d[64], ob[8][16];
    int tid = threadIdx.x;
    for (int i = tid; i < 16 * 64; i += 256) W2s[i] = W2[i];
    if (tid < 64) { a2s[tid] = as2[tid]; a2d[tid] = ad2[tid]; }
    __syncthreads();

    int warp = tid >> 5, lane = tid & 31;
    int j = blockIdx.x * 8 + warp;
    float dj = g_d1[j];
    const unsigned* adjw = &g_adjT[j * NWRD];

    float m = -1e30f, ssum = 0.f;
    for (int c = lane; c < NWRD; c += 32) {
        unsigned w = adjw[c];
        while (w) {
            int b = __ffs(w) - 1; w &= w - 1;
            int i = c * 32 + b;
            float e = lrelu(g_s1[i] + dj);
            if (e > m) { ssum = ssum * __expf(m - e) + 1.f; m = e; }
            else         ssum += __expf(e - m);
        }
    }
    float M = m;
    #pragma unroll
    for (int o = 16; o; o >>= 1) M = fmaxf(M, __shfl_xor_sync(~0u, M, o));
    ssum *= __expf(m - M);
    #pragma unroll
    for (int o = 16; o; o >>= 1) ssum += __shfl_xor_sync(~0u, ssum, o);
    float inv = 1.f / ssum;

    float acc[16];
    #pragma unroll
    for (int h = 0; h < 16; ++h) acc[h] = 0.f;
    for (int c = lane * 2; c < lane * 2 + 2; ++c) {
        unsigned w = adjw[c];
        while (w) {
            int b = __ffs(w) - 1; w &= w - 1;
            int i = c * 32 + b;
            float al = __expf(lrelu(g_s1[i] + dj) - M) * inv;
            const float4* hp = (const float4*)&g_h1[i * 16];
            float4 v0 = hp[0], v1 = hp[1], v2 = hp[2], v3 = hp[3];
            acc[0] += al * v0.x; acc[1] += al * v0.y; acc[2]  += al * v0.z; acc[3]  += al * v0.w;
            acc[4] += al * v1.x; acc[5] += al * v1.y; acc[6]  += al * v1.z; acc[7]  += al * v1.w;
            acc[8] += al * v2.x; acc[9] += al * v2.y; acc[10] += al * v2.z; acc[11] += al * v2.w;
            acc[12] += al * v3.x; acc[13] += al * v3.y; acc[14] += al * v3.z; acc[15] += al * v3.w;
        }
    }
    #pragma unroll
    for (int h = 0; h < 16; ++h) {
        #pragma unroll
        for (int o = 16; o; o >>= 1) acc[h] += __shfl_xor_sync(~0u, acc[h], o);
    }
    if (lane < 16) {
        float v = acc[lane] + b1[lane];
        ob[warp][lane] = v > 0.f ? v : 0.f;
    }
    __syncwarp();

    float o[16];
    #pragma unroll
    for (int k = 0; k < 16; ++k) o[k] = ob[warp][k];
    float hv0 = 0.f, hv1 = 0.f;
    #pragma unroll
    for (int k = 0; k < 16; ++k) {
        hv0 += o[k] * W2s[k * 64 + lane];
        hv1 += o[k] * W2s[k * 64 + lane + 32];
    }
    g_h2[(size_t)j * 64 + lane]      = hv0;
    g_h2[(size_t)j * 64 + lane + 32] = hv1;
    float sp = hv0 * a2s[lane] + hv1 * a2s[lane + 32];
    float dp = hv0 * a2d[lane] + hv1 * a2d[lane + 32];
    #pragma unroll
    for (int oo = 16; oo; oo >>= 1) {
        sp += __shfl_xor_sync(~0u, sp, oo);
        dp += __shfl_xor_sync(~0u, dp, oo);
    }
    if (lane == 0) { g_s2[j] = sp; g_d2[j] = dp; }
}

// ================= GAT2 aggregate + FC =================
__global__ void __launch_bounds__(256) k_gmain2(const float* __restrict__ b2,
                                                const float* __restrict__ fcW,
                                                const float* __restrict__ fcb,
                                                float* __restrict__ out)
{
    int warp = threadIdx.x >> 5, lane = threadIdx.x & 31;
    int j = blockIdx.x * 8 + warp;
    float dj = g_d2[j];
    const unsigned* adjw = &g_adjT[j * NWRD];

    float m = -1e30f, ssum = 0.f;
    for (int c = lane; c < NWRD; c += 32) {
        unsigned w = adjw[c];
        while (w) {
            int b = __ffs(w) - 1; w &= w - 1;
            int i = c * 32 + b;
            float e = lrelu(g_s2[i] + dj);
            if (e > m) { ssum = ssum * __expf(m - e) + 1.f; m = e; }
            else         ssum += __expf(e - m);
        }
    }
    float M = m;
    #pragma unroll
    for (int o = 16; o; o >>= 1) M = fmaxf(M, __shfl_xor_sync(~0u, M, o));
    ssum *= __expf(m - M);
    #pragma unroll
    for (int o = 16; o; o >>= 1) ssum += __shfl_xor_sync(~0u, ssum, o);
    float inv = 1.f / ssum;

    float a0 = 0.f, a1 = 0.f;
    for (int c = 0; c < NWRD; ++c) {
        unsigned w = adjw[c];
        while (w) {
            int b = __ffs(w) - 1; w &= w - 1;
            int i = c * 32 + b;
            float e = lrelu(g_s2[i] + dj);
            float al = __expf(e - M) * inv;
            a0 += al * g_h2[(size_t)i * 64 + lane];
            a1 += al * g_h2[(size_t)i * 64 + lane + 32];
        }
    }
    float part = (a0 + b2[lane]) * fcW[lane] + (a1 + b2[lane + 32]) * fcW[lane + 32];
    #pragma unroll
    for (int o = 16; o; o >>= 1) part += __shfl_xor_sync(~0u, part, o);
    if (lane == 0) out[j] = lrelu(part + fcb[0]);
}

// ================= launch =================
extern "C" void kernel_launch(void* const* d_in, const int* in_sizes, int n_in,
                              void* d_out, int out_size)
{
    const float* inputs   = (const float*)d_in[0];
    // d_in[1] relation, d_in[3] rel_w_W, d_in[4] rel_w_b: provably unused (adj = mask|diag)
    const float* rel_mask = (const float*)d_in[2];
    const float* w_ih0 = (const float*)d_in[5];
    const float* w_hh0 = (const float*)d_in[6];
    const float* b_ih0 = (const float*)d_in[7];
    const float* b_hh0 = (const float*)d_in[8];
    const float* w_ih1 = (const float*)d_in[9];
    const float* w_hh1 = (const float*)d_in[10];
    const float* b_ih1 = (const float*)d_in[11];
    const float* b_hh1 = (const float*)d_in[12];
    const float* gat1_W  = (const float*)d_in[13];
    const float* gat1_as = (const float*)d_in[14];
    const float* gat1_ad = (const float*)d_in[15];
    const float* gat1_b  = (const float*)d_in[16];
    const float* gat2_W  = (const float*)d_in[17];
    const float* gat2_as = (const float*)d_in[18];
    const float* gat2_ad = (const float*)d_in[19];
    const float* gat2_b  = (const float*)d_in[20];
    const float* fc_W    = (const float*)d_in[21];
    const float* fc_b    = (const float*)d_in[22];

    cudaFuncSetAttribute(k_lstm_mma, cudaFuncAttributeMaxDynamicSharedMemorySize, SMEM_REQ);

    k_adj<<<dim3(8, 16), 256>>>(rel_mask);
    k_lstm_mma<<<NBLK, 512, SMEM_REQ>>>(0, inputs, w_ih0, w_hh0, b_ih0, b_hh0,
                                        gat1_W, gat1_as, gat1_ad);
    k_lstm_mma<<<NBLK, 512, SMEM_REQ>>>(1, inputs, w_ih1, w_hh1, b_ih1, b_hh1,
                                        gat1_W, gat1_as, gat1_ad);
    k_gmain1<<<NN / 8, 256>>>(gat1_b, gat2_W, gat2_as, gat2_ad);
    k_gmain2<<<NN / 8, 256>>>(gat2_b, fc_W, fc_b, (float*)d_out);
}

// round 7
// speedup vs baseline: 1.5882x; 1.5882x over previous
#include <cuda_runtime.h>
#include <cuda_bf16.h>

#define NN   2048
#define TT   32
#define FIN  5
#define HH   64
#define NB   16
#define NBLK 128
#define NWRD 64

// ---- smem byte offsets ----
#define ZROWB    272
#define STAGE_HI 0                      // 256x128 bf16 = 65536 (permuted rows)
#define STAGE_LO 65536
#define Z0HI     131072                 // 16 x 272 = 4352 each
#define Z0LO     135424
#define Z1HI     139776                 // Z1* = Z0* + 8704
#define Z1LO     144128
#define ZSTRIDE  8704
#define BIAS_OFF 148480                 // 256 f32
#define XS_OFF   149504                 // layer0 xs: 32x5x16 f32 = 10240
#define HFIN_OFF 159744                 // layer1: 64x16 f32 = 4096
#define SMEM_REQ 164096

// -------- scratch (device globals) --------
__device__ unsigned long long g_h0hi[(size_t)TT * NBLK * 256]; // [t][blk][nb*16+q] 4 bf16
__device__ unsigned long long g_h0lo[(size_t)TT * NBLK * 256];
__device__ unsigned g_adjT[NN * NWRD];
__device__ float g_h1[NN * 16];
__device__ float g_s1[NN], g_d1[NN];
__device__ float g_h2[NN * HH];
__device__ float g_s2[NN], g_d2[NN];

// -------- helpers --------
__device__ __forceinline__ unsigned smem_u32(const void* p) {
    unsigned a;
    asm("{ .reg .u64 t; cvta.to.shared.u64 t, %1; cvt.u32.u64 %0, t; }" : "=r"(a) : "l"(p));
    return a;
}
__device__ __forceinline__ float sigm(float x)   { return 1.f / (1.f + __expf(-x)); }
__device__ __forceinline__ float tanh_f(float x) { return 1.f - 2.f / (__expf(2.f * x) + 1.f); }
__device__ __forceinline__ float lrelu(float x)  { return x >= 0.f ? x : 0.2f * x; }

__device__ __forceinline__ void split_bf(float v, unsigned short& hi, unsigned short& lo) {
    __nv_bfloat16 h = __float2bfloat16(v);
    __nv_bfloat16 l = __float2bfloat16(v - __bfloat162float(h));
    hi = __bfloat16_as_ushort(h);
    lo = __bfloat16_as_ushort(l);
}
__device__ __forceinline__ void mma_bf16(float* d, const unsigned* a, unsigned b0, unsigned b1) {
    asm volatile(
        "mma.sync.aligned.m16n8k16.row.col.f32.bf16.bf16.f32 "
        "{%0,%1,%2,%3}, {%4,%5,%6,%7}, {%8,%9}, {%0,%1,%2,%3};"
        : "+f"(d[0]), "+f"(d[1]), "+f"(d[2]), "+f"(d[3])
        : "r"(a[0]), "r"(a[1]), "r"(a[2]), "r"(a[3]), "r"(b0), "r"(b1));
}
__device__ __forceinline__ void ldmx4(unsigned addr, unsigned* r) {
    asm volatile("ldmatrix.sync.aligned.m8n8.x4.shared.b16 {%0,%1,%2,%3}, [%4];"
                 : "=r"(r[0]), "=r"(r[1]), "=r"(r[2]), "=r"(r[3]) : "r"(addr));
}

extern __shared__ float4 smemv[];

// ================= HMMA LSTM layer, gate-permuted, transpose-free =================
// 512 threads = 16 warps. Warp w's m16 tile rows r: gate = (r>>2)*64 + 4w + (r&3).
__global__ void __launch_bounds__(512, 1) k_lstm_mma(
    int layer,
    const float* __restrict__ inputs,
    const float* __restrict__ w_ih, const float* __restrict__ w_hh,
    const float* __restrict__ b_ih, const float* __restrict__ b_hh,
    const float* __restrict__ gat1_W, const float* __restrict__ gat1_as,
    const float* __restrict__ gat1_ad)
{
    char* smp = (char*)smemv;
    unsigned sbu = smem_u32(smemv);

    int tid  = threadIdx.x;
    int wid  = tid >> 5;
    int lane = tid & 31;
    int blk  = blockIdx.x;
    int n0   = blk * NB;

    // zero staging + both Z buffers
    {
        float4 z4 = make_float4(0.f, 0.f, 0.f, 0.f);
        float4* dst = (float4*)smp;
        for (int i = tid; i < 148480 / 16; i += 512) dst[i] = z4;
    }
    __syncthreads();

    // ---- stage W hi/lo with gate-row permutation ----
    int kw = (layer == 0) ? FIN : HH;
    for (int idx = tid; idx < 256 * kw; idx += 512) {
        int gate = idx / kw, k = idx % kw;
        int srow = ((gate & 63) >> 2) * 16 + (gate >> 6) * 4 + (gate & 3);
        unsigned short hi, lo;
        split_bf(w_ih[idx], hi, lo);
        *(unsigned short*)(smp + STAGE_HI + (srow * 128 + k) * 2) = hi;
        *(unsigned short*)(smp + STAGE_LO + (srow * 128 + k) * 2) = lo;
    }
    for (int idx = tid; idx < 256 * HH; idx += 512) {
        int gate = idx >> 6, k = idx & 63;
        int srow = ((gate & 63) >> 2) * 16 + (gate >> 6) * 4 + (gate & 3);
        unsigned short hi, lo;
        split_bf(w_hh[idx], hi, lo);
        *(unsigned short*)(smp + STAGE_HI + (srow * 128 + 64 + k) * 2) = hi;
        *(unsigned short*)(smp + STAGE_LO + (srow * 128 + 64 + k) * 2) = lo;
    }
    float* bias_s = (float*)(smp + BIAS_OFF);
    if (tid < 256) bias_s[tid] = b_ih[tid] + b_hh[tid];

    float* xs = (float*)(smp + XS_OFF);
    uint2 pf = make_uint2(0u, 0u);
    if (layer == 0) {
        for (int idx = tid; idx < NB * TT * FIN; idx += 512) {
            int nb = idx / (TT * FIN);
            int r  = idx % (TT * FIN);
            int t  = r / FIN, f = r % FIN;
            xs[t * 80 + f * 16 + nb] = inputs[(size_t)(n0 + nb) * (TT * FIN) + t * FIN + f];
        }
        if (tid < 80) {
            int f = tid >> 4, nb = tid & 15;
            unsigned short hi, lo;
            split_bf(inputs[(size_t)(n0 + nb) * (TT * FIN) + f], hi, lo);
            *(unsigned short*)(smp + Z0HI + nb * ZROWB + f * 2) = hi;
            *(unsigned short*)(smp + Z0LO + nb * ZROWB + f * 2) = lo;
        }
    } else {
        int half = tid >> 8, r = tid & 255;
        int nb = r >> 4, q = r & 15;
        const uint2* src = (const uint2*)(half ? (void*)g_h0lo : (void*)g_h0hi);
        uint2 v0 = src[(size_t)blk * 256 + r];
        *(uint2*)(smp + (half ? Z0LO : Z0HI) + nb * ZROWB + q * 8) = v0;
        pf = src[((size_t)NBLK + blk) * 256 + r];
    }
    __syncthreads();

    // ---- load W fragments (permuted rows already) ----
    unsigned whi[8][4], wlo[8][4];
    {
        int g0 = wid * 16 + (lane >> 2);
        int kp = (lane & 3) * 2;
        #pragma unroll
        for (int kt = 0; kt < 8; ++kt) {
            const char* bh = smp + STAGE_HI + (g0 * 128 + kt * 16 + kp) * 2;
            whi[kt][0] = *(const unsigned*)(bh);
            whi[kt][1] = *(const unsigned*)(bh + 2048);
            whi[kt][2] = *(const unsigned*)(bh + 16);
            whi[kt][3] = *(const unsigned*)(bh + 2048 + 16);
            const char* bl = smp + STAGE_LO + (g0 * 128 + kt * 16 + kp) * 2;
            wlo[kt][0] = *(const unsigned*)(bl);
            wlo[kt][1] = *(const unsigned*)(bl + 2048);
            wlo[kt][2] = *(const unsigned*)(bl + 16);
            wlo[kt][3] = *(const unsigned*)(bl + 2048 + 16);
        }
    }
    int q = lane >> 2, s = lane & 3;
    float bv0 = bias_s[(q < 4 ? 0 : 64)  + 4 * wid + (q & 3)];
    float bv1 = bias_s[(q < 4 ? 128 : 192) + 4 * wid + (q & 3)];

    int nrow  = (lane & 7) + ((lane >> 4) << 3);
    int khalf = (lane >> 3) & 1;
    unsigned zrel = nrow * ZROWB + khalf * 16;

    float* hfin = (float*)(smp + HFIN_OFF);
    int jp = 4 * wid + (q & 3);
    int nbA = (q < 4) ? 2 * s : 8 + 2 * s;
    int nbB = nbA + 1;
    float c0 = 0.f, c1 = 0.f;
    __syncthreads();

    #pragma unroll 1
    for (int t = 0; t < TT; ++t) {
        unsigned zoffR = (t & 1) ? ZSTRIDE : 0;     // read buffer offset
        unsigned zoffW = (t & 1) ? 0 : ZSTRIDE;     // write buffer offset

        // layer0: export h(t-1) from current read buffer (concurrent with MMA reads)
        if (layer == 0 && t > 0) {
            int half = tid >> 8, r = tid & 255;
            int nb = r >> 4, qq = r & 15;
            uint2 v = *(const uint2*)(smp + (half ? Z0LO : Z0HI) + zoffR
                                      + nb * ZROWB + 128 + qq * 8);
            ((uint2*)(half ? (void*)g_h0lo : (void*)g_h0hi))
                [((size_t)(t - 1) * NBLK + blk) * 256 + r] = v;
        }

        // single merged accumulator pair (reg diet vs R6)
        float acc[2][4];
        acc[0][0] = bv0; acc[0][1] = bv0; acc[0][2] = bv1; acc[0][3] = bv1;
        acc[1][0] = bv0; acc[1][1] = bv0; acc[1][2] = bv1; acc[1][3] = bv1;

        unsigned zhiB = sbu + Z0HI + zoffR + zrel;
        unsigned zloB = sbu + Z0LO + zoffR + zrel;
        #pragma unroll
        for (int kt = 0; kt < 8; ++kt) {
            unsigned bh[4], bl[4];
            ldmx4(zhiB + kt * 32, bh);
            ldmx4(zloB + kt * 32, bl);
            mma_bf16(acc[0], whi[kt], bh[0], bh[1]);
            mma_bf16(acc[1], whi[kt], bh[2], bh[3]);
            mma_bf16(acc[0], wlo[kt], bh[0], bh[1]);
            mma_bf16(acc[1], wlo[kt], bh[2], bh[3]);
            mma_bf16(acc[0], whi[kt], bl[0], bl[1]);
            mma_bf16(acc[1], whi[kt], bl[2], bl[3]);
        }

        // in-warp gate gather via shfl.xor 16 (lane q <-> q+4 rows)
        float pp[8];
        #pragma unroll
        for (int i = 0; i < 4; ++i) {
            pp[i]     = __shfl_xor_sync(~0u, acc[0][i], 16);
            pp[4 + i] = __shfl_xor_sync(~0u, acc[1][i], 16);
        }

        float iA, fA, gA, oA, iB, fB, gB, oB;
        if (q < 4) {
            iA = acc[0][0]; gA = acc[0][2]; fA = pp[0]; oA = pp[2];
            iB = acc[0][1]; gB = acc[0][3]; fB = pp[1]; oB = pp[3];
        } else {
            iA = pp[4]; gA = pp[6]; fA = acc[1][0]; oA = acc[1][2];
            iB = pp[5]; gB = pp[7]; fB = acc[1][1]; oB = acc[1][3];
        }
        c0 = sigm(fA) * c0 + sigm(iA) * tanh_f(gA);
        c1 = sigm(fB) * c1 + sigm(iB) * tanh_f(gB);
        float h0v = sigm(oA) * tanh_f(c0);
        float h1v = sigm(oB) * tanh_f(c1);

        if (layer == 1 && t == TT - 1) {
            hfin[jp * 16 + nbA] = h0v;
            hfin[jp * 16 + nbB] = h1v;
        } else {
            unsigned short h0h, h0l, h1h, h1l;
            split_bf(h0v, h0h, h0l);
            split_bf(h1v, h1h, h1l);
            *(unsigned short*)(smp + Z0HI + zoffW + nbA * ZROWB + (64 + jp) * 2) = h0h;
            *(unsigned short*)(smp + Z0LO + zoffW + nbA * ZROWB + (64 + jp) * 2) = h0l;
            *(unsigned short*)(smp + Z0HI + zoffW + nbB * ZROWB + (64 + jp) * 2) = h1h;
            *(unsigned short*)(smp + Z0LO + zoffW + nbB * ZROWB + (64 + jp) * 2) = h1l;
        }

        if (layer == 0) {
            if (t + 1 < TT && tid < 80) {
                int f = tid >> 4, nb = tid & 15;
                unsigned short hi, lo;
                split_bf(xs[(t + 1) * 80 + f * 16 + nb], hi, lo);
                *(unsigned short*)(smp + Z0HI + zoffW + nb * ZROWB + f * 2) = hi;
                *(unsigned short*)(smp + Z0LO + zoffW + nb * ZROWB + f * 2) = lo;
            }
        } else if (t + 1 < TT) {
            int half = tid >> 8, r = tid & 255;
            int nb = r >> 4, qq = r & 15;
            *(uint2*)(smp + (half ? Z0LO : Z0HI) + zoffW + nb * ZROWB + qq * 8) = pf;
            if (t + 2 < TT)
                pf = ((const uint2*)(half ? (void*)g_h0lo : (void*)g_h0hi))
                         [((size_t)(t + 2) * NBLK + blk) * 256 + r];
        }
        __syncthreads();
    }

    if (layer == 0) {
        // final export: h(TT-1) lives in buf (TT & 1) = 0
        int half = tid >> 8, r = tid & 255;
        int nb = r >> 4, qq = r & 15;
        uint2 v = *(const uint2*)(smp + (half ? Z0LO : Z0HI) + nb * ZROWB + 128 + qq * 8);
        ((uint2*)(half ? (void*)g_h0lo : (void*)g_h0hi))
            [((size_t)(TT - 1) * NBLK + blk) * 256 + r] = v;
    } else {
        // fused GAT1 projection
        float* W1s = (float*)(smp + STAGE_HI);
        float* asv = W1s + HH * 16;
        float* adv = asv + 16;
        float* h1b = adv + 16;
        for (int idx = tid; idx < HH * 16; idx += 512) W1s[idx] = gat1_W[idx];
        if (tid < 32) {
            if (tid < 16) asv[tid] = gat1_as[tid];
            else          adv[tid - 16] = gat1_ad[tid - 16];
        }
        __syncthreads();
        if (tid < 256) {
            int nb = tid & 15, jj = tid >> 4;
            float hv = 0.f;
            #pragma unroll
            for (int k = 0; k < HH; ++k) hv += hfin[k * 16 + nb] * W1s[k * 16 + jj];
            h1b[nb * 16 + jj] = hv;
            g_h1[(size_t)(n0 + nb) * 16 + jj] = hv;
        }
        __syncthreads();
        if (tid < 32) {
            int nb = tid & 15;
            const float* av = (tid < 16) ? asv : adv;
            float sv = 0.f;
            #pragma unroll
            for (int jj = 0; jj < 16; ++jj) sv += h1b[nb * 16 + jj] * av[jj];
            if (tid < 16) g_s1[n0 + nb] = sv; else g_d1[n0 + nb] = sv;
        }
    }
}

// ================= adjacency bitmask =================
__global__ void k_adj(const float* __restrict__ rel_mask) {
    int j  = blockIdx.x * 256 + threadIdx.x;
    int c0 = blockIdx.y * 4;
    for (int c = c0; c < c0 + 4; ++c) {
        unsigned w = 0;
        #pragma unroll 8
        for (int b = 0; b < 32; ++b) {
            int i = c * 32 + b;
            float v = rel_mask[(size_t)i * NN + j];
            if (v > -1.f || i == j) w |= (1u << b);
        }
        g_adjT[j * NWRD + c] = w;
    }
}

// ================= GAT1 aggregate + fused GAT2 projection =================
__global__ void __launch_bounds__(256) k_gmain1(const float* __restrict__ b1,
                                                const float* __restrict__ W2,
                                                const float* __restrict__ as2,
                                                const float* __restrict__ ad2)
{
    __shared__ float W2s[16 * 64], a2s[64], a2d[64], ob[8][16];
    int tid = threadIdx.x;
    for (int i = tid; i < 16 * 64; i += 256) W2s[i] = W2[i];
    if (tid < 64) { a2s[tid] = as2[tid]; a2d[tid] = ad2[tid]; }
    __syncthreads();

    int warp = tid >> 5, lane = tid & 31;
    int j = blockIdx.x * 8 + warp;
    float dj = g_d1[j];
    const unsigned* adjw = &g_adjT[j * NWRD];

    float m = -1e30f, ssum = 0.f;
    for (int c = lane; c < NWRD; c += 32) {
        unsigned w = adjw[c];
        while (w) {
            int b = __ffs(w) - 1; w &= w - 1;
            int i = c * 32 + b;
            float e = lrelu(g_s1[i] + dj);
            if (e > m) { ssum = ssum * __expf(m - e) + 1.f; m = e; }
            else         ssum += __expf(e - m);
        }
    }
    float M = m;
    #pragma unroll
    for (int o = 16; o; o >>= 1) M = fmaxf(M, __shfl_xor_sync(~0u, M, o));
    ssum *= __expf(m - M);
    #pragma unroll
    for (int o = 16; o; o >>= 1) ssum += __shfl_xor_sync(~0u, ssum, o);
    float inv = 1.f / ssum;

    float acc[16];
    #pragma unroll
    for (int h = 0; h < 16; ++h) acc[h] = 0.f;
    for (int c = lane * 2; c < lane * 2 + 2; ++c) {
        unsigned w = adjw[c];
        while (w) {
            int b = __ffs(w) - 1; w &= w - 1;
            int i = c * 32 + b;
            float al = __expf(lrelu(g_s1[i] + dj) - M) * inv;
            const float4* hp = (const float4*)&g_h1[i * 16];
            float4 v0 = hp[0], v1 = hp[1], v2 = hp[2], v3 = hp[3];
            acc[0] += al * v0.x; acc[1] += al * v0.y; acc[2]  += al * v0.z; acc[3]  += al * v0.w;
            acc[4] += al * v1.x; acc[5] += al * v1.y; acc[6]  += al * v1.z; acc[7]  += al * v1.w;
            acc[8] += al * v2.x; acc[9] += al * v2.y; acc[10] += al * v2.z; acc[11] += al * v2.w;
            acc[12] += al * v3.x; acc[13] += al * v3.y; acc[14] += al * v3.z; acc[15] += al * v3.w;
        }
    }
    #pragma unroll
    for (int h = 0; h < 16; ++h) {
        #pragma unroll
        for (int o = 16; o; o >>= 1) acc[h] += __shfl_xor_sync(~0u, acc[h], o);
    }
    if (lane < 16) {
        float v = acc[lane] + b1[lane];
        ob[warp][lane] = v > 0.f ? v : 0.f;
    }
    __syncwarp();

    float o[16];
    #pragma unroll
    for (int k = 0; k < 16; ++k) o[k] = ob[warp][k];
    float hv0 = 0.f, hv1 = 0.f;
    #pragma unroll
    for (int k = 0; k < 16; ++k) {
        hv0 += o[k] * W2s[k * 64 + lane];
        hv1 += o[k] * W2s[k * 64 + lane + 32];
    }
    g_h2[(size_t)j * 64 + lane]      = hv0;
    g_h2[(size_t)j * 64 + lane + 32] = hv1;
    float sp = hv0 * a2s[lane] + hv1 * a2s[lane + 32];
    float dp = hv0 * a2d[lane] + hv1 * a2d[lane + 32];
    #pragma unroll
    for (int oo = 16; oo; oo >>= 1) {
        sp += __shfl_xor_sync(~0u, sp, oo);
        dp += __shfl_xor_sync(~0u, dp, oo);
    }
    if (lane == 0) { g_s2[j] = sp; g_d2[j] = dp; }
}

// ================= GAT2 aggregate + FC =================
__global__ void __launch_bounds__(256) k_gmain2(const float* __restrict__ b2,
                                                const float* __restrict__ fcW,
                                                const float* __restrict__ fcb,
                                                float* __restrict__ out)
{
    int warp = threadIdx.x >> 5, lane = threadIdx.x & 31;
    int j = blockIdx.x * 8 + warp;
    float dj = g_d2[j];
    const unsigned* adjw = &g_adjT[j * NWRD];

    float m = -1e30f, ssum = 0.f;
    for (int c = lane; c < NWRD; c += 32) {
        unsigned w = adjw[c];
        while (w) {
            int b = __ffs(w) - 1; w &= w - 1;
            int i = c * 32 + b;
            float e = lrelu(g_s2[i] + dj);
            if (e > m) { ssum = ssum * __expf(m - e) + 1.f; m = e; }
            else         ssum += __expf(e - m);
        }
    }
    float M = m;
    #pragma unroll
    for (int o = 16; o; o >>= 1) M = fmaxf(M, __shfl_xor_sync(~0u, M, o));
    ssum *= __expf(m - M);
    #pragma unroll
    for (int o = 16; o; o >>= 1) ssum += __shfl_xor_sync(~0u, ssum, o);
    float inv = 1.f / ssum;

    float a0 = 0.f, a1 = 0.f;
    for (int c = 0; c < NWRD; ++c) {
        unsigned w = adjw[c];
        while (w) {
            int b = __ffs(w) - 1; w &= w - 1;
            int i = c * 32 + b;
            float e = lrelu(g_s2[i] + dj);
            float al = __expf(e - M) * inv;
            a0 += al * g_h2[(size_t)i * 64 + lane];
            a1 += al * g_h2[(size_t)i * 64 + lane + 32];
        }
    }
    float part = (a0 + b2[lane]) * fcW[lane] + (a1 + b2[lane + 32]) * fcW[lane + 32];
    #pragma unroll
    for (int o = 16; o; o >>= 1) part += __shfl_xor_sync(~0u, part, o);
    if (lane == 0) out[j] = lrelu(part + fcb[0]);
}

// ================= launch =================
extern "C" void kernel_launch(void* const* d_in, const int* in_sizes, int n_in,
                              void* d_out, int out_size)
{
    const float* inputs   = (const float*)d_in[0];
    // d_in[1] relation, d_in[3] rel_w_W, d_in[4] rel_w_b: provably unused (adj = mask|diag)
    const float* rel_mask = (const float*)d_in[2];
    const float* w_ih0 = (const float*)d_in[5];
    const float* w_hh0 = (const float*)d_in[6];
    const float* b_ih0 = (const float*)d_in[7];
    const float* b_hh0 = (const float*)d_in[8];
    const float* w_ih1 = (const float*)d_in[9];
    const float* w_hh1 = (const float*)d_in[10];
    const float* b_ih1 = (const float*)d_in[11];
    const float* b_hh1 = (const float*)d_in[12];
    const float* gat1_W  = (const float*)d_in[13];
    const float* gat1_as = (const float*)d_in[14];
    const float* gat1_ad = (const float*)d_in[15];
    const float* gat1_b  = (const float*)d_in[16];
    const float* gat2_W  = (const float*)d_in[17];
    const float* gat2_as = (const float*)d_in[18];
    const float* gat2_ad = (const float*)d_in[19];
    const float* gat2_b  = (const float*)d_in[20];
    const float* fc_W    = (const float*)d_in[21];
    const float* fc_b    = (const float*)d_in[22];

    cudaFuncSetAttribute(k_lstm_mma, cudaFuncAttributeMaxDynamicSharedMemorySize, SMEM_REQ);

    k_adj<<<dim3(8, 16), 256>>>(rel_mask);
    k_lstm_mma<<<NBLK, 512, SMEM_REQ>>>(0, inputs, w_ih0, w_hh0, b_ih0, b_hh0,
                                        gat1_W, gat1_as, gat1_ad);
    k_lstm_mma<<<NBLK, 512, SMEM_REQ>>>(1, inputs, w_ih1, w_hh1, b_ih1, b_hh1,
                                        gat1_W, gat1_as, gat1_ad);
    k_gmain1<<<NN / 8, 256>>>(gat1_b, gat2_W, gat2_as, gat2_ad);
    k_gmain2<<<NN / 8, 256>>>(gat2_b, fc_W, fc_b, (float*)d_out);
}

// round 9
// speedup vs baseline: 1.8717x; 1.1785x over previous
#include <cuda_runtime.h>
#include <cuda_bf16.h>

#define NN   2048
#define TT   32
#define FIN  5
#define HH   64
#define NB   16
#define NBLK 128
#define NWRD 64

// ---- smem byte offsets ----
#define ZROWB    272
#define STAGE_HI 0                      // 256x128 bf16 = 65536 (permuted rows)
#define STAGE_LO 65536
#define Z0HI     131072                 // 16 x 272 = 4352 each
#define Z0LO     135424
#define Z1HI     139776                 // Z1* = Z0* + 8704
#define Z1LO     144128
#define ZSTRIDE  8704
#define BIAS_OFF 148480                 // 256 f32
#define XS_OFF   149504                 // layer0 xs: 32x5x16 f32 = 10240
#define HFIN_OFF 159744                 // layer1: 64x16 f32 = 4096
#define SMEM_REQ 164096

// -------- scratch (device globals) --------
__device__ unsigned long long g_h0hi[(size_t)TT * NBLK * 256]; // [t][blk][nb*16+q] 4 bf16
__device__ unsigned long long g_h0lo[(size_t)TT * NBLK * 256];
__device__ unsigned g_adjT[NN * NWRD];
__device__ float g_h1[NN * 16];
__device__ float g_s1[NN], g_d1[NN];
__device__ float g_h2[NN * HH];
__device__ float g_s2[NN], g_d2[NN];

// -------- helpers --------
__device__ __forceinline__ unsigned smem_u32(const void* p) {
    unsigned a;
    asm("{ .reg .u64 t; cvta.to.shared.u64 t, %1; cvt.u32.u64 %0, t; }" : "=r"(a) : "l"(p));
    return a;
}
__device__ __forceinline__ float sigm(float x)   { return 1.f / (1.f + __expf(-x)); }
__device__ __forceinline__ float tanh_f(float x) { return 1.f - 2.f / (__expf(2.f * x) + 1.f); }
__device__ __forceinline__ float lrelu(float x)  { return x >= 0.f ? x : 0.2f * x; }

__device__ __forceinline__ void split_bf(float v, unsigned short& hi, unsigned short& lo) {
    __nv_bfloat16 h = __float2bfloat16(v);
    __nv_bfloat16 l = __float2bfloat16(v - __bfloat162float(h));
    hi = __bfloat16_as_ushort(h);
    lo = __bfloat16_as_ushort(l);
}
__device__ __forceinline__ void mma_bf16(float* d, const unsigned* a, unsigned b0, unsigned b1) {
    asm volatile(
        "mma.sync.aligned.m16n8k16.row.col.f32.bf16.bf16.f32 "
        "{%0,%1,%2,%3}, {%4,%5,%6,%7}, {%8,%9}, {%0,%1,%2,%3};"
        : "+f"(d[0]), "+f"(d[1]), "+f"(d[2]), "+f"(d[3])
        : "r"(a[0]), "r"(a[1]), "r"(a[2]), "r"(a[3]), "r"(b0), "r"(b1));
}
__device__ __forceinline__ void ldmx4(unsigned addr, unsigned* r) {
    asm volatile("ldmatrix.sync.aligned.m8n8.x4.shared.b16 {%0,%1,%2,%3}, [%4];"
                 : "=r"(r[0]), "=r"(r[1]), "=r"(r[2]), "=r"(r[3]) : "r"(addr));
}

extern __shared__ float4 smemv[];

// ================= HMMA LSTM layer, gate-permuted, transpose-free =================
// 512 threads = 16 warps. Warp w's m16 tile rows r: gate = (r>>2)*64 + 4w + (r&3).
// LAYER=0: Z = [x cols 0-4 | pad | h cols 16-79], K tiles = 5.
// LAYER=1: Z = [hin cols 0-63 | h cols 64-127],   K tiles = 8.
template<int LAYER>
__global__ void __launch_bounds__(512, 1) k_lstm_mma(
    const float* __restrict__ inputs,
    const float* __restrict__ w_ih, const float* __restrict__ w_hh,
    const float* __restrict__ b_ih, const float* __restrict__ b_hh,
    const float* __restrict__ gat1_W, const float* __restrict__ gat1_as,
    const float* __restrict__ gat1_ad)
{
    constexpr int KT   = LAYER ? 8 : 5;      // k16 tiles
    constexpr int HCOL = LAYER ? 64 : 16;    // first h column in Z
    constexpr int HB   = HCOL * 2;           // h byte offset in Z row

    char* smp = (char*)smemv;
    unsigned sbu = smem_u32(smemv);

    int tid  = threadIdx.x;
    int wid  = tid >> 5;
    int lane = tid & 31;
    int blk  = blockIdx.x;
    int n0   = blk * NB;

    // zero: layer0 zeroes stage+Z (pad cols must be 0); layer1 only Z buffers
    {
        float4 z4 = make_float4(0.f, 0.f, 0.f, 0.f);
        if (LAYER == 0) {
            float4* dst = (float4*)smp;
            for (int i = tid; i < 148480 / 16; i += 512) dst[i] = z4;
        } else {
            float4* dst = (float4*)(smp + Z0HI);
            for (int i = tid; i < 17408 / 16; i += 512) dst[i] = z4;
        }
    }
    __syncthreads();

    // ---- stage W hi/lo with gate-row permutation ----
    int kw = LAYER ? HH : FIN;
    for (int idx = tid; idx < 256 * kw; idx += 512) {
        int gate = idx / kw, k = idx % kw;
        int srow = ((gate & 63) >> 2) * 16 + (gate >> 6) * 4 + (gate & 3);
        unsigned short hi, lo;
        split_bf(w_ih[idx], hi, lo);
        *(unsigned short*)(smp + STAGE_HI + (srow * 128 + k) * 2) = hi;
        *(unsigned short*)(smp + STAGE_LO + (srow * 128 + k) * 2) = lo;
    }
    for (int idx = tid; idx < 256 * HH; idx += 512) {
        int gate = idx >> 6, k = idx & 63;
        int srow = ((gate & 63) >> 2) * 16 + (gate >> 6) * 4 + (gate & 3);
        unsigned short hi, lo;
        split_bf(w_hh[idx], hi, lo);
        *(unsigned short*)(smp + STAGE_HI + (srow * 128 + HCOL + k) * 2) = hi;
        *(unsigned short*)(smp + STAGE_LO + (srow * 128 + HCOL + k) * 2) = lo;
    }
    float* bias_s = (float*)(smp + BIAS_OFF);
    if (tid < 256) bias_s[tid] = b_ih[tid] + b_hh[tid];

    float* xs = (float*)(smp + XS_OFF);
    uint2 pf = make_uint2(0u, 0u);
    if (LAYER == 0) {
        for (int idx = tid; idx < NB * TT * FIN; idx += 512) {
            int nb = idx / (TT * FIN);
            int r  = idx % (TT * FIN);
            int t  = r / FIN, f = r % FIN;
            xs[t * 80 + f * 16 + nb] = inputs[(size_t)(n0 + nb) * (TT * FIN) + t * FIN + f];
        }
        if (tid < 80) {
            int f = tid >> 4, nb = tid & 15;
            unsigned short hi, lo;
            split_bf(inputs[(size_t)(n0 + nb) * (TT * FIN) + f], hi, lo);
            *(unsigned short*)(smp + Z0HI + nb * ZROWB + f * 2) = hi;
            *(unsigned short*)(smp + Z0LO + nb * ZROWB + f * 2) = lo;
        }
    } else {
        int half = tid >> 8, r = tid & 255;
        int nb = r >> 4, q = r & 15;
        const uint2* src = (const uint2*)(half ? (void*)g_h0lo : (void*)g_h0hi);
        uint2 v0 = src[(size_t)blk * 256 + r];
        *(uint2*)(smp + (half ? Z0LO : Z0HI) + nb * ZROWB + q * 8) = v0;
        pf = src[((size_t)NBLK + blk) * 256 + r];
    }
    __syncthreads();

    // ---- load W fragments (permuted rows) ----
    unsigned whi[KT][4], wlo[KT][4];
    {
        int g0 = wid * 16 + (lane >> 2);
        int kp = (lane & 3) * 2;
        #pragma unroll
        for (int kt = 0; kt < KT; ++kt) {
            const char* bh = smp + STAGE_HI + (g0 * 128 + kt * 16 + kp) * 2;
            whi[kt][0] = *(const unsigned*)(bh);
            whi[kt][1] = *(const unsigned*)(bh + 2048);
            whi[kt][2] = *(const unsigned*)(bh + 16);
            whi[kt][3] = *(const unsigned*)(bh + 2048 + 16);
            const char* bl = smp + STAGE_LO + (g0 * 128 + kt * 16 + kp) * 2;
            wlo[kt][0] = *(const unsigned*)(bl);
            wlo[kt][1] = *(const unsigned*)(bl + 2048);
            wlo[kt][2] = *(const unsigned*)(bl + 16);
            wlo[kt][3] = *(const unsigned*)(bl + 2048 + 16);
        }
    }
    int q = lane >> 2, s = lane & 3;
    float bv0 = bias_s[(q < 4 ? 0 : 64)  + 4 * wid + (q & 3)];
    float bv1 = bias_s[(q < 4 ? 128 : 192) + 4 * wid + (q & 3)];

    int nrow  = (lane & 7) + ((lane >> 4) << 3);
    int khalf = (lane >> 3) & 1;
    unsigned zrel = nrow * ZROWB + khalf * 16;

    float* hfin = (float*)(smp + HFIN_OFF);
    int jp = 4 * wid + (q & 3);
    int nbA = (q < 4) ? 2 * s : 8 + 2 * s;
    int nbB = nbA + 1;
    float c0 = 0.f, c1 = 0.f;
    __syncthreads();

    #pragma unroll 1
    for (int t = 0; t < TT; ++t) {
        unsigned zoffR = (t & 1) ? ZSTRIDE : 0;
        unsigned zoffW = (t & 1) ? 0 : ZSTRIDE;

        // layer0: export h(t-1) from read buffer (concurrent with MMA reads)
        if (LAYER == 0 && t > 0) {
            int half = tid >> 8, r = tid & 255;
            int nb = r >> 4, qq = r & 15;
            uint2 v = *(const uint2*)(smp + (half ? Z0LO : Z0HI) + zoffR
                                      + nb * ZROWB + HB + qq * 8);
            ((uint2*)(half ? (void*)g_h0lo : (void*)g_h0hi))
                [((size_t)(t - 1) * NBLK + blk) * 256 + r] = v;
        }

        float acc[2][4];
        acc[0][0] = bv0; acc[0][1] = bv0; acc[0][2] = bv1; acc[0][3] = bv1;
        acc[1][0] = bv0; acc[1][1] = bv0; acc[1][2] = bv1; acc[1][3] = bv1;

        unsigned zhiB = sbu + Z0HI + zoffR + zrel;
        unsigned zloB = sbu + Z0LO + zoffR + zrel;
        #pragma unroll
        for (int kt = 0; kt < KT; ++kt) {
            unsigned bh[4], bl[4];
            ldmx4(zhiB + kt * 32, bh);
            ldmx4(zloB + kt * 32, bl);
            mma_bf16(acc[0], whi[kt], bh[0], bh[1]);
            mma_bf16(acc[1], whi[kt], bh[2], bh[3]);
            mma_bf16(acc[0], wlo[kt], bh[0], bh[1]);
            mma_bf16(acc[1], wlo[kt], bh[2], bh[3]);
            mma_bf16(acc[0], whi[kt], bl[0], bl[1]);
            mma_bf16(acc[1], whi[kt], bl[2], bl[3]);
        }

        // in-warp gate gather via shfl.xor 16
        float pp[8];
        #pragma unroll
        for (int i = 0; i < 4; ++i) {
            pp[i]     = __shfl_xor_sync(~0u, acc[0][i], 16);
            pp[4 + i] = __shfl_xor_sync(~0u, acc[1][i], 16);
        }

        float iA, fA, gA, oA, iB, fB, gB, oB;
        if (q < 4) {
            iA = acc[0][0]; gA = acc[0][2]; fA = pp[0]; oA = pp[2];
            iB = acc[0][1]; gB = acc[0][3]; fB = pp[1]; oB = pp[3];
        } else {
            iA = pp[4]; gA = pp[6]; fA = acc[1][0]; oA = acc[1][2];
            iB = pp[5]; gB = pp[7]; fB = acc[1][1]; oB = acc[1][3];
        }
        c0 = sigm(fA) * c0 + sigm(iA) * tanh_f(gA);
        c1 = sigm(fB) * c1 + sigm(iB) * tanh_f(gB);
        float h0v = sigm(oA) * tanh_f(c0);
        float h1v = sigm(oB) * tanh_f(c1);

        if (LAYER == 1 && t == TT - 1) {
            hfin[jp * 16 + nbA] = h0v;
            hfin[jp * 16 + nbB] = h1v;
        } else {
            unsigned short h0h, h0l, h1h, h1l;
            split_bf(h0v, h0h, h0l);
            split_bf(h1v, h1h, h1l);
            *(unsigned short*)(smp + Z0HI + zoffW + nbA * ZROWB + (HCOL + jp) * 2) = h0h;
            *(unsigned short*)(smp + Z0LO + zoffW + nbA * ZROWB + (HCOL + jp) * 2) = h0l;
            *(unsigned short*)(smp + Z0HI + zoffW + nbB * ZROWB + (HCOL + jp) * 2) = h1h;
            *(unsigned short*)(smp + Z0LO + zoffW + nbB * ZROWB + (HCOL + jp) * 2) = h1l;
        }

        if (LAYER == 0) {
            if (t + 1 < TT && tid < 80) {
                int f = tid >> 4, nb = tid & 15;
                unsigned short hi, lo;
                split_bf(xs[(t + 1) * 80 + f * 16 + nb], hi, lo);
                *(unsigned short*)(smp + Z0HI + zoffW + nb * ZROWB + f * 2) = hi;
                *(unsigned short*)(smp + Z0LO + zoffW + nb * ZROWB + f * 2) = lo;
            }
        } else if (t + 1 < TT) {
            int half = tid >> 8, r = tid & 255;
            int nb = r >> 4, qq = r & 15;
            *(uint2*)(smp + (half ? Z0LO : Z0HI) + zoffW + nb * ZROWB + qq * 8) = pf;
            if (t + 2 < TT)
                pf = ((const uint2*)(half ? (void*)g_h0lo : (void*)g_h0hi))
                         [((size_t)(t + 2) * NBLK + blk) * 256 + r];
        }
        __syncthreads();
    }

    if (LAYER == 0) {
        // final export: h(TT-1) lives in buf 0
        int half = tid >> 8, r = tid & 255;
        int nb = r >> 4, qq = r & 15;
        uint2 v = *(const uint2*)(smp + (half ? Z0LO : Z0HI) + nb * ZROWB + HB + qq * 8);
        ((uint2*)(half ? (void*)g_h0lo : (void*)g_h0hi))
            [((size_t)(TT - 1) * NBLK + blk) * 256 + r] = v;
    } else {
        // fused GAT1 projection
        float* W1s = (float*)(smp + STAGE_HI);
        float* asv = W1s + HH * 16;
        float* adv = asv + 16;
        float* h1b = adv + 16;
        for (int idx = tid; idx < HH * 16; idx += 512) W1s[idx] = gat1_W[idx];
        if (tid < 32) {
            if (tid < 16) asv[tid] = gat1_as[tid];
            else          adv[tid - 16] = gat1_ad[tid - 16];
        }
        __syncthreads();
        if (tid < 256) {
            int nb = tid & 15, jj = tid >> 4;
            float hv = 0.f;
            #pragma unroll
            for (int k = 0; k < HH; ++k) hv += hfin[k * 16 + nb] * W1s[k * 16 + jj];
            h1b[nb * 16 + jj] = hv;
            g_h1[(size_t)(n0 + nb) * 16 + jj] = hv;
        }
        __syncthreads();
        if (tid < 32) {
            int nb = tid & 15;
            const float* av = (tid < 16) ? asv : adv;
            float sv = 0.f;
            #pragma unroll
            for (int jj = 0; jj < 16; ++jj) sv += h1b[nb * 16 + jj] * av[jj];
            if (tid < 16) g_s1[n0 + nb] = sv; else g_d1[n0 + nb] = sv;
        }
    }
}

// ================= adjacency bitmask =================
__global__ void k_adj(const float* __restrict__ rel_mask) {
    int j  = blockIdx.x * 256 + threadIdx.x;
    int c0 = blockIdx.y * 4;
    for (int c = c0; c < c0 + 4; ++c) {
        unsigned w = 0;
        #pragma unroll 8
        for (int b = 0; b < 32; ++b) {
            int i = c * 32 + b;
            float v = rel_mask[(size_t)i * NN + j];
            if (v > -1.f || i == j) w |= (1u << b);
        }
        g_adjT[j * NWRD + c] = w;
    }
}

// ================= GAT1 aggregate + fused GAT2 projection =================
__global__ void __launch_bounds__(256) k_gmain1(const float* __restrict__ b1,
                                                const float* __restrict__ W2,
                                                const float* __restrict__ as2,
                                                const float* __restrict__ ad2)
{
    __shared__ float W2s[16 * 64], a2s[64], a2d[64], ob[8][16];
    int tid = threadIdx.x;
    for (int i = tid; i < 16 * 64; i += 256) W2s[i] = W2[i];
    if (tid < 64) { a2s[tid] = as2[tid]; a2d[tid] = ad2[tid]; }
    __syncthreads();

    int warp = tid >> 5, lane = tid & 31;
    int j = blockIdx.x * 8 + warp;
    float dj = g_d1[j];
    const unsigned* adjw = &g_adjT[j * NWRD];

    float m = -1e30f, ssum = 0.f;
    for (int c = lane; c < NWRD; c += 32) {
        unsigned w = adjw[c];
        while (w) {
            int b = __ffs(w) - 1; w &= w - 1;
            int i = c * 32 + b;
            float e = lrelu(g_s1[i] + dj);
            if (e > m) { ssum = ssum * __expf(m - e) + 1.f; m = e; }
            else         ssum += __expf(e - m);
        }
    }
    float M = m;
    #pragma unroll
    for (int o = 16; o; o >>= 1) M = fmaxf(M, __shfl_xor_sync(~0u, M, o));
    ssum *= __expf(m - M);
    #pragma unroll
    for (int o = 16; o; o >>= 1) ssum += __shfl_xor_sync(~0u, ssum, o);
    float inv = 1.f / ssum;

    float acc[16];
    #pragma unroll
    for (int h = 0; h < 16; ++h) acc[h] = 0.f;
    for (int c = lane * 2; c < lane * 2 + 2; ++c) {
        unsigned w = adjw[c];
        while (w) {
            int b = __ffs(w) - 1; w &= w - 1;
            int i = c * 32 + b;
            float al = __expf(lrelu(g_s1[i] + dj) - M) * inv;
            const float4* hp = (const float4*)&g_h1[i * 16];
            float4 v0 = hp[0], v1 = hp[1], v2 = hp[2], v3 = hp[3];
            acc[0] += al * v0.x; acc[1] += al * v0.y; acc[2]  += al * v0.z; acc[3]  += al * v0.w;
            acc[4] += al * v1.x; acc[5] += al * v1.y; acc[6]  += al * v1.z; acc[7]  += al * v1.w;
            acc[8] += al * v2.x; acc[9] += al * v2.y; acc[10] += al * v2.z; acc[11] += al * v2.w;
            acc[12] += al * v3.x; acc[13] += al * v3.y; acc[14] += al * v3.z; acc[15] += al * v3.w;
        }
    }
    #pragma unroll
    for (int h = 0; h < 16; ++h) {
        #pragma unroll
        for (int o = 16; o; o >>= 1) acc[h] += __shfl_xor_sync(~0u, acc[h], o);
    }
    if (lane < 16) {
        float v = acc[lane] + b1[lane];
        ob[warp][lane] = v > 0.f ? v : 0.f;
    }
    __syncwarp();

    float o[16];
    #pragma unroll
    for (int k = 0; k < 16; ++k) o[k] = ob[warp][k];
    float hv0 = 0.f, hv1 = 0.f;
    #pragma unroll
    for (int k = 0; k < 16; ++k) {
        hv0 += o[k] * W2s[k * 64 + lane];
        hv1 += o[k] * W2s[k * 64 + lane + 32];
    }
    g_h2[(size_t)j * 64 + lane]      = hv0;
    g_h2[(size_t)j * 64 + lane + 32] = hv1;
    float sp = hv0 * a2s[lane] + hv1 * a2s[lane + 32];
    float dp = hv0 * a2d[lane] + hv1 * a2d[lane + 32];
    #pragma unroll
    for (int oo = 16; oo; oo >>= 1) {
        sp += __shfl_xor_sync(~0u, sp, oo);
        dp += __shfl_xor_sync(~0u, dp, oo);
    }
    if (lane == 0) { g_s2[j] = sp; g_d2[j] = dp; }
}

// ================= GAT2 aggregate + FC =================
// pass2: 4 subgroups x 8 lanes; lane owns 8 h-dims, subgroup owns 16 adj words.
__global__ void __launch_bounds__(256) k_gmain2(const float* __restrict__ b2,
                                                const float* __restrict__ fcW,
                                                const float* __restrict__ fcb,
                                                float* __restrict__ out)
{
    int warp = threadIdx.x >> 5, lane = threadIdx.x & 31;
    int j = blockIdx.x * 8 + warp;
    float dj = g_d2[j];
    const unsigned* adjw = &g_adjT[j * NWRD];

    float m = -1e30f, ssum = 0.f;
    for (int c = lane; c < NWRD; c += 32) {
        unsigned w = adjw[c];
        while (w) {
            int b = __ffs(w) - 1; w &= w - 1;
            int i = c * 32 + b;
            float e = lrelu(g_s2[i] + dj);
            if (e > m) { ssum = ssum * __expf(m - e) + 1.f; m = e; }
            else         ssum += __expf(e - m);
        }
    }
    float M = m;
    #pragma unroll
    for (int o = 16; o; o >>= 1) M = fmaxf(M, __shfl_xor_sync(~0u, M, o));
    ssum *= __expf(m - M);
    #pragma unroll
    for (int o = 16; o; o >>= 1) ssum += __shfl_xor_sync(~0u, ssum, o);
    float inv = 1.f / ssum;

    int sg = lane >> 3, d8 = lane & 7;   // subgroup id, dim-octet id
    float acc[8];
    #pragma unroll
    for (int k = 0; k < 8; ++k) acc[k] = 0.f;
    for (int c = sg * 16; c < sg * 16 + 16; ++c) {
        unsigned w = adjw[c];
        while (w) {
            int b = __ffs(w) - 1; w &= w - 1;
            int i = c * 32 + b;
            float al = __expf(lrelu(g_s2[i] + dj) - M) * inv;
            const float4* hp = (const float4*)&g_h2[(size_t)i * 64 + d8 * 8];
            float4 v0 = hp[0], v1 = hp[1];
            acc[0] += al * v0.x; acc[1] += al * v0.y; acc[2] += al * v0.z; acc[3] += al * v0.w;
            acc[4] += al * v1.x; acc[5] += al * v1.y; acc[6] += al * v1.z; acc[7] += al * v1.w;
        }
    }
    // reduce across subgroups (lanes differing in bits 3,4)
    #pragma unroll
    for (int k = 0; k < 8; ++k) {
        acc[k] += __shfl_xor_sync(~0u, acc[k], 8);
        acc[k] += __shfl_xor_sync(~0u, acc[k], 16);
    }
    // fold into FC dot: lanes within a subgroup hold distinct octets; xor 1,2,4
    // sums all 8 octets exactly once -> full dot product (no overcount).
    float part = 0.f;
    #pragma unroll
    for (int k = 0; k < 8; ++k)
        part += (acc[k] + b2[d8 * 8 + k]) * fcW[d8 * 8 + k];
    part += __shfl_xor_sync(~0u, part, 1);
    part += __shfl_xor_sync(~0u, part, 2);
    part += __shfl_xor_sync(~0u, part, 4);
    if (lane == 0) out[j] = lrelu(part + fcb[0]);
}

// ================= launch =================
extern "C" void kernel_launch(void* const* d_in, const int* in_sizes, int n_in,
                              void* d_out, int out_size)
{
    const float* inputs   = (const float*)d_in[0];
    // d_in[1] relation, d_in[3] rel_w_W, d_in[4] rel_w_b: provably unused (adj = mask|diag)
    const float* rel_mask = (const float*)d_in[2];
    const float* w_ih0 = (const float*)d_in[5];
    const float* w_hh0 = (const float*)d_in[6];
    const float* b_ih0 = (const float*)d_in[7];
    const float* b_hh0 = (const float*)d_in[8];
    const float* w_ih1 = (const float*)d_in[9];
    const float* w_hh1 = (const float*)d_in[10];
    const float* b_ih1 = (const float*)d_in[11];
    const float* b_hh1 = (const float*)d_in[12];
    const float* gat1_W  = (const float*)d_in[13];
    const float* gat1_as = (const float*)d_in[14];
    const float* gat1_ad = (const float*)d_in[15];
    const float* gat1_b  = (const float*)d_in[16];
    const float* gat2_W  = (const float*)d_in[17];
    const float* gat2_as = (const float*)d_in[18];
    const float* gat2_ad = (const float*)d_in[19];
    const float* gat2_b  = (const float*)d_in[20];
    const float* fc_W    = (const float*)d_in[21];
    const float* fc_b    = (const float*)d_in[22];

    cudaFuncSetAttribute(k_lstm_mma<0>, cudaFuncAttributeMaxDynamicSharedMemorySize, SMEM_REQ);
    cudaFuncSetAttribute(k_lstm_mma<1>, cudaFuncAttributeMaxDynamicSharedMemorySize, SMEM_REQ);

    k_adj<<<dim3(8, 16), 256>>>(rel_mask);
    k_lstm_mma<0><<<NBLK, 512, SMEM_REQ>>>(inputs, w_ih0, w_hh0, b_ih0, b_hh0,
                                           gat1_W, gat1_as, gat1_ad);
    k_lstm_mma<1><<<NBLK, 512, SMEM_REQ>>>(inputs, w_ih1, w_hh1, b_ih1, b_hh1,
                                           gat1_W, gat1_as, gat1_ad);
    k_gmain1<<<NN / 8, 256>>>(gat1_b, gat2_W, gat2_as, gat2_ad);
    k_gmain2<<<NN / 8, 256>>>(gat2_b, fc_W, fc_b, (float*)d_out);
}

// round 10
// speedup vs baseline: 2.0771x; 1.1097x over previous
#include <cuda_runtime.h>
#include <cuda_fp16.h>

#define NN   2048
#define TT   32
#define FIN  5
#define HH   64
#define NB   16
#define NBLK 128
#define NWRD 64

// ---- smem byte offsets ----
#define ZROWB    272
#define STAGE_HI 0                      // 256x128 fp16 = 65536 (permuted rows)
#define STAGE_LO 65536
#define Z0HI     131072                 // 16 x 272 = 4352 each (hi only now)
#define Z1HI     135424
#define ZSTRIDE  4352
#define BIAS_OFF 139776                 // 256 f32
#define XS_OFF   140800                 // layer0 xs: 32x5x16 f32 = 10240
#define HFIN_OFF 151040                 // layer1: 64x16 f32 = 4096
#define SMEM_REQ 155648

// -------- scratch (device globals) --------
__device__ unsigned long long g_h0hi[(size_t)TT * NBLK * 256]; // [t][blk][nb*16+q] 4 fp16
__device__ unsigned g_adjT[NN * NWRD];
__device__ float g_h1[NN * 16];
__device__ float g_s1[NN], g_d1[NN];
__device__ float g_h2[NN * HH];
__device__ float g_s2[NN], g_d2[NN];

// -------- helpers --------
__device__ __forceinline__ unsigned smem_u32(const void* p) {
    unsigned a;
    asm("{ .reg .u64 t; cvta.to.shared.u64 t, %1; cvt.u32.u64 %0, t; }" : "=r"(a) : "l"(p));
    return a;
}
__device__ __forceinline__ float sigm(float x)   { return 1.f / (1.f + __expf(-x)); }
__device__ __forceinline__ float tanh_f(float x) { return 1.f - 2.f / (__expf(2.f * x) + 1.f); }
__device__ __forceinline__ float lrelu(float x)  { return x >= 0.f ? x : 0.2f * x; }

// fp16 hi/lo weight split: whi+wlo == w to ~2^-23
__device__ __forceinline__ void split_h(float v, unsigned short& hi, unsigned short& lo) {
    __half h = __float2half_rn(v);
    __half l = __float2half_rn(v - __half2float(h));
    hi = __half_as_ushort(h);
    lo = __half_as_ushort(l);
}
__device__ __forceinline__ void mma_f16(float* d, const unsigned* a, unsigned b0, unsigned b1) {
    asm volatile(
        "mma.sync.aligned.m16n8k16.row.col.f32.f16.f16.f32 "
        "{%0,%1,%2,%3}, {%4,%5,%6,%7}, {%8,%9}, {%0,%1,%2,%3};"
        : "+f"(d[0]), "+f"(d[1]), "+f"(d[2]), "+f"(d[3])
        : "r"(a[0]), "r"(a[1]), "r"(a[2]), "r"(a[3]), "r"(b0), "r"(b1));
}
__device__ __forceinline__ void ldmx4(unsigned addr, unsigned* r) {
    asm volatile("ldmatrix.sync.aligned.m8n8.x4.shared.b16 {%0,%1,%2,%3}, [%4];"
                 : "=r"(r[0]), "=r"(r[1]), "=r"(r[2]), "=r"(r[3]) : "r"(addr));
}

extern __shared__ float4 smemv[];

// ================= HMMA LSTM layer, fp16 2-pass, gate-permuted =================
// 512 threads = 16 warps. Warp w's m16 tile rows r: gate = (r>>2)*64 + 4w + (r&3).
// LAYER=0: Z = [x cols 0-4 | pad | h cols 16-79], K tiles = 5.
// LAYER=1: Z = [hin cols 0-63 | h cols 64-127],   K tiles = 8.
template<int LAYER>
__global__ void __launch_bounds__(512, 1) k_lstm_mma(
    const float* __restrict__ inputs,
    const float* __restrict__ w_ih, const float* __restrict__ w_hh,
    const float* __restrict__ b_ih, const float* __restrict__ b_hh,
    const float* __restrict__ gat1_W, const float* __restrict__ gat1_as,
    const float* __restrict__ gat1_ad)
{
    constexpr int KT   = LAYER ? 8 : 5;      // k16 tiles
    constexpr int HCOL = LAYER ? 64 : 16;    // first h column in Z
    constexpr int HB   = HCOL * 2;           // h byte offset in Z row

    char* smp = (char*)smemv;
    unsigned sbu = smem_u32(smemv);

    int tid  = threadIdx.x;
    int wid  = tid >> 5;
    int lane = tid & 31;
    int blk  = blockIdx.x;
    int n0   = blk * NB;

    // zero: layer0 zeroes stage+Z (pad cols must be 0); layer1 only Z buffers
    {
        float4 z4 = make_float4(0.f, 0.f, 0.f, 0.f);
        if (LAYER == 0) {
            float4* dst = (float4*)smp;
            for (int i = tid; i < 139776 / 16; i += 512) dst[i] = z4;
        } else {
            float4* dst = (float4*)(smp + Z0HI);
            for (int i = tid; i < 8704 / 16; i += 512) dst[i] = z4;
        }
    }
    __syncthreads();

    // ---- stage W hi/lo (fp16) with gate-row permutation ----
    int kw = LAYER ? HH : FIN;
    for (int idx = tid; idx < 256 * kw; idx += 512) {
        int gate = idx / kw, k = idx % kw;
        int srow = ((gate & 63) >> 2) * 16 + (gate >> 6) * 4 + (gate & 3);
        unsigned short hi, lo;
        split_h(w_ih[idx], hi, lo);
        *(unsigned short*)(smp + STAGE_HI + (srow * 128 + k) * 2) = hi;
        *(unsigned short*)(smp + STAGE_LO + (srow * 128 + k) * 2) = lo;
    }
    for (int idx = tid; idx < 256 * HH; idx += 512) {
        int gate = idx >> 6, k = idx & 63;
        int srow = ((gate & 63) >> 2) * 16 + (gate >> 6) * 4 + (gate & 3);
        unsigned short hi, lo;
        split_h(w_hh[idx], hi, lo);
        *(unsigned short*)(smp + STAGE_HI + (srow * 128 + HCOL + k) * 2) = hi;
        *(unsigned short*)(smp + STAGE_LO + (srow * 128 + HCOL + k) * 2) = lo;
    }
    float* bias_s = (float*)(smp + BIAS_OFF);
    if (tid < 256) bias_s[tid] = b_ih[tid] + b_hh[tid];

    float* xs = (float*)(smp + XS_OFF);
    uint2 pf = make_uint2(0u, 0u);
    if (LAYER == 0) {
        for (int idx = tid; idx < NB * TT * FIN; idx += 512) {
            int nb = idx / (TT * FIN);
            int r  = idx % (TT * FIN);
            int t  = r / FIN, f = r % FIN;
            xs[t * 80 + f * 16 + nb] = inputs[(size_t)(n0 + nb) * (TT * FIN) + t * FIN + f];
        }
        if (tid < 80) {
            int f = tid >> 4, nb = tid & 15;
            *(__half*)(smp + Z0HI + nb * ZROWB + f * 2) =
                __float2half_rn(inputs[(size_t)(n0 + nb) * (TT * FIN) + f]);
        }
    } else {
        if (tid < 256) {
            int nb = tid >> 4, q = tid & 15;
            uint2 v0 = ((const uint2*)g_h0hi)[(size_t)blk * 256 + tid];
            *(uint2*)(smp + Z0HI + nb * ZROWB + q * 8) = v0;
            pf = ((const uint2*)g_h0hi)[((size_t)NBLK + blk) * 256 + tid];
        }
    }
    __syncthreads();

    // ---- load W fragments (permuted rows) ----
    unsigned whi[KT][4], wlo[KT][4];
    {
        int g0 = wid * 16 + (lane >> 2);
        int kp = (lane & 3) * 2;
        #pragma unroll
        for (int kt = 0; kt < KT; ++kt) {
            const char* bh = smp + STAGE_HI + (g0 * 128 + kt * 16 + kp) * 2;
            whi[kt][0] = *(const unsigned*)(bh);
            whi[kt][1] = *(const unsigned*)(bh + 2048);
            whi[kt][2] = *(const unsigned*)(bh + 16);
            whi[kt][3] = *(const unsigned*)(bh + 2048 + 16);
            const char* bl = smp + STAGE_LO + (g0 * 128 + kt * 16 + kp) * 2;
            wlo[kt][0] = *(const unsigned*)(bl);
            wlo[kt][1] = *(const unsigned*)(bl + 2048);
            wlo[kt][2] = *(const unsigned*)(bl + 16);
            wlo[kt][3] = *(const unsigned*)(bl + 2048 + 16);
        }
    }
    int q = lane >> 2, s = lane & 3;
    float bv0 = bias_s[(q < 4 ? 0 : 64)  + 4 * wid + (q & 3)];
    float bv1 = bias_s[(q < 4 ? 128 : 192) + 4 * wid + (q & 3)];

    int nrow  = (lane & 7) + ((lane >> 4) << 3);
    int khalf = (lane >> 3) & 1;
    unsigned zrel = nrow * ZROWB + khalf * 16;

    float* hfin = (float*)(smp + HFIN_OFF);
    int jp = 4 * wid + (q & 3);
    int nbA = (q < 4) ? 2 * s : 8 + 2 * s;
    int nbB = nbA + 1;
    float c0 = 0.f, c1 = 0.f;
    __syncthreads();

    #pragma unroll 1
    for (int t = 0; t < TT; ++t) {
        unsigned zoffR = (t & 1) ? ZSTRIDE : 0;
        unsigned zoffW = (t & 1) ? 0 : ZSTRIDE;

        // layer0: export h(t-1) from read buffer (concurrent with MMA reads)
        if (LAYER == 0 && t > 0 && tid < 256) {
            int nb = tid >> 4, qq = tid & 15;
            uint2 v = *(const uint2*)(smp + Z0HI + zoffR + nb * ZROWB + HB + qq * 8);
            ((uint2*)g_h0hi)[((size_t)(t - 1) * NBLK + blk) * 256 + tid] = v;
        }

        float acc[2][4];
        acc[0][0] = bv0; acc[0][1] = bv0; acc[0][2] = bv1; acc[0][3] = bv1;
        acc[1][0] = bv0; acc[1][1] = bv0; acc[1][2] = bv1; acc[1][3] = bv1;

        unsigned zhiB = sbu + Z0HI + zoffR + zrel;
        #pragma unroll
        for (int kt = 0; kt < KT; ++kt) {
            unsigned bh[4];
            ldmx4(zhiB + kt * 32, bh);
            mma_f16(acc[0], whi[kt], bh[0], bh[1]);
            mma_f16(acc[1], whi[kt], bh[2], bh[3]);
            mma_f16(acc[0], wlo[kt], bh[0], bh[1]);
            mma_f16(acc[1], wlo[kt], bh[2], bh[3]);
        }

        // in-warp gate gather via shfl.xor 16
        float pp[8];
        #pragma unroll
        for (int i = 0; i < 4; ++i) {
            pp[i]     = __shfl_xor_sync(~0u, acc[0][i], 16);
            pp[4 + i] = __shfl_xor_sync(~0u, acc[1][i], 16);
        }

        float iA, fA, gA, oA, iB, fB, gB, oB;
        if (q < 4) {
            iA = acc[0][0]; gA = acc[0][2]; fA = pp[0]; oA = pp[2];
            iB = acc[0][1]; gB = acc[0][3]; fB = pp[1]; oB = pp[3];
        } else {
            iA = pp[4]; gA = pp[6]; fA = acc[1][0]; oA = acc[1][2];
            iB = pp[5]; gB = pp[7]; fB = acc[1][1]; oB = acc[1][3];
        }
        c0 = sigm(fA) * c0 + sigm(iA) * tanh_f(gA);
        c1 = sigm(fB) * c1 + sigm(iB) * tanh_f(gB);
        float h0v = sigm(oA) * tanh_f(c0);
        float h1v = sigm(oB) * tanh_f(c1);

        if (LAYER == 1 && t == TT - 1) {
            hfin[jp * 16 + nbA] = h0v;
            hfin[jp * 16 + nbB] = h1v;
        } else {
            *(__half*)(smp + Z0HI + zoffW + nbA * ZROWB + (HCOL + jp) * 2) = __float2half_rn(h0v);
            *(__half*)(smp + Z0HI + zoffW + nbB * ZROWB + (HCOL + jp) * 2) = __float2half_rn(h1v);
        }

        if (LAYER == 0) {
            if (t + 1 < TT && tid < 80) {
                int f = tid >> 4, nb = tid & 15;
                *(__half*)(smp + Z0HI + zoffW + nb * ZROWB + f * 2) =
                    __float2half_rn(xs[(t + 1) * 80 + f * 16 + nb]);
            }
        } else if (t + 1 < TT && tid < 256) {
            int nb = tid >> 4, qq = tid & 15;
            *(uint2*)(smp + Z0HI + zoffW + nb * ZROWB + qq * 8) = pf;
            if (t + 2 < TT)
                pf = ((const uint2*)g_h0hi)[((size_t)(t + 2) * NBLK + blk) * 256 + tid];
        }
        __syncthreads();
    }

    if (LAYER == 0) {
        // final export: h(TT-1) lives in buf 0
        if (tid < 256) {
            int nb = tid >> 4, qq = tid & 15;
            uint2 v = *(const uint2*)(smp + Z0HI + nb * ZROWB + HB + qq * 8);
            ((uint2*)g_h0hi)[((size_t)(TT - 1) * NBLK + blk) * 256 + tid] = v;
        }
    } else {
        // fused GAT1 projection
        float* W1s = (float*)(smp + STAGE_HI);
        float* asv = W1s + HH * 16;
        float* adv = asv + 16;
        float* h1b = adv + 16;
        for (int idx = tid; idx < HH * 16; idx += 512) W1s[idx] = gat1_W[idx];
        if (tid < 32) {
            if (tid < 16) asv[tid] = gat1_as[tid];
            else          adv[tid - 16] = gat1_ad[tid - 16];
        }
        __syncthreads();
        if (tid < 256) {
            int nb = tid & 15, jj = tid >> 4;
            float hv = 0.f;
            #pragma unroll
            for (int k = 0; k < HH; ++k) hv += hfin[k * 16 + nb] * W1s[k * 16 + jj];
            h1b[nb * 16 + jj] = hv;
            g_h1[(size_t)(n0 + nb) * 16 + jj] = hv;
        }
        __syncthreads();
        if (tid < 32) {
            int nb = tid & 15;
            const float* av = (tid < 16) ? asv : adv;
            float sv = 0.f;
            #pragma unroll
            for (int jj = 0; jj < 16; ++jj) sv += h1b[nb * 16 + jj] * av[jj];
            if (tid < 16) g_s1[n0 + nb] = sv; else g_d1[n0 + nb] = sv;
        }
    }
}

// ================= adjacency bitmask =================
__global__ void k_adj(const float* __restrict__ rel_mask) {
    int j  = blockIdx.x * 256 + threadIdx.x;
    int c0 = blockIdx.y * 4;
    for (int c = c0; c < c0 + 4; ++c) {
        unsigned w = 0;
        #pragma unroll 8
        for (int b = 0; b < 32; ++b) {
            int i = c * 32 + b;
            float v = rel_mask[(size_t)i * NN + j];
            if (v > -1.f || i == j) w |= (1u << b);
        }
        g_adjT[j * NWRD + c] = w;
    }
}

// ================= GAT1 aggregate + fused GAT2 projection =================
__global__ void __launch_bounds__(256) k_gmain1(const float* __restrict__ b1,
                                                const float* __restrict__ W2,
                                                const float* __restrict__ as2,
                                                const float* __restrict__ ad2)
{
    __shared__ float W2s[16 * 64], a2s[64], a2d[64], ob[8][16];
    int tid = threadIdx.x;
    for (int i = tid; i < 16 * 64; i += 256) W2s[i] = W2[i];
    if (tid < 64) { a2s[tid] = as2[tid]; a2d[tid] = ad2[tid]; }
    __syncthreads();

    int warp = tid >> 5, lane = tid & 31;
    int j = blockIdx.x * 8 + warp;
    float dj = g_d1[j];
    const unsigned* adjw = &g_adjT[j * NWRD];

    float m = -1e30f, ssum = 0.f;
    for (int c = lane; c < NWRD; c += 32) {
        unsigned w = adjw[c];
        while (w) {
            int b = __ffs(w) - 1; w &= w - 1;
            int i = c * 32 + b;
            float e = lrelu(g_s1[i] + dj);
            if (e > m) { ssum = ssum * __expf(m - e) + 1.f; m = e; }
            else         ssum += __expf(e - m);
        }
    }
    float M = m;
    #pragma unroll
    for (int o = 16; o; o >>= 1) M = fmaxf(M, __shfl_xor_sync(~0u, M, o));
    ssum *= __expf(m - M);
    #pragma unroll
    for (int o = 16; o; o >>= 1) ssum += __shfl_xor_sync(~0u, ssum, o);
    float inv = 1.f / ssum;

    float acc[16];
    #pragma unroll
    for (int h = 0; h < 16; ++h) acc[h] = 0.f;
    for (int c = lane * 2; c < lane * 2 + 2; ++c) {
        unsigned w = adjw[c];
        while (w) {
            int b = __ffs(w) - 1; w &= w - 1;
            int i = c * 32 + b;
            float al = __expf(lrelu(g_s1[i] + dj) - M) * inv;
            const float4* hp = (const float4*)&g_h1[i * 16];
            float4 v0 = hp[0], v1 = hp[1], v2 = hp[2], v3 = hp[3];
            acc[0] += al * v0.x; acc[1] += al * v0.y; acc[2]  += al * v0.z; acc[3]  += al * v0.w;
            acc[4] += al * v1.x; acc[5] += al * v1.y; acc[6]  += al * v1.z; acc[7]  += al * v1.w;
            acc[8] += al * v2.x; acc[9] += al * v2.y; acc[10] += al * v2.z; acc[11] += al * v2.w;
            acc[12] += al * v3.x; acc[13] += al * v3.y; acc[14] += al * v3.z; acc[15] += al * v3.w;
        }
    }
    #pragma unroll
    for (int h = 0; h < 16; ++h) {
        #pragma unroll
        for (int o = 16; o; o >>= 1) acc[h] += __shfl_xor_sync(~0u, acc[h], o);
    }
    if (lane < 16) {
        float v = acc[lane] + b1[lane];
        ob[warp][lane] = v > 0.f ? v : 0.f;
    }
    __syncwarp();

    float o[16];
    #pragma unroll
    for (int k = 0; k < 16; ++k) o[k] = ob[warp][k];
    float hv0 = 0.f, hv1 = 0.f;
    #pragma unroll
    for (int k = 0; k < 16; ++k) {
        hv0 += o[k] * W2s[k * 64 + lane];
        hv1 += o[k] * W2s[k * 64 + lane + 32];
    }
    g_h2[(size_t)j * 64 + lane]      = hv0;
    g_h2[(size_t)j * 64 + lane + 32] = hv1;
    float sp = hv0 * a2s[lane] + hv1 * a2s[lane + 32];
    float dp = hv0 * a2d[lane] + hv1 * a2d[lane + 32];
    #pragma unroll
    for (int oo = 16; oo; oo >>= 1) {
        sp += __shfl_xor_sync(~0u, sp, oo);
        dp += __shfl_xor_sync(~0u, dp, oo);
    }
    if (lane == 0) { g_s2[j] = sp; g_d2[j] = dp; }
}

// ================= GAT2 aggregate + FC =================
// pass2: 4 subgroups x 8 lanes; lane owns 8 h-dims, subgroup owns 16 adj words.
__global__ void __launch_bounds__(256) k_gmain2(const float* __restrict__ b2,
                                                const float* __restrict__ fcW,
                                                const float* __restrict__ fcb,
                                                float* __restrict__ out)
{
    int warp = threadIdx.x >> 5, lane = threadIdx.x & 31;
    int j = blockIdx.x * 8 + warp;
    float dj = g_d2[j];
    const unsigned* adjw = &g_adjT[j * NWRD];

    float m = -1e30f, ssum = 0.f;
    for (int c = lane; c < NWRD; c += 32) {
        unsigned w = adjw[c];
        while (w) {
            int b = __ffs(w) - 1; w &= w - 1;
            int i = c * 32 + b;
            float e = lrelu(g_s2[i] + dj);
            if (e > m) { ssum = ssum * __expf(m - e) + 1.f; m = e; }
            else         ssum += __expf(e - m);
        }
    }
    float M = m;
    #pragma unroll
    for (int o = 16; o; o >>= 1) M = fmaxf(M, __shfl_xor_sync(~0u, M, o));
    ssum *= __expf(m - M);
    #pragma unroll
    for (int o = 16; o; o >>= 1) ssum += __shfl_xor_sync(~0u, ssum, o);
    float inv = 1.f / ssum;

    int sg = lane >> 3, d8 = lane & 7;
    float acc[8];
    #pragma unroll
    for (int k = 0; k < 8; ++k) acc[k] = 0.f;
    for (int c = sg * 16; c < sg * 16 + 16; ++c) {
        unsigned w = adjw[c];
        while (w) {
            int b = __ffs(w) - 1; w &= w - 1;
            int i = c * 32 + b;
            float al = __expf(lrelu(g_s2[i] + dj) - M) * inv;
            const float4* hp = (const float4*)&g_h2[(size_t)i * 64 + d8 * 8];
            float4 v0 = hp[0], v1 = hp[1];
            acc[0] += al * v0.x; acc[1] += al * v0.y; acc[2] += al * v0.z; acc[3] += al * v0.w;
            acc[4] += al * v1.x; acc[5] += al * v1.y; acc[6] += al * v1.z; acc[7] += al * v1.w;
        }
    }
    #pragma unroll
    for (int k = 0; k < 8; ++k) {
        acc[k] += __shfl_xor_sync(~0u, acc[k], 8);
        acc[k] += __shfl_xor_sync(~0u, acc[k], 16);
    }
    float part = 0.f;
    #pragma unroll
    for (int k = 0; k < 8; ++k)
        part += (acc[k] + b2[d8 * 8 + k]) * fcW[d8 * 8 + k];
    part += __shfl_xor_sync(~0u, part, 1);
    part += __shfl_xor_sync(~0u, part, 2);
    part += __shfl_xor_sync(~0u, part, 4);
    if (lane == 0) out[j] = lrelu(part + fcb[0]);
}

// ================= launch =================
extern "C" void kernel_launch(void* const* d_in, const int* in_sizes, int n_in,
                              void* d_out, int out_size)
{
    const float* inputs   = (const float*)d_in[0];
    // d_in[1] relation, d_in[3] rel_w_W, d_in[4] rel_w_b: provably unused (adj = mask|diag)
    const float* rel_mask = (const float*)d_in[2];
    const float* w_ih0 = (const float*)d_in[5];
    const float* w_hh0 = (const float*)d_in[6];
    const float* b_ih0 = (const float*)d_in[7];
    const float* b_hh0 = (const float*)d_in[8];
    const float* w_ih1 = (const float*)d_in[9];
    const float* w_hh1 = (const float*)d_in[10];
    const float* b_ih1 = (const float*)d_in[11];
    const float* b_hh1 = (const float*)d_in[12];
    const float* gat1_W  = (const float*)d_in[13];
    const float* gat1_as = (const float*)d_in[14];
    const float* gat1_ad = (const float*)d_in[15];
    const float* gat1_b  = (const float*)d_in[16];
    const float* gat2_W  = (const float*)d_in[17];
    const float* gat2_as = (const float*)d_in[18];
    const float* gat2_ad = (const float*)d_in[19];
    const float* gat2_b  = (const float*)d_in[20];
    const float* fc_W    = (const float*)d_in[21];
    const float* fc_b    = (const float*)d_in[22];

    cudaFuncSetAttribute(k_lstm_mma<0>, cudaFuncAttributeMaxDynamicSharedMemorySize, SMEM_REQ);
    cudaFuncSetAttribute(k_lstm_mma<1>, cudaFuncAttributeMaxDynamicSharedMemorySize, SMEM_REQ);

    k_adj<<<dim3(8, 16), 256>>>(rel_mask);
    k_lstm_mma<0><<<NBLK, 512, SMEM_REQ>>>(inputs, w_ih0, w_hh0, b_ih0, b_hh0,
                                           gat1_W, gat1_as, gat1_ad);
    k_lstm_mma<1><<<NBLK, 512, SMEM_REQ>>>(inputs, w_ih1, w_hh1, b_ih1, b_hh1,
                                           gat1_W, gat1_as, gat1_ad);
    k_gmain1<<<NN / 8, 256>>>(gat1_b, gat2_W, gat2_as, gat2_ad);
    k_gmain2<<<NN / 8, 256>>>(gat2_b, fc_W, fc_b, (float*)d_out);
}

// round 12
// speedup vs baseline: 2.2382x; 1.0776x over previous
#include <cuda_runtime.h>
#include <cuda_fp16.h>

#define NN   2048
#define TT   32
#define FIN  5
#define HH   64
#define NB   16
#define NBLK 128
#define NWRD 64

// ---- smem byte offsets (no W staging) ----
#define ZROWB    272
#define Z0HI     0                      // 16 x 272 = 4352 per buffer
#define ZSTRIDE  4352
#define XS_OFF   8704                   // layer0 xs: 32x5x16 f32 = 10240 (ends 18944) | layer1: hfin 4096
#define W1S_OFF  12800                  // layer1 GAT: 64x16 f32 (aliases upper xs, layer1 only)
#define ASV_OFF  16896
#define ADV_OFF  16960
#define H1B_OFF  17024                  // 16x16 f32 (ends 18048)
#define SMEM_REQ 19456                  // covers layer0 xs end (18944) + pad

// -------- scratch (device globals) --------
__device__ unsigned long long g_h0hi[(size_t)TT * NBLK * 256]; // [t][blk][nb*16+q] 4 fp16
__device__ unsigned g_adjT[NN * NWRD];
__device__ float g_h1[NN * 16];
__device__ float g_s1[NN], g_d1[NN];
__device__ float g_h2[NN * HH];
__device__ float g_s2[NN], g_d2[NN];

// -------- helpers --------
__device__ __forceinline__ unsigned smem_u32(const void* p) {
    unsigned a;
    asm("{ .reg .u64 t; cvta.to.shared.u64 t, %1; cvt.u32.u64 %0, t; }" : "=r"(a) : "l"(p));
    return a;
}
__device__ __forceinline__ float sigm(float x)   { return 1.f / (1.f + __expf(-x)); }
__device__ __forceinline__ float tanh_f(float x) { return 1.f - 2.f / (__expf(2.f * x) + 1.f); }
__device__ __forceinline__ float lrelu(float x)  { return x >= 0.f ? x : 0.2f * x; }

// pack two consecutive-k weights into hi/lo fp16x2 fragment regs
__device__ __forceinline__ void packsplit(float w0, float w1, unsigned& hi, unsigned& lo) {
    __half h0 = __float2half_rn(w0), h1 = __float2half_rn(w1);
    __half l0 = __float2half_rn(w0 - __half2float(h0));
    __half l1 = __float2half_rn(w1 - __half2float(h1));
    hi = (unsigned)__half_as_ushort(h0) | ((unsigned)__half_as_ushort(h1) << 16);
    lo = (unsigned)__half_as_ushort(l0) | ((unsigned)__half_as_ushort(l1) << 16);
}
__device__ __forceinline__ void mma_f16(float* d, const unsigned* a, unsigned b0, unsigned b1) {
    asm volatile(
        "mma.sync.aligned.m16n8k16.row.col.f32.f16.f16.f32 "
        "{%0,%1,%2,%3}, {%4,%5,%6,%7}, {%8,%9}, {%0,%1,%2,%3};"
        : "+f"(d[0]), "+f"(d[1]), "+f"(d[2]), "+f"(d[3])
        : "r"(a[0]), "r"(a[1]), "r"(a[2]), "r"(a[3]), "r"(b0), "r"(b1));
}
__device__ __forceinline__ void ldmx4(unsigned addr, unsigned* r) {
    asm volatile("ldmatrix.sync.aligned.m8n8.x4.shared.b16 {%0,%1,%2,%3}, [%4];"
                 : "=r"(r[0]), "=r"(r[1]), "=r"(r[2]), "=r"(r[3]) : "r"(addr));
}

extern __shared__ float4 smemv[];

// Z-column weight lookup: LAYER0 Z = [x 0-4 | pad 5-15 | h 16-79]; LAYER1 Z = [hin 0-63 | h 64-127]
template<int LAYER>
__device__ __forceinline__ float getw(const float* wih, const float* whh, int gate, int c) {
    if (LAYER == 0) {
        if (c < FIN) return wih[gate * FIN + c];
        if (c < 16)  return 0.f;
        return whh[gate * HH + (c - 16)];
    } else {
        if (c < 64) return wih[gate * HH + c];
        return whh[gate * HH + (c - 64)];
    }
}

// ================= HMMA LSTM layer, fp16 2-pass, gate-permuted, no staging =================
// 512 threads = 16 warps. Warp w's m16 tile rows r: gate(r) = (r>>2)*64 + 4w + (r&3).
template<int LAYER>
__global__ void __launch_bounds__(512, 1) k_lstm_mma(
    const float* __restrict__ inputs,
    const float* __restrict__ w_ih, const float* __restrict__ w_hh,
    const float* __restrict__ b_ih, const float* __restrict__ b_hh,
    const float* __restrict__ gat1_W, const float* __restrict__ gat1_as,
    const float* __restrict__ gat1_ad)
{
    constexpr int KT   = LAYER ? 8 : 5;
    constexpr int HCOL = LAYER ? 64 : 16;
    constexpr int HB   = HCOL * 2;

    char* smp = (char*)smemv;
    unsigned sbu = smem_u32(smemv);

    int tid  = threadIdx.x;
    int wid  = tid >> 5;
    int lane = tid & 31;
    int blk  = blockIdx.x;
    int n0   = blk * NB;

    // zero both Z buffers (pad cols must stay 0)
    {
        float4 z4 = make_float4(0.f, 0.f, 0.f, 0.f);
        float4* dst = (float4*)smp;
        for (int i = tid; i < 2 * ZSTRIDE / 16; i += 512) dst[i] = z4;
    }

    // ---- direct-gmem W fragment loads (permuted rows, fp16 hi/lo split in regs) ----
    int q = lane >> 2, s = lane & 3;
    int gateA = (q >> 2) * 64 + 4 * wid + (q & 3);        // row q
    int gateB = gateA + 128;                              // row q+8
    unsigned whi[KT][4], wlo[KT][4];
    #pragma unroll
    for (int kt = 0; kt < KT; ++kt) {
        int c = kt * 16 + s * 2;
        packsplit(getw<LAYER>(w_ih, w_hh, gateA, c),     getw<LAYER>(w_ih, w_hh, gateA, c + 1),
                  whi[kt][0], wlo[kt][0]);
        packsplit(getw<LAYER>(w_ih, w_hh, gateB, c),     getw<LAYER>(w_ih, w_hh, gateB, c + 1),
                  whi[kt][1], wlo[kt][1]);
        packsplit(getw<LAYER>(w_ih, w_hh, gateA, c + 8), getw<LAYER>(w_ih, w_hh, gateA, c + 9),
                  whi[kt][2], wlo[kt][2]);
        packsplit(getw<LAYER>(w_ih, w_hh, gateB, c + 8), getw<LAYER>(w_ih, w_hh, gateB, c + 9),
                  whi[kt][3], wlo[kt][3]);
    }
    float bv0 = b_ih[gateA] + b_hh[gateA];
    float bv1 = b_ih[gateB] + b_hh[gateB];

    float* xs = (float*)(smp + XS_OFF);
    uint2 pf = make_uint2(0u, 0u);
    if (LAYER == 0) {
        for (int idx = tid; idx < NB * TT * FIN; idx += 512) {
            int nb = idx / (TT * FIN);
            int r  = idx % (TT * FIN);
            int t  = r / FIN, f = r % FIN;
            xs[t * 80 + f * 16 + nb] = inputs[(size_t)(n0 + nb) * (TT * FIN) + t * FIN + f];
        }
        if (tid < 80) {
            int f = tid >> 4, nb = tid & 15;
            *(__half*)(smp + Z0HI + nb * ZROWB + f * 2) =
                __float2half_rn(inputs[(size_t)(n0 + nb) * (TT * FIN) + f]);
        }
    } else {
        if (tid < 256) {
            int nb = tid >> 4, qq = tid & 15;
            uint2 v0 = ((const uint2*)g_h0hi)[(size_t)blk * 256 + tid];
            *(uint2*)(smp + Z0HI + nb * ZROWB + qq * 8) = v0;
            pf = ((const uint2*)g_h0hi)[((size_t)NBLK + blk) * 256 + tid];
        }
    }
    __syncthreads();

    int nrow  = (lane & 7) + ((lane >> 4) << 3);
    int khalf = (lane >> 3) & 1;
    unsigned zrel = nrow * ZROWB + khalf * 16;

    float* hfin = (float*)(smp + XS_OFF);        // layer1 alias
    int jp = 4 * wid + (q & 3);
    int nbA = (q < 4) ? 2 * s : 8 + 2 * s;
    int nbB = nbA + 1;
    float c0 = 0.f, c1 = 0.f;

    #pragma unroll 1
    for (int t = 0; t < TT; ++t) {
        unsigned zoffR = (t & 1) ? ZSTRIDE : 0;
        unsigned zoffW = (t & 1) ? 0 : ZSTRIDE;

        // layer0: export h(t-1) from read buffer (concurrent with MMA reads)
        if (LAYER == 0 && t > 0 && tid < 256) {
            int nb = tid >> 4, qq = tid & 15;
            uint2 v = *(const uint2*)(smp + Z0HI + zoffR + nb * ZROWB + HB + qq * 8);
            ((uint2*)g_h0hi)[((size_t)(t - 1) * NBLK + blk) * 256 + tid] = v;
        }

        float acc[2][4];
        acc[0][0] = bv0; acc[0][1] = bv0; acc[0][2] = bv1; acc[0][3] = bv1;
        acc[1][0] = bv0; acc[1][1] = bv0; acc[1][2] = bv1; acc[1][3] = bv1;

        unsigned zhiB = sbu + Z0HI + zoffR + zrel;
        #pragma unroll
        for (int kt = 0; kt < KT; ++kt) {
            unsigned bh[4];
            ldmx4(zhiB + kt * 32, bh);
            mma_f16(acc[0], whi[kt], bh[0], bh[1]);
            mma_f16(acc[1], whi[kt], bh[2], bh[3]);
            mma_f16(acc[0], wlo[kt], bh[0], bh[1]);
            mma_f16(acc[1], wlo[kt], bh[2], bh[3]);
        }

        // in-warp gate gather via shfl.xor 16
        float pp[8];
        #pragma unroll
        for (int i = 0; i < 4; ++i) {
            pp[i]     = __shfl_xor_sync(~0u, acc[0][i], 16);
            pp[4 + i] = __shfl_xor_sync(~0u, acc[1][i], 16);
        }

        float iA, fA, gA, oA, iB, fB, gB, oB;
        if (q < 4) {
            iA = acc[0][0]; gA = acc[0][2]; fA = pp[0]; oA = pp[2];
            iB = acc[0][1]; gB = acc[0][3]; fB = pp[1]; oB = pp[3];
        } else {
            iA = pp[4]; gA = pp[6]; fA = acc[1][0]; oA = acc[1][2];
            iB = pp[5]; gB = pp[7]; fB = acc[1][1]; oB = acc[1][3];
        }
        c0 = sigm(fA) * c0 + sigm(iA) * tanh_f(gA);
        c1 = sigm(fB) * c1 + sigm(iB) * tanh_f(gB);
        float h0v = sigm(oA) * tanh_f(c0);
        float h1v = sigm(oB) * tanh_f(c1);

        if (LAYER == 1 && t == TT - 1) {
            hfin[jp * 16 + nbA] = h0v;
            hfin[jp * 16 + nbB] = h1v;
        } else {
            *(__half*)(smp + Z0HI + zoffW + nbA * ZROWB + (HCOL + jp) * 2) = __float2half_rn(h0v);
            *(__half*)(smp + Z0HI + zoffW + nbB * ZROWB + (HCOL + jp) * 2) = __float2half_rn(h1v);
        }

        if (LAYER == 0) {
            if (t + 1 < TT && tid < 80) {
                int f = tid >> 4, nb = tid & 15;
                *(__half*)(smp + Z0HI + zoffW + nb * ZROWB + f * 2) =
                    __float2half_rn(xs[(t + 1) * 80 + f * 16 + nb]);
            }
        } else if (t + 1 < TT && tid < 256) {
            int nb = tid >> 4, qq = tid & 15;
            *(uint2*)(smp + Z0HI + zoffW + nb * ZROWB + qq * 8) = pf;
            if (t + 2 < TT)
                pf = ((const uint2*)g_h0hi)[((size_t)(t + 2) * NBLK + blk) * 256 + tid];
        }
        __syncthreads();
    }

    if (LAYER == 0) {
        // final export: h(TT-1) lives in buf 0
        if (tid < 256) {
            int nb = tid >> 4, qq = tid & 15;
            uint2 v = *(const uint2*)(smp + Z0HI + nb * ZROWB + HB + qq * 8);
            ((uint2*)g_h0hi)[((size_t)(TT - 1) * NBLK + blk) * 256 + tid] = v;
        }
    } else {
        // fused GAT1 projection
        float* W1s = (float*)(smp + W1S_OFF);
        float* asv = (float*)(smp + ASV_OFF);
        float* adv = (float*)(smp + ADV_OFF);
        float* h1b = (float*)(smp + H1B_OFF);
        for (int idx = tid; idx < HH * 16; idx += 512) W1s[idx] = gat1_W[idx];
        if (tid < 32) {
            if (tid < 16) asv[tid] = gat1_as[tid];
            else          adv[tid - 16] = gat1_ad[tid - 16];
        }
        __syncthreads();
        if (tid < 256) {
            int nb = tid & 15, jj = tid >> 4;
            float hv = 0.f;
            #pragma unroll
            for (int k = 0; k < HH; ++k) hv += hfin[k * 16 + nb] * W1s[k * 16 + jj];
            h1b[nb * 16 + jj] = hv;
            g_h1[(size_t)(n0 + nb) * 16 + jj] = hv;
        }
        __syncthreads();
        if (tid < 32) {
            int nb = tid & 15;
            const float* av = (tid < 16) ? asv : adv;
            float sv = 0.f;
            #pragma unroll
            for (int jj = 0; jj < 16; ++jj) sv += h1b[nb * 16 + jj] * av[jj];
            if (tid < 16) g_s1[n0 + nb] = sv; else g_d1[n0 + nb] = sv;
        }
    }
}

// ================= adjacency bitmask =================
__global__ void k_adj(const float* __restrict__ rel_mask) {
    int j  = blockIdx.x * 256 + threadIdx.x;
    int c0 = blockIdx.y * 4;
    for (int c = c0; c < c0 + 4; ++c) {
        unsigned w = 0;
        #pragma unroll 8
        for (int b = 0; b < 32; ++b) {
            int i = c * 32 + b;
            float v = rel_mask[(size_t)i * NN + j];
            if (v > -1.f || i == j) w |= (1u << b);
        }
        g_adjT[j * NWRD + c] = w;
    }
}

// ================= GAT1 aggregate (single-pass softmax) + fused GAT2 projection ===
// Logits |e| <~ 2 (sub-unit dot products) -> exp cannot overflow; max-pass redundant.
__global__ void __launch_bounds__(256) k_gmain1(const float* __restrict__ b1,
                                                const float* __restrict__ W2,
                                                const float* __restrict__ as2,
                                                const float* __restrict__ ad2)
{
    __shared__ float W2s[16 * 64], a2s[64], a2d[64], ob[8][16];
    int tid = threadIdx.x;
    for (int i = tid; i < 16 * 64; i += 256) W2s[i] = W2[i];
    if (tid < 64) { a2s[tid] = as2[tid]; a2d[tid] = ad2[tid]; }
    __syncthreads();

    int warp = tid >> 5, lane = tid & 31;
    int j = blockIdx.x * 8 + warp;
    float dj = g_d1[j];
    const unsigned* adjw = &g_adjT[j * NWRD];

    float sum = 0.f, acc[16];
    #pragma unroll
    for (int h = 0; h < 16; ++h) acc[h] = 0.f;
    for (int c = lane * 2; c < lane * 2 + 2; ++c) {
        unsigned w = adjw[c];
        while (w) {
            int b = __ffs(w) - 1; w &= w - 1;
            int i = c * 32 + b;
            float al = __expf(lrelu(g_s1[i] + dj));
            sum += al;
            const float4* hp = (const float4*)&g_h1[i * 16];
            float4 v0 = hp[0], v1 = hp[1], v2 = hp[2], v3 = hp[3];
            acc[0] += al * v0.x; acc[1] += al * v0.y; acc[2]  += al * v0.z; acc[3]  += al * v0.w;
            acc[4] += al * v1.x; acc[5] += al * v1.y; acc[6]  += al * v1.z; acc[7]  += al * v1.w;
            acc[8] += al * v2.x; acc[9] += al * v2.y; acc[10] += al * v2.z; acc[11] += al * v2.w;
            acc[12] += al * v3.x; acc[13] += al * v3.y; acc[14] += al * v3.z; acc[15] += al * v3.w;
        }
    }
    #pragma unroll
    for (int o = 16; o; o >>= 1) sum += __shfl_xor_sync(~0u, sum, o);
    #pragma unroll
    for (int h = 0; h < 16; ++h) {
        #pragma unroll
        for (int o = 16; o; o >>= 1) acc[h] += __shfl_xor_sync(~0u, acc[h], o);
    }
    float inv = 1.f / sum;

    // static (predicated) select of acc[lane&15] — avoids dynamic-index local mem
    int hsel = lane & 15;
    float vsel = acc[0];
    #pragma unroll
    for (int h = 1; h < 16; ++h) if (hsel == h) vsel = acc[h];
    if (lane < 16) {
        float v = vsel * inv + b1[lane];
        ob[warp][lane] = v > 0.f ? v : 0.f;
    }
    __syncwarp();

    float o[16];
    #pragma unroll
    for (int k = 0; k < 16; ++k) o[k] = ob[warp][k];
    float hv0 = 0.f, hv1 = 0.f;
    #pragma unroll
    for (int k = 0; k < 16; ++k) {
        hv0 += o[k] * W2s[k * 64 + lane];
        hv1 += o[k] * W2s[k * 64 + lane + 32];
    }
    g_h2[(size_t)j * 64 + lane]      = hv0;
    g_h2[(size_t)j * 64 + lane + 32] = hv1;
    float sp = hv0 * a2s[lane] + hv1 * a2s[lane + 32];
    float dp = hv0 * a2d[lane] + hv1 * a2d[lane + 32];
    #pragma unroll
    for (int oo = 16; oo; oo >>= 1) {
        sp += __shfl_xor_sync(~0u, sp, oo);
        dp += __shfl_xor_sync(~0u, dp, oo);
    }
    if (lane == 0) { g_s2[j] = sp; g_d2[j] = dp; }
}

// ================= GAT2 aggregate (single-pass softmax) + FC =================
// pass: 4 subgroups x 8 lanes; lane owns 8 h-dims, subgroup owns 16 adj words.
__global__ void __launch_bounds__(256) k_gmain2(const float* __restrict__ b2,
                                                const float* __restrict__ fcW,
                                                const float* __restrict__ fcb,
                                                float* __restrict__ out)
{
    int warp = threadIdx.x >> 5, lane = threadIdx.x & 31;
    int j = blockIdx.x * 8 + warp;
    float dj = g_d2[j];
    const unsigned* adjw = &g_adjT[j * NWRD];

    int sg = lane >> 3, d8 = lane & 7;
    float sum = 0.f, acc[8];
    #pragma unroll
    for (int k = 0; k < 8; ++k) acc[k] = 0.f;
    for (int c = sg * 16; c < sg * 16 + 16; ++c) {
        unsigned w = adjw[c];
        while (w) {
            int b = __ffs(w) - 1; w &= w - 1;
            int i = c * 32 + b;
            float al = __expf(lrelu(g_s2[i] + dj));
            sum += al;
            const float4* hp = (const float4*)&g_h2[(size_t)i * 64 + d8 * 8];
            float4 v0 = hp[0], v1 = hp[1];
            acc[0] += al * v0.x; acc[1] += al * v0.y; acc[2] += al * v0.z; acc[3] += al * v0.w;
            acc[4] += al * v1.x; acc[5] += al * v1.y; acc[6] += al * v1.z; acc[7] += al * v1.w;
        }
    }
    // sum is replicated across the 8 lanes of a subgroup; reduce only across sg bits (8,16)
    #pragma unroll
    for (int k = 0; k < 8; ++k) {
        acc[k] += __shfl_xor_sync(~0u, acc[k], 8);
        acc[k] += __shfl_xor_sync(~0u, acc[k], 16);
    }
    sum += __shfl_xor_sync(~0u, sum, 8);
    sum += __shfl_xor_sync(~0u, sum, 16);
    float inv = 1.f / sum;

    float part = 0.f;
    #pragma unroll
    for (int k = 0; k < 8; ++k)
        part += (acc[k] * inv + b2[d8 * 8 + k]) * fcW[d8 * 8 + k];
    part += __shfl_xor_sync(~0u, part, 1);
    part += __shfl_xor_sync(~0u, part, 2);
    part += __shfl_xor_sync(~0u, part, 4);
    if (lane == 0) out[j] = lrelu(part + fcb[0]);
}

// ================= launch =================
extern "C" void kernel_launch(void* const* d_in, const int* in_sizes, int n_in,
                              void* d_out, int out_size)
{
    const float* inputs   = (const float*)d_in[0];
    // d_in[1] relation, d_in[3] rel_w_W, d_in[4] rel_w_b: provably unused (adj = mask|diag)
    const float* rel_mask = (const float*)d_in[2];
    const float* w_ih0 = (const float*)d_in[5];
    const float* w_hh0 = (const float*)d_in[6];
    const float* b_ih0 = (const float*)d_in[7];
    const float* b_hh0 = (const float*)d_in[8];
    const float* w_ih1 = (const float*)d_in[9];
    const float* w_hh1 = (const float*)d_in[10];
    const float* b_ih1 = (const float*)d_in[11];
    const float* b_hh1 = (const float*)d_in[12];
    const float* gat1_W  = (const float*)d_in[13];
    const float* gat1_as = (const float*)d_in[14];
    const float* gat1_ad = (const float*)d_in[15];
    const float* gat1_b  = (const float*)d_in[16];
    const float* gat2_W  = (const float*)d_in[17];
    const float* gat2_as = (const float*)d_in[18];
    const float* gat2_ad = (const float*)d_in[19];
    const float* gat2_b  = (const float*)d_in[20];
    const float* fc_W    = (const float*)d_in[21];
    const float* fc_b    = (const float*)d_in[22];

    cudaFuncSetAttribute(k_lstm_mma<0>, cudaFuncAttributeMaxDynamicSharedMemorySize, SMEM_REQ);
    cudaFuncSetAttribute(k_lstm_mma<1>, cudaFuncAttributeMaxDynamicSharedMemorySize, SMEM_REQ);

    k_adj<<<dim3(8, 16), 256>>>(rel_mask);
    k_lstm_mma<0><<<NBLK, 512, SMEM_REQ>>>(inputs, w_ih0, w_hh0, b_ih0, b_hh0,
                                           gat1_W, gat1_as, gat1_ad);
    k_lstm_mma<1><<<NBLK, 512, SMEM_REQ>>>(inputs, w_ih1, w_hh1, b_ih1, b_hh1,
                                           gat1_W, gat1_as, gat1_ad);
    k_gmain1<<<NN / 8, 256>>>(gat1_b, gat2_W, gat2_as, gat2_ad);
    k_gmain2<<<NN / 8, 256>>>(gat2_b, fc_W, fc_b, (float*)d_out);
}

// round 13
// speedup vs baseline: 2.4602x; 1.0992x over previous
#include <cuda_runtime.h>
#include <cuda_fp16.h>

#define NN   2048
#define TT   32
#define FIN  5
#define HH   64
#define NB   16
#define NBLK 128
#define NWRD 64

// ---- smem layout: fused LSTM ----
#define ZROWB    272
#define Z0A      0                      // Z0 buffers: 16 x 272 each
#define Z1A      8704                   // Z1 buffers
#define ZSTRIDE  4352
#define XS_OFF   17408                  // xs 32x5x16 f32 = 10240 (ends 27648); hfin alias
#define SMEM_REQ 28672
// post-loop GAT aliases (Z0 region dead):
#define W1S_OFF  0
#define ASV_OFF  4096
#define ADV_OFF  4160
#define H1B_OFF  4224

// -------- scratch (device globals) --------
__device__ unsigned g_adjT[NN * NWRD];
__device__ float g_h1[NN * 16];
__device__ float g_s1[NN], g_d1[NN];
__device__ float g_h2[NN * HH];
__device__ float g_s2[NN], g_d2[NN];

// -------- helpers --------
__device__ __forceinline__ unsigned smem_u32(const void* p) {
    unsigned a;
    asm("{ .reg .u64 t; cvta.to.shared.u64 t, %1; cvt.u32.u64 %0, t; }" : "=r"(a) : "l"(p));
    return a;
}
__device__ __forceinline__ float sigm(float x)   { return 1.f / (1.f + __expf(-x)); }
__device__ __forceinline__ float tanh_f(float x) { return 1.f - 2.f / (__expf(2.f * x) + 1.f); }
__device__ __forceinline__ float lrelu(float x)  { return x >= 0.f ? x : 0.2f * x; }

__device__ __forceinline__ unsigned packhi(float w0, float w1) {
    return (unsigned)__half_as_ushort(__float2half_rn(w0))
         | ((unsigned)__half_as_ushort(__float2half_rn(w1)) << 16);
}
__device__ __forceinline__ void packsplit(float w0, float w1, unsigned& hi, unsigned& lo) {
    __half h0 = __float2half_rn(w0), h1 = __float2half_rn(w1);
    __half l0 = __float2half_rn(w0 - __half2float(h0));
    __half l1 = __float2half_rn(w1 - __half2float(h1));
    hi = (unsigned)__half_as_ushort(h0) | ((unsigned)__half_as_ushort(h1) << 16);
    lo = (unsigned)__half_as_ushort(l0) | ((unsigned)__half_as_ushort(l1) << 16);
}
__device__ __forceinline__ void mma_f16(float* d, const unsigned* a, unsigned b0, unsigned b1) {
    asm volatile(
        "mma.sync.aligned.m16n8k16.row.col.f32.f16.f16.f32 "
        "{%0,%1,%2,%3}, {%4,%5,%6,%7}, {%8,%9}, {%0,%1,%2,%3};"
        : "+f"(d[0]), "+f"(d[1]), "+f"(d[2]), "+f"(d[3])
        : "r"(a[0]), "r"(a[1]), "r"(a[2]), "r"(a[3]), "r"(b0), "r"(b1));
}
__device__ __forceinline__ void ldmx4(unsigned addr, unsigned* r) {
    asm volatile("ldmatrix.sync.aligned.m8n8.x4.shared.b16 {%0,%1,%2,%3}, [%4];"
                 : "=r"(r[0]), "=r"(r[1]), "=r"(r[2]), "=r"(r[3]) : "r"(addr));
}

extern __shared__ float4 smemv[];

// layer0 Z cols: [x 0-4 | pad 5-15 | h0 16-79]; layer1 Z cols: [h0 0-63 | h1 64-127]
__device__ __forceinline__ float getw0(const float* wih, const float* whh, int gate, int c) {
    if (c < FIN) return wih[gate * FIN + c];
    if (c < 16)  return 0.f;
    return whh[gate * HH + (c - 16)];
}
__device__ __forceinline__ float getw1(const float* wih, const float* whh, int gate, int c) {
    if (c < 64) return wih[gate * HH + c];
    return whh[gate * HH + (c - 64)];
}

// ================= fused 2-layer HMMA LSTM, software-pipelined =================
// 512 threads = 16 warps; warp w's m16 rows r: gate(r) = (r>>2)*64 + 4w + (r&3).
// Iteration u: layer0 step u (u<TT), layer1 step u-1 (u>=1). One barrier per iter.
__global__ void __launch_bounds__(512, 1) k_lstm_fused(
    const float* __restrict__ inputs,
    const float* __restrict__ w_ih0, const float* __restrict__ w_hh0,
    const float* __restrict__ b_ih0, const float* __restrict__ b_hh0,
    const float* __restrict__ w_ih1, const float* __restrict__ w_hh1,
    const float* __restrict__ b_ih1, const float* __restrict__ b_hh1,
    const float* __restrict__ gat1_W, const float* __restrict__ gat1_as,
    const float* __restrict__ gat1_ad)
{
    char* smp = (char*)smemv;
    unsigned sbu = smem_u32(smemv);

    int tid  = threadIdx.x;
    int wid  = tid >> 5;
    int lane = tid & 31;
    int blk  = blockIdx.x;
    int n0   = blk * NB;

    // zero all 4 Z buffers (pads + h(-1) states must be 0)
    {
        float4 z4 = make_float4(0.f, 0.f, 0.f, 0.f);
        float4* dst = (float4*)smp;
        for (int i = tid; i < 4 * ZSTRIDE / 16; i += 512) dst[i] = z4;
    }

    // ---- W fragments from gmem (permuted rows) ----
    int q = lane >> 2, s = lane & 3;
    int gateA = (q >> 2) * 64 + 4 * wid + (q & 3);
    int gateB = gateA + 128;
    unsigned w0hi[5][4];
    #pragma unroll
    for (int kt = 0; kt < 5; ++kt) {
        int c = kt * 16 + s * 2;
        w0hi[kt][0] = packhi(getw0(w_ih0, w_hh0, gateA, c),     getw0(w_ih0, w_hh0, gateA, c + 1));
        w0hi[kt][1] = packhi(getw0(w_ih0, w_hh0, gateB, c),     getw0(w_ih0, w_hh0, gateB, c + 1));
        w0hi[kt][2] = packhi(getw0(w_ih0, w_hh0, gateA, c + 8), getw0(w_ih0, w_hh0, gateA, c + 9));
        w0hi[kt][3] = packhi(getw0(w_ih0, w_hh0, gateB, c + 8), getw0(w_ih0, w_hh0, gateB, c + 9));
    }
    unsigned w1hi[8][4], w1lo[8][4];
    #pragma unroll
    for (int kt = 0; kt < 8; ++kt) {
        int c = kt * 16 + s * 2;
        packsplit(getw1(w_ih1, w_hh1, gateA, c),     getw1(w_ih1, w_hh1, gateA, c + 1),
                  w1hi[kt][0], w1lo[kt][0]);
        packsplit(getw1(w_ih1, w_hh1, gateB, c),     getw1(w_ih1, w_hh1, gateB, c + 1),
                  w1hi[kt][1], w1lo[kt][1]);
        packsplit(getw1(w_ih1, w_hh1, gateA, c + 8), getw1(w_ih1, w_hh1, gateA, c + 9),
                  w1hi[kt][2], w1lo[kt][2]);
        packsplit(getw1(w_ih1, w_hh1, gateB, c + 8), getw1(w_ih1, w_hh1, gateB, c + 9),
                  w1hi[kt][3], w1lo[kt][3]);
    }
    float bA0 = b_ih0[gateA] + b_hh0[gateA], bB0 = b_ih0[gateB] + b_hh0[gateB];
    float bA1 = b_ih1[gateA] + b_hh1[gateA], bB1 = b_ih1[gateB] + b_hh1[gateB];

    // stage all x; x(0) into Z0A
    float* xs = (float*)(smp + XS_OFF);
    for (int idx = tid; idx < NB * TT * FIN; idx += 512) {
        int nb = idx / (TT * FIN);
        int r  = idx % (TT * FIN);
        int t  = r / FIN, f = r % FIN;
        xs[t * 80 + f * 16 + nb] = inputs[(size_t)(n0 + nb) * (TT * FIN) + t * FIN + f];
    }
    if (tid < 80) {
        int f = tid >> 4, nb = tid & 15;
        *(__half*)(smp + Z0A + nb * ZROWB + f * 2) =
            __float2half_rn(inputs[(size_t)(n0 + nb) * (TT * FIN) + f]);
    }
    __syncthreads();

    int nrow  = (lane & 7) + ((lane >> 4) << 3);
    int khalf = (lane >> 3) & 1;
    unsigned zrel = nrow * ZROWB + khalf * 16;

    float* hfin = (float*)(smp + XS_OFF);   // alias: xs dead after u=30 stage
    int jp  = 4 * wid + (q & 3);
    int nbA = (q < 4) ? 2 * s : 8 + 2 * s;
    int nbB = nbA + 1;
    float c00 = 0.f, c01 = 0.f;   // layer0 cell states
    float c10 = 0.f, c11 = 0.f;   // layer1 cell states

    #pragma unroll 1
    for (int u = 0; u <= TT; ++u) {
        int p = u & 1;
        unsigned z0r = Z0A + p * ZSTRIDE,        z0w = Z0A + (p ^ 1) * ZSTRIDE;
        unsigned z1r = Z1A + (p ^ 1) * ZSTRIDE,  z1w = Z1A + p * ZSTRIDE;

        // ---------- layer 0: step u ----------
        if (u < TT) {
            float acc[2][4];
            acc[0][0] = bA0; acc[0][1] = bA0; acc[0][2] = bB0; acc[0][3] = bB0;
            acc[1][0] = bA0; acc[1][1] = bA0; acc[1][2] = bB0; acc[1][3] = bB0;
            unsigned zb = sbu + z0r + zrel;
            #pragma unroll
            for (int kt = 0; kt < 5; ++kt) {
                unsigned bh[4];
                ldmx4(zb + kt * 32, bh);
                mma_f16(acc[0], w0hi[kt], bh[0], bh[1]);
                mma_f16(acc[1], w0hi[kt], bh[2], bh[3]);
            }
            float pp[8];
            #pragma unroll
            for (int i = 0; i < 4; ++i) {
                pp[i]     = __shfl_xor_sync(~0u, acc[0][i], 16);
                pp[4 + i] = __shfl_xor_sync(~0u, acc[1][i], 16);
            }
            float iA, fA, gA, oA, iB, fB, gB, oB;
            if (q < 4) {
                iA = acc[0][0]; gA = acc[0][2]; fA = pp[0]; oA = pp[2];
                iB = acc[0][1]; gB = acc[0][3]; fB = pp[1]; oB = pp[3];
            } else {
                iA = pp[4]; gA = pp[6]; fA = acc[1][0]; oA = acc[1][2];
                iB = pp[5]; gB = pp[7]; fB = acc[1][1]; oB = acc[1][3];
            }
            c00 = sigm(fA) * c00 + sigm(iA) * tanh_f(gA);
            c01 = sigm(fB) * c01 + sigm(iB) * tanh_f(gB);
            float h0A = sigm(oA) * tanh_f(c00);
            float h0B = sigm(oB) * tanh_f(c01);
            __half h0Ah = __float2half_rn(h0A), h0Bh = __float2half_rn(h0B);
            // h0(u): feed layer0 next step (Z0w col 16+jp) + layer1 (Z1w col jp)
            *(__half*)(smp + z0w + nbA * ZROWB + (16 + jp) * 2) = h0Ah;
            *(__half*)(smp + z0w + nbB * ZROWB + (16 + jp) * 2) = h0Bh;
            *(__half*)(smp + z1w + nbA * ZROWB + jp * 2) = h0Ah;
            *(__half*)(smp + z1w + nbB * ZROWB + jp * 2) = h0Bh;
            if (u + 1 < TT && tid < 80) {
                int f = tid >> 4, nb = tid & 15;
                *(__half*)(smp + z0w + nb * ZROWB + f * 2) =
                    __float2half_rn(xs[(u + 1) * 80 + f * 16 + nb]);
            }
        }

        // ---------- layer 1: step u-1 ----------
        if (u >= 1) {
            float acc[2][4];
            acc[0][0] = bA1; acc[0][1] = bA1; acc[0][2] = bB1; acc[0][3] = bB1;
            acc[1][0] = bA1; acc[1][1] = bA1; acc[1][2] = bB1; acc[1][3] = bB1;
            unsigned zb = sbu + z1r + zrel;
            #pragma unroll
            for (int kt = 0; kt < 8; ++kt) {
                unsigned bh[4];
                ldmx4(zb + kt * 32, bh);
                mma_f16(acc[0], w1hi[kt], bh[0], bh[1]);
                mma_f16(acc[1], w1hi[kt], bh[2], bh[3]);
                mma_f16(acc[0], w1lo[kt], bh[0], bh[1]);
                mma_f16(acc[1], w1lo[kt], bh[2], bh[3]);
            }
            float pp[8];
            #pragma unroll
            for (int i = 0; i < 4; ++i) {
                pp[i]     = __shfl_xor_sync(~0u, acc[0][i], 16);
                pp[4 + i] = __shfl_xor_sync(~0u, acc[1][i], 16);
            }
            float iA, fA, gA, oA, iB, fB, gB, oB;
            if (q < 4) {
                iA = acc[0][0]; gA = acc[0][2]; fA = pp[0]; oA = pp[2];
                iB = acc[0][1]; gB = acc[0][3]; fB = pp[1]; oB = pp[3];
            } else {
                iA = pp[4]; gA = pp[6]; fA = acc[1][0]; oA = acc[1][2];
                iB = pp[5]; gB = pp[7]; fB = acc[1][1]; oB = acc[1][3];
            }
            c10 = sigm(fA) * c10 + sigm(iA) * tanh_f(gA);
            c11 = sigm(fB) * c11 + sigm(iB) * tanh_f(gB);
            float h1A = sigm(oA) * tanh_f(c10);
            float h1B = sigm(oB) * tanh_f(c11);
            if (u == TT) {
                hfin[jp * 16 + nbA] = h1A;
                hfin[jp * 16 + nbB] = h1B;
            } else {
                *(__half*)(smp + z1w + nbA * ZROWB + (64 + jp) * 2) = __float2half_rn(h1A);
                *(__half*)(smp + z1w + nbB * ZROWB + (64 + jp) * 2) = __float2half_rn(h1B);
            }
        }
        __syncthreads();
    }

    // ---- fused GAT1 projection (aliases dead Z0 region) ----
    float* W1s = (float*)(smp + W1S_OFF);
    float* asv = (float*)(smp + ASV_OFF);
    float* adv = (float*)(smp + ADV_OFF);
    float* h1b = (float*)(smp + H1B_OFF);
    for (int idx = tid; idx < HH * 16; idx += 512) W1s[idx] = gat1_W[idx];
    if (tid < 32) {
        if (tid < 16) asv[tid] = gat1_as[tid];
        else          adv[tid - 16] = gat1_ad[tid - 16];
    }
    __syncthreads();
    if (tid < 256) {
        int nb = tid & 15, jj = tid >> 4;
        float hv = 0.f;
        #pragma unroll
        for (int k = 0; k < HH; ++k) hv += hfin[k * 16 + nb] * W1s[k * 16 + jj];
        h1b[nb * 16 + jj] = hv;
        g_h1[(size_t)(n0 + nb) * 16 + jj] = hv;
    }
    __syncthreads();
    if (tid < 32) {
        int nb = tid & 15;
        const float* av = (tid < 16) ? asv : adv;
        float sv = 0.f;
        #pragma unroll
        for (int jj = 0; jj < 16; ++jj) sv += h1b[nb * 16 + jj] * av[jj];
        if (tid < 16) g_s1[n0 + nb] = sv; else g_d1[n0 + nb] = sv;
    }
}

// ================= adjacency bitmask =================
__global__ void k_adj(const float* __restrict__ rel_mask) {
    int j  = blockIdx.x * 256 + threadIdx.x;
    int c0 = blockIdx.y * 4;
    for (int c = c0; c < c0 + 4; ++c) {
        unsigned w = 0;
        #pragma unroll 8
        for (int b = 0; b < 32; ++b) {
            int i = c * 32 + b;
            float v = rel_mask[(size_t)i * NN + j];
            if (v > -1.f || i == j) w |= (1u << b);
        }
        g_adjT[j * NWRD + c] = w;
    }
}

// ================= GAT1 aggregate (single-pass softmax) + fused GAT2 projection ===
__global__ void __launch_bounds__(256) k_gmain1(const float* __restrict__ b1,
                                                const float* __restrict__ W2,
                                                const float* __restrict__ as2,
                                                const float* __restrict__ ad2)
{
    __shared__ float W2s[16 * 64], a2s[64], a2d[64], ob[8][16];
    int tid = threadIdx.x;
    for (int i = tid; i < 16 * 64; i += 256) W2s[i] = W2[i];
    if (tid < 64) { a2s[tid] = as2[tid]; a2d[tid] = ad2[tid]; }
    __syncthreads();

    int warp = tid >> 5, lane = tid & 31;
    int j = blockIdx.x * 8 + warp;
    float dj = g_d1[j];
    const unsigned* adjw = &g_adjT[j * NWRD];

    float sum = 0.f, acc[16];
    #pragma unroll
    for (int h = 0; h < 16; ++h) acc[h] = 0.f;
    for (int c = lane * 2; c < lane * 2 + 2; ++c) {
        unsigned w = adjw[c];
        while (w) {
            int b = __ffs(w) - 1; w &= w - 1;
            int i = c * 32 + b;
            float al = __expf(lrelu(g_s1[i] + dj));
            sum += al;
            const float4* hp = (const float4*)&g_h1[i * 16];
            float4 v0 = hp[0], v1 = hp[1], v2 = hp[2], v3 = hp[3];
            acc[0] += al * v0.x; acc[1] += al * v0.y; acc[2]  += al * v0.z; acc[3]  += al * v0.w;
            acc[4] += al * v1.x; acc[5] += al * v1.y; acc[6]  += al * v1.z; acc[7]  += al * v1.w;
            acc[8] += al * v2.x; acc[9] += al * v2.y; acc[10] += al * v2.z; acc[11] += al * v2.w;
            acc[12] += al * v3.x; acc[13] += al * v3.y; acc[14] += al * v3.z; acc[15] += al * v3.w;
        }
    }
    #pragma unroll
    for (int o = 16; o; o >>= 1) sum += __shfl_xor_sync(~0u, sum, o);
    #pragma unroll
    for (int h = 0; h < 16; ++h) {
        #pragma unroll
        for (int o = 16; o; o >>= 1) acc[h] += __shfl_xor_sync(~0u, acc[h], o);
    }
    float inv = 1.f / sum;

    int hsel = lane & 15;
    float vsel = acc[0];
    #pragma unroll
    for (int h = 1; h < 16; ++h) if (hsel == h) vsel = acc[h];
    if (lane < 16) {
        float v = vsel * inv + b1[lane];
        ob[warp][lane] = v > 0.f ? v : 0.f;
    }
    __syncwarp();

    float o[16];
    #pragma unroll
    for (int k = 0; k < 16; ++k) o[k] = ob[warp][k];
    float hv0 = 0.f, hv1 = 0.f;
    #pragma unroll
    for (int k = 0; k < 16; ++k) {
        hv0 += o[k] * W2s[k * 64 + lane];
        hv1 += o[k] * W2s[k * 64 + lane + 32];
    }
    g_h2[(size_t)j * 64 + lane]      = hv0;
    g_h2[(size_t)j * 64 + lane + 32] = hv1;
    float sp = hv0 * a2s[lane] + hv1 * a2s[lane + 32];
    float dp = hv0 * a2d[lane] + hv1 * a2d[lane + 32];
    #pragma unroll
    for (int oo = 16; oo; oo >>= 1) {
        sp += __shfl_xor_sync(~0u, sp, oo);
        dp += __shfl_xor_sync(~0u, dp, oo);
    }
    if (lane == 0) { g_s2[j] = sp; g_d2[j] = dp; }
}

// ================= GAT2 aggregate (single-pass softmax) + FC =================
__global__ void __launch_bounds__(256) k_gmain2(const float* __restrict__ b2,
                                                const float* __restrict__ fcW,
                                                const float* __restrict__ fcb,
                                                float* __restrict__ out)
{
    int warp = threadIdx.x >> 5, lane = threadIdx.x & 31;
    int j = blockIdx.x * 8 + warp;
    float dj = g_d2[j];
    const unsigned* adjw = &g_adjT[j * NWRD];

    int sg = lane >> 3, d8 = lane & 7;
    float sum = 0.f, acc[8];
    #pragma unroll
    for (int k = 0; k < 8; ++k) acc[k] = 0.f;
    for (int c = sg * 16; c < sg * 16 + 16; ++c) {
        unsigned w = adjw[c];
        while (w) {
            int b = __ffs(w) - 1; w &= w - 1;
            int i = c * 32 + b;
            float al = __expf(lrelu(g_s2[i] + dj));
            sum += al;
            const float4* hp = (const float4*)&g_h2[(size_t)i * 64 + d8 * 8];
            float4 v0 = hp[0], v1 = hp[1];
            acc[0] += al * v0.x; acc[1] += al * v0.y; acc[2] += al * v0.z; acc[3] += al * v0.w;
            acc[4] += al * v1.x; acc[5] += al * v1.y; acc[6] += al * v1.z; acc[7] += al * v1.w;
        }
    }
    #pragma unroll
    for (int k = 0; k < 8; ++k) {
        acc[k] += __shfl_xor_sync(~0u, acc[k], 8);
        acc[k] += __shfl_xor_sync(~0u, acc[k], 16);
    }
    sum += __shfl_xor_sync(~0u, sum, 8);
    sum += __shfl_xor_sync(~0u, sum, 16);
    float inv = 1.f / sum;

    float part = 0.f;
    #pragma unroll
    for (int k = 0; k < 8; ++k)
        part += (acc[k] * inv + b2[d8 * 8 + k]) * fcW[d8 * 8 + k];
    part += __shfl_xor_sync(~0u, part, 1);
    part += __shfl_xor_sync(~0u, part, 2);
    part += __shfl_xor_sync(~0u, part, 4);
    if (lane == 0) out[j] = lrelu(part + fcb[0]);
}

// ================= launch =================
extern "C" void kernel_launch(void* const* d_in, const int* in_sizes, int n_in,
                              void* d_out, int out_size)
{
    const float* inputs   = (const float*)d_in[0];
    // d_in[1] relation, d_in[3] rel_w_W, d_in[4] rel_w_b: provably unused (adj = mask|diag)
    const float* rel_mask = (const float*)d_in[2];
    const float* w_ih0 = (const float*)d_in[5];
    const float* w_hh0 = (const float*)d_in[6];
    const float* b_ih0 = (const float*)d_in[7];
    const float* b_hh0 = (const float*)d_in[8];
    const float* w_ih1 = (const float*)d_in[9];
    const float* w_hh1 = (const float*)d_in[10];
    const float* b_ih1 = (const float*)d_in[11];
    const float* b_hh1 = (const float*)d_in[12];
    const float* gat1_W  = (const float*)d_in[13];
    const float* gat1_as = (const float*)d_in[14];
    const float* gat1_ad = (const float*)d_in[15];
    const float* gat1_b  = (const float*)d_in[16];
    const float* gat2_W  = (const float*)d_in[17];
    const float* gat2_as = (const float*)d_in[18];
    const float* gat2_ad = (const float*)d_in[19];
    const float* gat2_b  = (const float*)d_in[20];
    const float* fc_W    = (const float*)d_in[21];
    const float* fc_b    = (const float*)d_in[22];

    cudaFuncSetAttribute(k_lstm_fused, cudaFuncAttributeMaxDynamicSharedMemorySize, SMEM_REQ);

    k_adj<<<dim3(8, 16), 256>>>(rel_mask);
    k_lstm_fused<<<NBLK, 512, SMEM_REQ>>>(inputs, w_ih0, w_hh0, b_ih0, b_hh0,
                                          w_ih1, w_hh1, b_ih1, b_hh1,
                                          gat1_W, gat1_as, gat1_ad);
    k_gmain1<<<NN / 8, 256>>>(gat1_b, gat2_W, gat2_as, gat2_ad);
    k_gmain2<<<NN / 8, 256>>>(gat2_b, fc_W, fc_b, (float*)d_out);
}

// round 14
// speedup vs baseline: 2.5081x; 1.0194x over previous
#include <cuda_runtime.h>
#include <cuda_fp16.h>

#define NN   2048
#define TT   32
#define FIN  5
#define HH   64
#define NB   16
#define NBLK 128
#define NWRD 64

// ---- smem layout: fused LSTM ----
#define ZROWB    272
#define Z0A      0
#define Z1A      8704
#define ZSTRIDE  4352
#define XS_OFF   17408
#define SMEM_REQ 28672
// post-loop GAT aliases:
#define W1S_OFF  0
#define ASV_OFF  4096
#define ADV_OFF  4160
#define H1B_OFF  4224

// -------- scratch (device globals) --------
__device__ unsigned g_adjT[NN * NWRD];
__device__ float g_h1[NN * 16];
__device__ float g_s1[NN], g_d1[NN];
__device__ float g_h2[NN * HH];
__device__ float g_s2[NN], g_d2[NN];

// -------- helpers --------
__device__ __forceinline__ unsigned smem_u32(const void* p) {
    unsigned a;
    asm("{ .reg .u64 t; cvta.to.shared.u64 t, %1; cvt.u32.u64 %0, t; }" : "=r"(a) : "l"(p));
    return a;
}
__device__ __forceinline__ float sigm(float x)   { return 1.f / (1.f + __expf(-x)); }
__device__ __forceinline__ float tanh_f(float x) { return 1.f - 2.f / (__expf(2.f * x) + 1.f); }
__device__ __forceinline__ float lrelu(float x)  { return x >= 0.f ? x : 0.2f * x; }

__device__ __forceinline__ unsigned packhi(float w0, float w1) {
    return (unsigned)__half_as_ushort(__float2half_rn(w0))
         | ((unsigned)__half_as_ushort(__float2half_rn(w1)) << 16);
}
__device__ __forceinline__ void packsplit(float w0, float w1, unsigned& hi, unsigned& lo) {
    __half h0 = __float2half_rn(w0), h1 = __float2half_rn(w1);
    __half l0 = __float2half_rn(w0 - __half2float(h0));
    __half l1 = __float2half_rn(w1 - __half2float(h1));
    hi = (unsigned)__half_as_ushort(h0) | ((unsigned)__half_as_ushort(h1) << 16);
    lo = (unsigned)__half_as_ushort(l0) | ((unsigned)__half_as_ushort(l1) << 16);
}
__device__ __forceinline__ void mma_f16(float* d, const unsigned* a, unsigned b0, unsigned b1) {
    asm volatile(
        "mma.sync.aligned.m16n8k16.row.col.f32.f16.f16.f32 "
        "{%0,%1,%2,%3}, {%4,%5,%6,%7}, {%8,%9}, {%0,%1,%2,%3};"
        : "+f"(d[0]), "+f"(d[1]), "+f"(d[2]), "+f"(d[3])
        : "r"(a[0]), "r"(a[1]), "r"(a[2]), "r"(a[3]), "r"(b0), "r"(b1));
}
__device__ __forceinline__ void ldmx4(unsigned addr, unsigned* r) {
    asm volatile("ldmatrix.sync.aligned.m8n8.x4.shared.b16 {%0,%1,%2,%3}, [%4];"
                 : "=r"(r[0]), "=r"(r[1]), "=r"(r[2]), "=r"(r[3]) : "r"(addr));
}

extern __shared__ float4 smemv[];

__device__ __forceinline__ float getw0(const float* wih, const float* whh, int gate, int c) {
    if (c < FIN) return wih[gate * FIN + c];
    if (c < 16)  return 0.f;
    return whh[gate * HH + (c - 16)];
}
__device__ __forceinline__ float getw1(const float* wih, const float* whh, int gate, int c) {
    if (c < 64) return wih[gate * HH + c];
    return whh[gate * HH + (c - 64)];
}

// ================= fused 2-layer HMMA LSTM, software-pipelined =================
__global__ void __launch_bounds__(512, 1) k_lstm_fused(
    const float* __restrict__ inputs,
    const float* __restrict__ w_ih0, const float* __restrict__ w_hh0,
    const float* __restrict__ b_ih0, const float* __restrict__ b_hh0,
    const float* __restrict__ w_ih1, const float* __restrict__ w_hh1,
    const float* __restrict__ b_ih1, const float* __restrict__ b_hh1,
    const float* __restrict__ gat1_W, const float* __restrict__ gat1_as,
    const float* __restrict__ gat1_ad)
{
    char* smp = (char*)smemv;
    unsigned sbu = smem_u32(smemv);

    int tid  = threadIdx.x;
    int wid  = tid >> 5;
    int lane = tid & 31;
    int blk  = blockIdx.x;
    int n0   = blk * NB;

    {
        float4 z4 = make_float4(0.f, 0.f, 0.f, 0.f);
        float4* dst = (float4*)smp;
        for (int i = tid; i < 4 * ZSTRIDE / 16; i += 512) dst[i] = z4;
    }

    int q = lane >> 2, s = lane & 3;
    int gateA = (q >> 2) * 64 + 4 * wid + (q & 3);
    int gateB = gateA + 128;
    unsigned w0hi[5][4];
    #pragma unroll
    for (int kt = 0; kt < 5; ++kt) {
        int c = kt * 16 + s * 2;
        w0hi[kt][0] = packhi(getw0(w_ih0, w_hh0, gateA, c),     getw0(w_ih0, w_hh0, gateA, c + 1));
        w0hi[kt][1] = packhi(getw0(w_ih0, w_hh0, gateB, c),     getw0(w_ih0, w_hh0, gateB, c + 1));
        w0hi[kt][2] = packhi(getw0(w_ih0, w_hh0, gateA, c + 8), getw0(w_ih0, w_hh0, gateA, c + 9));
        w0hi[kt][3] = packhi(getw0(w_ih0, w_hh0, gateB, c + 8), getw0(w_ih0, w_hh0, gateB, c + 9));
    }
    unsigned w1hi[8][4], w1lo[8][4];
    #pragma unroll
    for (int kt = 0; kt < 8; ++kt) {
        int c = kt * 16 + s * 2;
        packsplit(getw1(w_ih1, w_hh1, gateA, c),     getw1(w_ih1, w_hh1, gateA, c + 1),
                  w1hi[kt][0], w1lo[kt][0]);
        packsplit(getw1(w_ih1, w_hh1, gateB, c),     getw1(w_ih1, w_hh1, gateB, c + 1),
                  w1hi[kt][1], w1lo[kt][1]);
        packsplit(getw1(w_ih1, w_hh1, gateA, c + 8), getw1(w_ih1, w_hh1, gateA, c + 9),
                  w1hi[kt][2], w1lo[kt][2]);
        packsplit(getw1(w_ih1, w_hh1, gateB, c + 8), getw1(w_ih1, w_hh1, gateB, c + 9),
                  w1hi[kt][3], w1lo[kt][3]);
    }
    float bA0 = b_ih0[gateA] + b_hh0[gateA], bB0 = b_ih0[gateB] + b_hh0[gateB];
    float bA1 = b_ih1[gateA] + b_hh1[gateA], bB1 = b_ih1[gateB] + b_hh1[gateB];

    float* xs = (float*)(smp + XS_OFF);
    for (int idx = tid; idx < NB * TT * FIN; idx += 512) {
        int nb = idx / (TT * FIN);
        int r  = idx % (TT * FIN);
        int t  = r / FIN, f = r % FIN;
        xs[t * 80 + f * 16 + nb] = inputs[(size_t)(n0 + nb) * (TT * FIN) + t * FIN + f];
    }
    if (tid < 80) {
        int f = tid >> 4, nb = tid & 15;
        *(__half*)(smp + Z0A + nb * ZROWB + f * 2) =
            __float2half_rn(inputs[(size_t)(n0 + nb) * (TT * FIN) + f]);
    }
    __syncthreads();

    int nrow  = (lane & 7) + ((lane >> 4) << 3);
    int khalf = (lane >> 3) & 1;
    unsigned zrel = nrow * ZROWB + khalf * 16;

    float* hfin = (float*)(smp + XS_OFF);
    int jp  = 4 * wid + (q & 3);
    int nbA = (q < 4) ? 2 * s : 8 + 2 * s;
    int nbB = nbA + 1;
    float c00 = 0.f, c01 = 0.f;
    float c10 = 0.f, c11 = 0.f;

    #pragma unroll 1
    for (int u = 0; u <= TT; ++u) {
        int p = u & 1;
        unsigned z0r = Z0A + p * ZSTRIDE,        z0w = Z0A + (p ^ 1) * ZSTRIDE;
        unsigned z1r = Z1A + (p ^ 1) * ZSTRIDE,  z1w = Z1A + p * ZSTRIDE;

        if (u < TT) {
            float acc[2][4];
            acc[0][0] = bA0; acc[0][1] = bA0; acc[0][2] = bB0; acc[0][3] = bB0;
            acc[1][0] = bA0; acc[1][1] = bA0; acc[1][2] = bB0; acc[1][3] = bB0;
            unsigned zb = sbu + z0r + zrel;
            #pragma unroll
            for (int kt = 0; kt < 5; ++kt) {
                unsigned bh[4];
                ldmx4(zb + kt * 32, bh);
                mma_f16(acc[0], w0hi[kt], bh[0], bh[1]);
                mma_f16(acc[1], w0hi[kt], bh[2], bh[3]);
            }
            float pp[8];
            #pragma unroll
            for (int i = 0; i < 4; ++i) {
                pp[i]     = __shfl_xor_sync(~0u, acc[0][i], 16);
                pp[4 + i] = __shfl_xor_sync(~0u, acc[1][i], 16);
            }
            float iA, fA, gA, oA, iB, fB, gB, oB;
            if (q < 4) {
                iA = acc[0][0]; gA = acc[0][2]; fA = pp[0]; oA = pp[2];
                iB = acc[0][1]; gB = acc[0][3]; fB = pp[1]; oB = pp[3];
            } else {
                iA = pp[4]; gA = pp[6]; fA = acc[1][0]; oA = acc[1][2];
                iB = pp[5]; gB = pp[7]; fB = acc[1][1]; oB = acc[1][3];
            }
            c00 = sigm(fA) * c00 + sigm(iA) * tanh_f(gA);
            c01 = sigm(fB) * c01 + sigm(iB) * tanh_f(gB);
            float h0A = sigm(oA) * tanh_f(c00);
            float h0B = sigm(oB) * tanh_f(c01);
            __half h0Ah = __float2half_rn(h0A), h0Bh = __float2half_rn(h0B);
            *(__half*)(smp + z0w + nbA * ZROWB + (16 + jp) * 2) = h0Ah;
            *(__half*)(smp + z0w + nbB * ZROWB + (16 + jp) * 2) = h0Bh;
            *(__half*)(smp + z1w + nbA * ZROWB + jp * 2) = h0Ah;
            *(__half*)(smp + z1w + nbB * ZROWB + jp * 2) = h0Bh;
            if (u + 1 < TT && tid < 80) {
                int f = tid >> 4, nb = tid & 15;
                *(__half*)(smp + z0w + nb * ZROWB + f * 2) =
                    __float2half_rn(xs[(u + 1) * 80 + f * 16 + nb]);
            }
        }

        if (u >= 1) {
            float acc[2][4];
            acc[0][0] = bA1; acc[0][1] = bA1; acc[0][2] = bB1; acc[0][3] = bB1;
            acc[1][0] = bA1; acc[1][1] = bA1; acc[1][2] = bB1; acc[1][3] = bB1;
            unsigned zb = sbu + z1r + zrel;
            #pragma unroll
            for (int kt = 0; kt < 8; ++kt) {
                unsigned bh[4];
                ldmx4(zb + kt * 32, bh);
                mma_f16(acc[0], w1hi[kt], bh[0], bh[1]);
                mma_f16(acc[1], w1hi[kt], bh[2], bh[3]);
                mma_f16(acc[0], w1lo[kt], bh[0], bh[1]);
                mma_f16(acc[1], w1lo[kt], bh[2], bh[3]);
            }
            float pp[8];
            #pragma unroll
            for (int i = 0; i < 4; ++i) {
                pp[i]     = __shfl_xor_sync(~0u, acc[0][i], 16);
                pp[4 + i] = __shfl_xor_sync(~0u, acc[1][i], 16);
            }
            float iA, fA, gA, oA, iB, fB, gB, oB;
            if (q < 4) {
                iA = acc[0][0]; gA = acc[0][2]; fA = pp[0]; oA = pp[2];
                iB = acc[0][1]; gB = acc[0][3]; fB = pp[1]; oB = pp[3];
            } else {
                iA = pp[4]; gA = pp[6]; fA = acc[1][0]; oA = acc[1][2];
                iB = pp[5]; gB = pp[7]; fB = acc[1][1]; oB = acc[1][3];
            }
            c10 = sigm(fA) * c10 + sigm(iA) * tanh_f(gA);
            c11 = sigm(fB) * c11 + sigm(iB) * tanh_f(gB);
            float h1A = sigm(oA) * tanh_f(c10);
            float h1B = sigm(oB) * tanh_f(c11);
            if (u == TT) {
                hfin[jp * 16 + nbA] = h1A;
                hfin[jp * 16 + nbB] = h1B;
            } else {
                *(__half*)(smp + z1w + nbA * ZROWB + (64 + jp) * 2) = __float2half_rn(h1A);
                *(__half*)(smp + z1w + nbB * ZROWB + (64 + jp) * 2) = __float2half_rn(h1B);
            }
        }
        __syncthreads();
    }

    // ---- fused GAT1 projection ----
    float* W1s = (float*)(smp + W1S_OFF);
    float* asv = (float*)(smp + ASV_OFF);
    float* adv = (float*)(smp + ADV_OFF);
    float* h1b = (float*)(smp + H1B_OFF);
    for (int idx = tid; idx < HH * 16; idx += 512) W1s[idx] = gat1_W[idx];
    if (tid < 32) {
        if (tid < 16) asv[tid] = gat1_as[tid];
        else          adv[tid - 16] = gat1_ad[tid - 16];
    }
    __syncthreads();
    if (tid < 256) {
        int nb = tid & 15, jj = tid >> 4;
        float hv = 0.f;
        #pragma unroll
        for (int k = 0; k < HH; ++k) hv += hfin[k * 16 + nb] * W1s[k * 16 + jj];
        h1b[nb * 16 + jj] = hv;
        g_h1[(size_t)(n0 + nb) * 16 + jj] = hv;
    }
    __syncthreads();
    if (tid < 32) {
        int nb = tid & 15;
        const float* av = (tid < 16) ? asv : adv;
        float sv = 0.f;
        #pragma unroll
        for (int jj = 0; jj < 16; ++jj) sv += h1b[nb * 16 + jj] * av[jj];
        if (tid < 16) g_s1[n0 + nb] = sv; else g_d1[n0 + nb] = sv;
    }
}

// ================= adjacency bitmask =================
__global__ void k_adj(const float* __restrict__ rel_mask) {
    int j  = blockIdx.x * 256 + threadIdx.x;
    int c0 = blockIdx.y * 4;
    for (int c = c0; c < c0 + 4; ++c) {
        unsigned w = 0;
        #pragma unroll 8
        for (int b = 0; b < 32; ++b) {
            int i = c * 32 + b;
            float v = rel_mask[(size_t)i * NN + j];
            if (v > -1.f || i == j) w |= (1u << b);
        }
        g_adjT[j * NWRD + c] = w;
    }
}

// ================= GAT1 aggregate + fused GAT2 projection =================
// 4 j per block (256 thr); 2 warps per j; 1 adjacency word per lane. s1 in smem.
__global__ void __launch_bounds__(256) k_gmain1(const float* __restrict__ b1,
                                                const float* __restrict__ W2,
                                                const float* __restrict__ as2,
                                                const float* __restrict__ ad2)
{
    __shared__ float s1s[NN];
    __shared__ float W2s[16 * 64], a2s[64], a2d[64];
    __shared__ float red[4][2][17];
    __shared__ float ob[4][16];
    int tid = threadIdx.x;
    for (int i = tid; i < NN; i += 256) s1s[i] = g_s1[i];
    for (int i = tid; i < 16 * 64; i += 256) W2s[i] = W2[i];
    if (tid < 64) { a2s[tid] = as2[tid]; a2d[tid] = ad2[tid]; }
    __syncthreads();

    int warp = tid >> 5, lane = tid & 31;
    int jloc = warp >> 1, wh = warp & 1;
    int j = blockIdx.x * 4 + jloc;
    float dj = g_d1[j];

    int word = wh * 32 + lane;
    unsigned w = g_adjT[j * NWRD + word];
    float sum = 0.f, acc[16];
    #pragma unroll
    for (int h = 0; h < 16; ++h) acc[h] = 0.f;
    while (w) {
        int b = __ffs(w) - 1; w &= w - 1;
        int i = word * 32 + b;
        float al = __expf(lrelu(s1s[i] + dj));
        sum += al;
        const float4* hp = (const float4*)&g_h1[i * 16];
        float4 v0 = hp[0], v1 = hp[1], v2 = hp[2], v3 = hp[3];
        acc[0] += al * v0.x; acc[1] += al * v0.y; acc[2]  += al * v0.z; acc[3]  += al * v0.w;
        acc[4] += al * v1.x; acc[5] += al * v1.y; acc[6]  += al * v1.z; acc[7]  += al * v1.w;
        acc[8] += al * v2.x; acc[9] += al * v2.y; acc[10] += al * v2.z; acc[11] += al * v2.w;
        acc[12] += al * v3.x; acc[13] += al * v3.y; acc[14] += al * v3.z; acc[15] += al * v3.w;
    }
    #pragma unroll
    for (int o = 16; o; o >>= 1) sum += __shfl_xor_sync(~0u, sum, o);
    #pragma unroll
    for (int h = 0; h < 16; ++h) {
        #pragma unroll
        for (int o = 16; o; o >>= 1) acc[h] += __shfl_xor_sync(~0u, acc[h], o);
    }
    // write warp partials (predicated select avoids dynamic reg index)
    {
        int hsel = lane & 15;
        float vsel = acc[0];
        #pragma unroll
        for (int h = 1; h < 16; ++h) if (hsel == h) vsel = acc[h];
        if (lane < 16) red[jloc][wh][lane] = vsel;
        if (lane == 16) red[jloc][wh][16] = sum;
    }
    __syncthreads();

    // combine 2 warps + finish (even warp of each jloc)
    if (wh == 0 && lane < 16) {
        float tot = red[jloc][0][lane] + red[jloc][1][lane];
        float S   = red[jloc][0][16] + red[jloc][1][16];
        float v = tot / S + b1[lane];
        ob[jloc][lane] = v > 0.f ? v : 0.f;
    }
    __syncthreads();

    if (wh == 0) {
        float o[16];
        #pragma unroll
        for (int k = 0; k < 16; ++k) o[k] = ob[jloc][k];
        float hv0 = 0.f, hv1 = 0.f;
        #pragma unroll
        for (int k = 0; k < 16; ++k) {
            hv0 += o[k] * W2s[k * 64 + lane];
            hv1 += o[k] * W2s[k * 64 + lane + 32];
        }
        g_h2[(size_t)j * 64 + lane]      = hv0;
        g_h2[(size_t)j * 64 + lane + 32] = hv1;
        float sp = hv0 * a2s[lane] + hv1 * a2s[lane + 32];
        float dp = hv0 * a2d[lane] + hv1 * a2d[lane + 32];
        #pragma unroll
        for (int oo = 16; oo; oo >>= 1) {
            sp += __shfl_xor_sync(~0u, sp, oo);
            dp += __shfl_xor_sync(~0u, dp, oo);
        }
        if (lane == 0) { g_s2[j] = sp; g_d2[j] = dp; }
    }
}

// ================= GAT2 aggregate + FC =================
// 2 j per block; 4 warps per j; warp scans 16 words, sg(8 lanes) scans 4, d8 owns 8 dims.
// FC dot folded pre-normalization: out = lrelu(num/S + dot(b2,fcW) + fcb).
__global__ void __launch_bounds__(256) k_gmain2(const float* __restrict__ b2,
                                                const float* __restrict__ fcW,
                                                const float* __restrict__ fcb,
                                                float* __restrict__ out)
{
    __shared__ float s2s[NN];
    __shared__ float bd[64];
    __shared__ float red[2][4][2];
    int tid = threadIdx.x;
    for (int i = tid; i < NN; i += 256) s2s[i] = g_s2[i];
    if (tid < 64) bd[tid] = b2[tid] * fcW[tid];
    __syncthreads();

    int warp = tid >> 5, lane = tid & 31;
    int jloc = warp >> 2, wq = warp & 3;
    int j = blockIdx.x * 2 + jloc;
    float dj = g_d2[j];
    const unsigned* adjw = &g_adjT[j * NWRD];

    int sg = lane >> 3, d8 = lane & 7;
    float sum = 0.f, acc[8];
    #pragma unroll
    for (int k = 0; k < 8; ++k) acc[k] = 0.f;
    int cbase = wq * 16 + sg * 4;
    #pragma unroll
    for (int cc = 0; cc < 4; ++cc) {
        unsigned w = adjw[cbase + cc];
        while (w) {
            int b = __ffs(w) - 1; w &= w - 1;
            int i = (cbase + cc) * 32 + b;
            float al = __expf(lrelu(s2s[i] + dj));
            sum += al;
            const float4* hp = (const float4*)&g_h2[(size_t)i * 64 + d8 * 8];
            float4 v0 = hp[0], v1 = hp[1];
            acc[0] += al * v0.x; acc[1] += al * v0.y; acc[2] += al * v0.z; acc[3] += al * v0.w;
            acc[4] += al * v1.x; acc[5] += al * v1.y; acc[6] += al * v1.z; acc[7] += al * v1.w;
        }
    }
    // reduce across sg (bits 3,4); sum is per-sg distinct (each sg scans its own 4 words)
    #pragma unroll
    for (int k = 0; k < 8; ++k) {
        acc[k] += __shfl_xor_sync(~0u, acc[k], 8);
        acc[k] += __shfl_xor_sync(~0u, acc[k], 16);
    }
    sum += __shfl_xor_sync(~0u, sum, 8);
    sum += __shfl_xor_sync(~0u, sum, 16);

    // per-warp numerator dot with fcW, reduce over d8 (bits 0-2)
    float nd = 0.f;
    #pragma unroll
    for (int k = 0; k < 8; ++k) nd += acc[k] * fcW[d8 * 8 + k];
    nd += __shfl_xor_sync(~0u, nd, 1);
    nd += __shfl_xor_sync(~0u, nd, 2);
    nd += __shfl_xor_sync(~0u, nd, 4);
    if (lane == 0) { red[jloc][wq][0] = nd; red[jloc][wq][1] = sum; }
    __syncthreads();

    if (tid < 2) {
        float num = red[tid][0][0] + red[tid][1][0] + red[tid][2][0] + red[tid][3][0];
        float S   = red[tid][0][1] + red[tid][1][1] + red[tid][2][1] + red[tid][3][1];
        float bdot = 0.f;
        #pragma unroll
        for (int k = 0; k < 64; ++k) bdot += bd[k];
        out[blockIdx.x * 2 + tid] = lrelu(num / S + bdot + fcb[0]);
    }
}

// ================= launch =================
extern "C" void kernel_launch(void* const* d_in, const int* in_sizes, int n_in,
                              void* d_out, int out_size)
{
    const float* inputs   = (const float*)d_in[0];
    // d_in[1] relation, d_in[3] rel_w_W, d_in[4] rel_w_b: provably unused (adj = mask|diag)
    const float* rel_mask = (const float*)d_in[2];
    const float* w_ih0 = (const float*)d_in[5];
    const float* w_hh0 = (const float*)d_in[6];
    const float* b_ih0 = (const float*)d_in[7];
    const float* b_hh0 = (const float*)d_in[8];
    const float* w_ih1 = (const float*)d_in[9];
    const float* w_hh1 = (const float*)d_in[10];
    const float* b_ih1 = (const float*)d_in[11];
    const float* b_hh1 = (const float*)d_in[12];
    const float* gat1_W  = (const float*)d_in[13];
    const float* gat1_as = (const float*)d_in[14];
    const float* gat1_ad = (const float*)d_in[15];
    const float* gat1_b  = (const float*)d_in[16];
    const float* gat2_W  = (const float*)d_in[17];
    const float* gat2_as = (const float*)d_in[18];
    const float* gat2_ad = (const float*)d_in[19];
    const float* gat2_b  = (const float*)d_in[20];
    const float* fc_W    = (const float*)d_in[21];
    const float* fc_b    = (const float*)d_in[22];

    cudaFuncSetAttribute(k_lstm_fused, cudaFuncAttributeMaxDynamicSharedMemorySize, SMEM_REQ);

    k_adj<<<dim3(8, 16), 256>>>(rel_mask);
    k_lstm_fused<<<NBLK, 512, SMEM_REQ>>>(inputs, w_ih0, w_hh0, b_ih0, b_hh0,
                                          w_ih1, w_hh1, b_ih1, b_hh1,
                                          gat1_W, gat1_as, gat1_ad);
    k_gmain1<<<NN / 4, 256>>>(gat1_b, gat2_W, gat2_as, gat2_ad);
    k_gmain2<<<NN / 2, 256>>>(gat2_b, fc_W, fc_b, (float*)d_out);
}

// round 15
// speedup vs baseline: 2.5607x; 1.0210x over previous
#include <cuda_runtime.h>
#include <cuda_fp16.h>

#define NN   2048
#define TT   32
#define FIN  5
#define HH   64
#define NB   16
#define NBLK 128
#define NWRD 64

// ---- smem layout: fused LSTM ----
#define ZROWB    272
#define Z0A      0
#define Z1A      8704
#define ZSTRIDE  4352
#define XS_OFF   17408
#define SMEM_REQ 28672
// post-loop GAT aliases:
#define W1S_OFF  0
#define ASV_OFF  4096
#define ADV_OFF  4160
#define H1B_OFF  4224

// -------- scratch (device globals) --------
__device__ unsigned g_adjT[NN * NWRD];
__device__ float g_h1[NN * 16];
__device__ float g_s1[NN], g_d1[NN];
__device__ float g_y[NN];               // y[i] = h2[i] . fcW  (FC folded)
__device__ float g_s2[NN], g_d2[NN];

// -------- helpers --------
__device__ __forceinline__ unsigned smem_u32(const void* p) {
    unsigned a;
    asm("{ .reg .u64 t; cvta.to.shared.u64 t, %1; cvt.u32.u64 %0, t; }" : "=r"(a) : "l"(p));
    return a;
}
__device__ __forceinline__ float sigm(float x)   { return 1.f / (1.f + __expf(-x)); }
__device__ __forceinline__ float tanh_f(float x) { return 1.f - 2.f / (__expf(2.f * x) + 1.f); }
__device__ __forceinline__ float lrelu(float x)  { return x >= 0.f ? x : 0.2f * x; }

__device__ __forceinline__ unsigned packhi(float w0, float w1) {
    return (unsigned)__half_as_ushort(__float2half_rn(w0))
         | ((unsigned)__half_as_ushort(__float2half_rn(w1)) << 16);
}
__device__ __forceinline__ void packsplit(float w0, float w1, unsigned& hi, unsigned& lo) {
    __half h0 = __float2half_rn(w0), h1 = __float2half_rn(w1);
    __half l0 = __float2half_rn(w0 - __half2float(h0));
    __half l1 = __float2half_rn(w1 - __half2float(h1));
    hi = (unsigned)__half_as_ushort(h0) | ((unsigned)__half_as_ushort(h1) << 16);
    lo = (unsigned)__half_as_ushort(l0) | ((unsigned)__half_as_ushort(l1) << 16);
}
__device__ __forceinline__ void mma_f16(float* d, const unsigned* a, unsigned b0, unsigned b1) {
    asm volatile(
        "mma.sync.aligned.m16n8k16.row.col.f32.f16.f16.f32 "
        "{%0,%1,%2,%3}, {%4,%5,%6,%7}, {%8,%9}, {%0,%1,%2,%3};"
        : "+f"(d[0]), "+f"(d[1]), "+f"(d[2]), "+f"(d[3])
        : "r"(a[0]), "r"(a[1]), "r"(a[2]), "r"(a[3]), "r"(b0), "r"(b1));
}
__device__ __forceinline__ void ldmx4(unsigned addr, unsigned* r) {
    asm volatile("ldmatrix.sync.aligned.m8n8.x4.shared.b16 {%0,%1,%2,%3}, [%4];"
                 : "=r"(r[0]), "=r"(r[1]), "=r"(r[2]), "=r"(r[3]) : "r"(addr));
}

extern __shared__ float4 smemv[];

__device__ __forceinline__ float getw0(const float* wih, const float* whh, int gate, int c) {
    if (c < FIN) return wih[gate * FIN + c];
    if (c < 16)  return 0.f;
    return whh[gate * HH + (c - 16)];
}
__device__ __forceinline__ float getw1(const float* wih, const float* whh, int gate, int c) {
    if (c < 64) return wih[gate * HH + c];
    return whh[gate * HH + (c - 64)];
}

// ================= fused 2-layer HMMA LSTM, software-pipelined =================
__global__ void __launch_bounds__(512, 1) k_lstm_fused(
    const float* __restrict__ inputs,
    const float* __restrict__ w_ih0, const float* __restrict__ w_hh0,
    const float* __restrict__ b_ih0, const float* __restrict__ b_hh0,
    const float* __restrict__ w_ih1, const float* __restrict__ w_hh1,
    const float* __restrict__ b_ih1, const float* __restrict__ b_hh1,
    const float* __restrict__ gat1_W, const float* __restrict__ gat1_as,
    const float* __restrict__ gat1_ad)
{
    char* smp = (char*)smemv;
    unsigned sbu = smem_u32(smemv);

    int tid  = threadIdx.x;
    int wid  = tid >> 5;
    int lane = tid & 31;
    int blk  = blockIdx.x;
    int n0   = blk * NB;

    {
        float4 z4 = make_float4(0.f, 0.f, 0.f, 0.f);
        float4* dst = (float4*)smp;
        for (int i = tid; i < 4 * ZSTRIDE / 16; i += 512) dst[i] = z4;
    }

    int q = lane >> 2, s = lane & 3;
    int gateA = (q >> 2) * 64 + 4 * wid + (q & 3);
    int gateB = gateA + 128;
    unsigned w0hi[5][4];
    #pragma unroll
    for (int kt = 0; kt < 5; ++kt) {
        int c = kt * 16 + s * 2;
        w0hi[kt][0] = packhi(getw0(w_ih0, w_hh0, gateA, c),     getw0(w_ih0, w_hh0, gateA, c + 1));
        w0hi[kt][1] = packhi(getw0(w_ih0, w_hh0, gateB, c),     getw0(w_ih0, w_hh0, gateB, c + 1));
        w0hi[kt][2] = packhi(getw0(w_ih0, w_hh0, gateA, c + 8), getw0(w_ih0, w_hh0, gateA, c + 9));
        w0hi[kt][3] = packhi(getw0(w_ih0, w_hh0, gateB, c + 8), getw0(w_ih0, w_hh0, gateB, c + 9));
    }
    unsigned w1hi[8][4], w1lo[8][4];
    #pragma unroll
    for (int kt = 0; kt < 8; ++kt) {
        int c = kt * 16 + s * 2;
        packsplit(getw1(w_ih1, w_hh1, gateA, c),     getw1(w_ih1, w_hh1, gateA, c + 1),
                  w1hi[kt][0], w1lo[kt][0]);
        packsplit(getw1(w_ih1, w_hh1, gateB, c),     getw1(w_ih1, w_hh1, gateB, c + 1),
                  w1hi[kt][1], w1lo[kt][1]);
        packsplit(getw1(w_ih1, w_hh1, gateA, c + 8), getw1(w_ih1, w_hh1, gateA, c + 9),
                  w1hi[kt][2], w1lo[kt][2]);
        packsplit(getw1(w_ih1, w_hh1, gateB, c + 8), getw1(w_ih1, w_hh1, gateB, c + 9),
                  w1hi[kt][3], w1lo[kt][3]);
    }
    float bA0 = b_ih0[gateA] + b_hh0[gateA], bB0 = b_ih0[gateB] + b_hh0[gateB];
    float bA1 = b_ih1[gateA] + b_hh1[gateA], bB1 = b_ih1[gateB] + b_hh1[gateB];

    float* xs = (float*)(smp + XS_OFF);
    for (int idx = tid; idx < NB * TT * FIN; idx += 512) {
        int nb = idx / (TT * FIN);
        int r  = idx % (TT * FIN);
        int t  = r / FIN, f = r % FIN;
        xs[t * 80 + f * 16 + nb] = inputs[(size_t)(n0 + nb) * (TT * FIN) + t * FIN + f];
    }
    if (tid < 80) {
        int f = tid >> 4, nb = tid & 15;
        *(__half*)(smp + Z0A + nb * ZROWB + f * 2) =
            __float2half_rn(inputs[(size_t)(n0 + nb) * (TT * FIN) + f]);
    }
    __syncthreads();

    int nrow  = (lane & 7) + ((lane >> 4) << 3);
    int khalf = (lane >> 3) & 1;
    unsigned zrel = nrow * ZROWB + khalf * 16;

    float* hfin = (float*)(smp + XS_OFF);
    int jp  = 4 * wid + (q & 3);
    int nbA = (q < 4) ? 2 * s : 8 + 2 * s;
    int nbB = nbA + 1;
    float c00 = 0.f, c01 = 0.f;
    float c10 = 0.f, c11 = 0.f;

    #pragma unroll 1
    for (int u = 0; u <= TT; ++u) {
        int p = u & 1;
        unsigned z0r = Z0A + p * ZSTRIDE,        z0w = Z0A + (p ^ 1) * ZSTRIDE;
        unsigned z1r = Z1A + (p ^ 1) * ZSTRIDE,  z1w = Z1A + p * ZSTRIDE;

        if (u < TT) {
            float acc[2][4];
            acc[0][0] = bA0; acc[0][1] = bA0; acc[0][2] = bB0; acc[0][3] = bB0;
            acc[1][0] = bA0; acc[1][1] = bA0; acc[1][2] = bB0; acc[1][3] = bB0;
            unsigned zb = sbu + z0r + zrel;
            #pragma unroll
            for (int kt = 0; kt < 5; ++kt) {
                unsigned bh[4];
                ldmx4(zb + kt * 32, bh);
                mma_f16(acc[0], w0hi[kt], bh[0], bh[1]);
                mma_f16(acc[1], w0hi[kt], bh[2], bh[3]);
            }
            float pp[8];
            #pragma unroll
            for (int i = 0; i < 4; ++i) {
                pp[i]     = __shfl_xor_sync(~0u, acc[0][i], 16);
                pp[4 + i] = __shfl_xor_sync(~0u, acc[1][i], 16);
            }
            float iA, fA, gA, oA, iB, fB, gB, oB;
            if (q < 4) {
                iA = acc[0][0]; gA = acc[0][2]; fA = pp[0]; oA = pp[2];
                iB = acc[0][1]; gB = acc[0][3]; fB = pp[1]; oB = pp[3];
            } else {
                iA = pp[4]; gA = pp[6]; fA = acc[1][0]; oA = acc[1][2];
                iB = pp[5]; gB = pp[7]; fB = acc[1][1]; oB = acc[1][3];
            }
            c00 = sigm(fA) * c00 + sigm(iA) * tanh_f(gA);
            c01 = sigm(fB) * c01 + sigm(iB) * tanh_f(gB);
            float h0A = sigm(oA) * tanh_f(c00);
            float h0B = sigm(oB) * tanh_f(c01);
            __half h0Ah = __float2half_rn(h0A), h0Bh = __float2half_rn(h0B);
            *(__half*)(smp + z0w + nbA * ZROWB + (16 + jp) * 2) = h0Ah;
            *(__half*)(smp + z0w + nbB * ZROWB + (16 + jp) * 2) = h0Bh;
            *(__half*)(smp + z1w + nbA * ZROWB + jp * 2) = h0Ah;
            *(__half*)(smp + z1w + nbB * ZROWB + jp * 2) = h0Bh;
            if (u + 1 < TT && tid < 80) {
                int f = tid >> 4, nb = tid & 15;
                *(__half*)(smp + z0w + nb * ZROWB + f * 2) =
                    __float2half_rn(xs[(u + 1) * 80 + f * 16 + nb]);
            }
        }

        if (u >= 1) {
            float acc[2][4];
            acc[0][0] = bA1; acc[0][1] = bA1; acc[0][2] = bB1; acc[0][3] = bB1;
            acc[1][0] = bA1; acc[1][1] = bA1; acc[1][2] = bB1; acc[1][3] = bB1;
            unsigned zb = sbu + z1r + zrel;
            #pragma unroll
            for (int kt = 0; kt < 8; ++kt) {
                unsigned bh[4];
                ldmx4(zb + kt * 32, bh);
                mma_f16(acc[0], w1hi[kt], bh[0], bh[1]);
                mma_f16(acc[1], w1hi[kt], bh[2], bh[3]);
                mma_f16(acc[0], w1lo[kt], bh[0], bh[1]);
                mma_f16(acc[1], w1lo[kt], bh[2], bh[3]);
            }
            float pp[8];
            #pragma unroll
            for (int i = 0; i < 4; ++i) {
                pp[i]     = __shfl_xor_sync(~0u, acc[0][i], 16);
                pp[4 + i] = __shfl_xor_sync(~0u, acc[1][i], 16);
            }
            float iA, fA, gA, oA, iB, fB, gB, oB;
            if (q < 4) {
                iA = acc[0][0]; gA = acc[0][2]; fA = pp[0]; oA = pp[2];
                iB = acc[0][1]; gB = acc[0][3]; fB = pp[1]; oB = pp[3];
            } else {
                iA = pp[4]; gA = pp[6]; fA = acc[1][0]; oA = acc[1][2];
                iB = pp[5]; gB = pp[7]; fB = acc[1][1]; oB = acc[1][3];
            }
            c10 = sigm(fA) * c10 + sigm(iA) * tanh_f(gA);
            c11 = sigm(fB) * c11 + sigm(iB) * tanh_f(gB);
            float h1A = sigm(oA) * tanh_f(c10);
            float h1B = sigm(oB) * tanh_f(c11);
            if (u == TT) {
                hfin[jp * 16 + nbA] = h1A;
                hfin[jp * 16 + nbB] = h1B;
            } else {
                *(__half*)(smp + z1w + nbA * ZROWB + (64 + jp) * 2) = __float2half_rn(h1A);
                *(__half*)(smp + z1w + nbB * ZROWB + (64 + jp) * 2) = __float2half_rn(h1B);
            }
        }
        __syncthreads();
    }

    // ---- fused GAT1 projection ----
    float* W1s = (float*)(smp + W1S_OFF);
    float* asv = (float*)(smp + ASV_OFF);
    float* adv = (float*)(smp + ADV_OFF);
    float* h1b = (float*)(smp + H1B_OFF);
    for (int idx = tid; idx < HH * 16; idx += 512) W1s[idx] = gat1_W[idx];
    if (tid < 32) {
        if (tid < 16) asv[tid] = gat1_as[tid];
        else          adv[tid - 16] = gat1_ad[tid - 16];
    }
    __syncthreads();
    if (tid < 256) {
        int nb = tid & 15, jj = tid >> 4;
        float hv = 0.f;
        #pragma unroll
        for (int k = 0; k < HH; ++k) hv += hfin[k * 16 + nb] * W1s[k * 16 + jj];
        h1b[nb * 16 + jj] = hv;
        g_h1[(size_t)(n0 + nb) * 16 + jj] = hv;
    }
    __syncthreads();
    if (tid < 32) {
        int nb = tid & 15;
        const float* av = (tid < 16) ? asv : adv;
        float sv = 0.f;
        #pragma unroll
        for (int jj = 0; jj < 16; ++jj) sv += h1b[nb * 16 + jj] * av[jj];
        if (tid < 16) g_s1[n0 + nb] = sv; else g_d1[n0 + nb] = sv;
    }
}

// ================= adjacency bitmask =================
__global__ void k_adj(const float* __restrict__ rel_mask) {
    int j  = blockIdx.x * 256 + threadIdx.x;
    int c0 = blockIdx.y * 4;
    for (int c = c0; c < c0 + 4; ++c) {
        unsigned w = 0;
        #pragma unroll 8
        for (int b = 0; b < 32; ++b) {
            int i = c * 32 + b;
            float v = rel_mask[(size_t)i * NN + j];
            if (v > -1.f || i == j) w |= (1u << b);
        }
        g_adjT[j * NWRD + c] = w;
    }
}

// ================= GAT1 aggregate + fused GAT2 projection + FC fold =================
// 4 j per block (256 thr); 2 warps per j; 1 adjacency word per lane. s1 in smem.
// Epilogue also computes y[j] = h2[j].fcW (FC is linear -> gmain2 only needs y).
__global__ void __launch_bounds__(256) k_gmain1(const float* __restrict__ b1,
                                                const float* __restrict__ W2,
                                                const float* __restrict__ as2,
                                                const float* __restrict__ ad2,
                                                const float* __restrict__ fcW)
{
    __shared__ float s1s[NN];
    __shared__ float W2s[16 * 64], a2s[64], a2d[64], fws[64];
    __shared__ float red[4][2][17];
    __shared__ float ob[4][16];
    int tid = threadIdx.x;
    for (int i = tid; i < NN; i += 256) s1s[i] = g_s1[i];
    for (int i = tid; i < 16 * 64; i += 256) W2s[i] = W2[i];
    if (tid < 64) { a2s[tid] = as2[tid]; a2d[tid] = ad2[tid]; fws[tid] = fcW[tid]; }
    __syncthreads();

    int warp = tid >> 5, lane = tid & 31;
    int jloc = warp >> 1, wh = warp & 1;
    int j = blockIdx.x * 4 + jloc;
    float dj = g_d1[j];

    int word = wh * 32 + lane;
    unsigned w = g_adjT[j * NWRD + word];
    float sum = 0.f, acc[16];
    #pragma unroll
    for (int h = 0; h < 16; ++h) acc[h] = 0.f;
    while (w) {
        int b = __ffs(w) - 1; w &= w - 1;
        int i = word * 32 + b;
        float al = __expf(lrelu(s1s[i] + dj));
        sum += al;
        const float4* hp = (const float4*)&g_h1[i * 16];
        float4 v0 = hp[0], v1 = hp[1], v2 = hp[2], v3 = hp[3];
        acc[0] += al * v0.x; acc[1] += al * v0.y; acc[2]  += al * v0.z; acc[3]  += al * v0.w;
        acc[4] += al * v1.x; acc[5] += al * v1.y; acc[6]  += al * v1.z; acc[7]  += al * v1.w;
        acc[8] += al * v2.x; acc[9] += al * v2.y; acc[10] += al * v2.z; acc[11] += al * v2.w;
        acc[12] += al * v3.x; acc[13] += al * v3.y; acc[14] += al * v3.z; acc[15] += al * v3.w;
    }
    #pragma unroll
    for (int o = 16; o; o >>= 1) sum += __shfl_xor_sync(~0u, sum, o);
    #pragma unroll
    for (int h = 0; h < 16; ++h) {
        #pragma unroll
        for (int o = 16; o; o >>= 1) acc[h] += __shfl_xor_sync(~0u, acc[h], o);
    }
    {
        int hsel = lane & 15;
        float vsel = acc[0];
        #pragma unroll
        for (int h = 1; h < 16; ++h) if (hsel == h) vsel = acc[h];
        if (lane < 16) red[jloc][wh][lane] = vsel;
        if (lane == 16) red[jloc][wh][16] = sum;
    }
    __syncthreads();

    if (wh == 0 && lane < 16) {
        float tot = red[jloc][0][lane] + red[jloc][1][lane];
        float S   = red[jloc][0][16] + red[jloc][1][16];
        float v = tot / S + b1[lane];
        ob[jloc][lane] = v > 0.f ? v : 0.f;
    }
    __syncthreads();

    if (wh == 0) {
        float o[16];
        #pragma unroll
        for (int k = 0; k < 16; ++k) o[k] = ob[jloc][k];
        float hv0 = 0.f, hv1 = 0.f;
        #pragma unroll
        for (int k = 0; k < 16; ++k) {
            hv0 += o[k] * W2s[k * 64 + lane];
            hv1 += o[k] * W2s[k * 64 + lane + 32];
        }
        float sp = hv0 * a2s[lane] + hv1 * a2s[lane + 32];
        float dp = hv0 * a2d[lane] + hv1 * a2d[lane + 32];
        float yp = hv0 * fws[lane] + hv1 * fws[lane + 32];
        #pragma unroll
        for (int oo = 16; oo; oo >>= 1) {
            sp += __shfl_xor_sync(~0u, sp, oo);
            dp += __shfl_xor_sync(~0u, dp, oo);
            yp += __shfl_xor_sync(~0u, yp, oo);
        }
        if (lane == 0) { g_s2[j] = sp; g_d2[j] = dp; g_y[j] = yp; }
    }
}

// ================= GAT2 aggregate (scalar, FC-folded) =================
// warp per j, 8 j per block; per edge: 2 smem loads + exp + 2 fma.
__global__ void __launch_bounds__(256) k_gmain2(const float* __restrict__ b2,
                                                const float* __restrict__ fcW,
                                                const float* __restrict__ fcb,
                                                float* __restrict__ out)
{
    __shared__ float s2s[NN], ys[NN];
    int tid = threadIdx.x;
    for (int i = tid; i < NN; i += 256) { s2s[i] = g_s2[i]; ys[i] = g_y[i]; }
    __syncthreads();

    int warp = tid >> 5, lane = tid & 31;
    int j = blockIdx.x * 8 + warp;
    float dj = g_d2[j];
    const unsigned* adjw = &g_adjT[j * NWRD];

    float num = 0.f, S = 0.f;
    #pragma unroll
    for (int cc = 0; cc < 2; ++cc) {
        unsigned w = adjw[lane * 2 + cc];
        int base = (lane * 2 + cc) * 32;
        while (w) {
            int b = __ffs(w) - 1; w &= w - 1;
            int i = base + b;
            float al = __expf(lrelu(s2s[i] + dj));
            S += al;
            num += al * ys[i];
        }
    }
    #pragma unroll
    for (int o = 16; o; o >>= 1) {
        num += __shfl_xor_sync(~0u, num, o);
        S   += __shfl_xor_sync(~0u, S, o);
    }
    if (lane == 0) {
        float bdot = 0.f;
        #pragma unroll 8
        for (int k = 0; k < 64; ++k) bdot += b2[k] * fcW[k];
        out[j] = lrelu(num / S + bdot + fcb[0]);
    }
}

// ================= launch =================
extern "C" void kernel_launch(void* const* d_in, const int* in_sizes, int n_in,
                              void* d_out, int out_size)
{
    const float* inputs   = (const float*)d_in[0];
    // d_in[1] relation, d_in[3] rel_w_W, d_in[4] rel_w_b: provably unused (adj = mask|diag)
    const float* rel_mask = (const float*)d_in[2];
    const float* w_ih0 = (const float*)d_in[5];
    const float* w_hh0 = (const float*)d_in[6];
    const float* b_ih0 = (const float*)d_in[7];
    const float* b_hh0 = (const float*)d_in[8];
    const float* w_ih1 = (const float*)d_in[9];
    const float* w_hh1 = (const float*)d_in[10];
    const float* b_ih1 = (const float*)d_in[11];
    const float* b_hh1 = (const float*)d_in[12];
    const float* gat1_W  = (const float*)d_in[13];
    const float* gat1_as = (const float*)d_in[14];
    const float* gat1_ad = (const float*)d_in[15];
    const float* gat1_b  = (const float*)d_in[16];
    const float* gat2_W  = (const float*)d_in[17];
    const float* gat2_as = (const float*)d_in[18];
    const float* gat2_ad = (const float*)d_in[19];
    const float* gat2_b  = (const float*)d_in[20];
    const float* fc_W    = (const float*)d_in[21];
    const float* fc_b    = (const float*)d_in[22];

    cudaFuncSetAttribute(k_lstm_fused, cudaFuncAttributeMaxDynamicSharedMemorySize, SMEM_REQ);

    k_adj<<<dim3(8, 16), 256>>>(rel_mask);
    k_lstm_fused<<<NBLK, 512, SMEM_REQ>>>(inputs, w_ih0, w_hh0, b_ih0, b_hh0,
                                          w_ih1, w_hh1, b_ih1, b_hh1,
                                          gat1_W, gat1_as, gat1_ad);
    k_gmain1<<<NN / 4, 256>>>(gat1_b, gat2_W, gat2_as, gat2_ad, fc_W);
    k_gmain2<<<NN / 8, 256>>>(gat2_b, fc_W, fc_b, (float*)d_out);
}

// round 17
// speedup vs baseline: 2.6501x; 1.0349x over previous
#include <cuda_runtime.h>
#include <cuda_fp16.h>

#define NN   2048
#define TT   32
#define FIN  5
#define HH   64
#define NB   16
#define NBLK 128
#define NWRD 64

// ---- smem layout: fused LSTM ----
#define ZROWB    272
#define Z0A      0
#define Z1A      8704
#define ZSTRIDE  4352
#define XS_OFF   17408
#define SMEM_REQ 28672
// post-loop GAT aliases:
#define W1S_OFF  0
#define ASV_OFF  4096
#define ADV_OFF  4160
#define H1B_OFF  4224

// -------- scratch (device globals) --------
__device__ unsigned g_adjT[NN * NWRD];
__device__ float g_h1[NN * 16];
__device__ float g_s1[NN], g_d1[NN];
__device__ float g_y[NN];               // y[i] = h2[i] . fcW
__device__ float g_s2[NN], g_d2[NN];

// -------- helpers --------
__device__ __forceinline__ unsigned smem_u32(const void* p) {
    unsigned a;
    asm("{ .reg .u64 t; cvta.to.shared.u64 t, %1; cvt.u32.u64 %0, t; }" : "=r"(a) : "l"(p));
    return a;
}
__device__ __forceinline__ float sigm(float x)   { return 1.f / (1.f + __expf(-x)); }
__device__ __forceinline__ float tanh_f(float x) { return 1.f - 2.f / (__expf(2.f * x) + 1.f); }
__device__ __forceinline__ float lrelu(float x)  { return x >= 0.f ? x : 0.2f * x; }

__device__ __forceinline__ unsigned packhi(float w0, float w1) {
    return (unsigned)__half_as_ushort(__float2half_rn(w0))
         | ((unsigned)__half_as_ushort(__float2half_rn(w1)) << 16);
}
__device__ __forceinline__ void packsplit(float w0, float w1, unsigned& hi, unsigned& lo) {
    __half h0 = __float2half_rn(w0), h1 = __float2half_rn(w1);
    __half l0 = __float2half_rn(w0 - __half2float(h0));
    __half l1 = __float2half_rn(w1 - __half2float(h1));
    hi = (unsigned)__half_as_ushort(h0) | ((unsigned)__half_as_ushort(h1) << 16);
    lo = (unsigned)__half_as_ushort(l0) | ((unsigned)__half_as_ushort(l1) << 16);
}
__device__ __forceinline__ void mma_f16(float* d, const unsigned* a, unsigned b0, unsigned b1) {
    asm volatile(
        "mma.sync.aligned.m16n8k16.row.col.f32.f16.f16.f32 "
        "{%0,%1,%2,%3}, {%4,%5,%6,%7}, {%8,%9}, {%0,%1,%2,%3};"
        : "+f"(d[0]), "+f"(d[1]), "+f"(d[2]), "+f"(d[3])
        : "r"(a[0]), "r"(a[1]), "r"(a[2]), "r"(a[3]), "r"(b0), "r"(b1));
}
__device__ __forceinline__ void ldmx4(unsigned addr, unsigned* r) {
    asm volatile("ldmatrix.sync.aligned.m8n8.x4.shared.b16 {%0,%1,%2,%3}, [%4];"
                 : "=r"(r[0]), "=r"(r[1]), "=r"(r[2]), "=r"(r[3]) : "r"(addr));
}

extern __shared__ float4 smemv[];

__device__ __forceinline__ float getw0(const float* wih, const float* whh, int gate, int c) {
    if (c < FIN) return wih[gate * FIN + c];
    if (c < 16)  return 0.f;
    return whh[gate * HH + (c - 16)];
}
__device__ __forceinline__ float getw1(const float* wih, const float* whh, int gate, int c) {
    if (c < 64) return wih[gate * HH + c];
    return whh[gate * HH + (c - 64)];
}

// ================= fused 2-layer HMMA LSTM (L0: hi-only, L1: hi+lo 2-pass) =================
__global__ void __launch_bounds__(512, 1) k_lstm_fused(
    const float* __restrict__ inputs,
    const float* __restrict__ w_ih0, const float* __restrict__ w_hh0,
    const float* __restrict__ b_ih0, const float* __restrict__ b_hh0,
    const float* __restrict__ w_ih1, const float* __restrict__ w_hh1,
    const float* __restrict__ b_ih1, const float* __restrict__ b_hh1,
    const float* __restrict__ gat1_W, const float* __restrict__ gat1_as,
    const float* __restrict__ gat1_ad)
{
    char* smp = (char*)smemv;
    unsigned sbu = smem_u32(smemv);

    int tid  = threadIdx.x;
    int wid  = tid >> 5;
    int lane = tid & 31;
    int blk  = blockIdx.x;
    int n0   = blk * NB;

    {
        float4 z4 = make_float4(0.f, 0.f, 0.f, 0.f);
        float4* dst = (float4*)smp;
        for (int i = tid; i < 4 * ZSTRIDE / 16; i += 512) dst[i] = z4;
    }

    int q = lane >> 2, s = lane & 3;
    int gateA = (q >> 2) * 64 + 4 * wid + (q & 3);
    int gateB = gateA + 128;
    unsigned w0hi[5][4];
    #pragma unroll
    for (int kt = 0; kt < 5; ++kt) {
        int c = kt * 16 + s * 2;
        w0hi[kt][0] = packhi(getw0(w_ih0, w_hh0, gateA, c),     getw0(w_ih0, w_hh0, gateA, c + 1));
        w0hi[kt][1] = packhi(getw0(w_ih0, w_hh0, gateB, c),     getw0(w_ih0, w_hh0, gateB, c + 1));
        w0hi[kt][2] = packhi(getw0(w_ih0, w_hh0, gateA, c + 8), getw0(w_ih0, w_hh0, gateA, c + 9));
        w0hi[kt][3] = packhi(getw0(w_ih0, w_hh0, gateB, c + 8), getw0(w_ih0, w_hh0, gateB, c + 9));
    }
    unsigned w1hi[8][4], w1lo[8][4];
    #pragma unroll
    for (int kt = 0; kt < 8; ++kt) {
        int c = kt * 16 + s * 2;
        packsplit(getw1(w_ih1, w_hh1, gateA, c),     getw1(w_ih1, w_hh1, gateA, c + 1),
                  w1hi[kt][0], w1lo[kt][0]);
        packsplit(getw1(w_ih1, w_hh1, gateB, c),     getw1(w_ih1, w_hh1, gateB, c + 1),
                  w1hi[kt][1], w1lo[kt][1]);
        packsplit(getw1(w_ih1, w_hh1, gateA, c + 8), getw1(w_ih1, w_hh1, gateA, c + 9),
                  w1hi[kt][2], w1lo[kt][2]);
        packsplit(getw1(w_ih1, w_hh1, gateB, c + 8), getw1(w_ih1, w_hh1, gateB, c + 9),
                  w1hi[kt][3], w1lo[kt][3]);
    }
    float bA0 = b_ih0[gateA] + b_hh0[gateA], bB0 = b_ih0[gateB] + b_hh0[gateB];
    float bA1 = b_ih1[gateA] + b_hh1[gateA], bB1 = b_ih1[gateB] + b_hh1[gateB];

    float* xs = (float*)(smp + XS_OFF);
    for (int idx = tid; idx < NB * TT * FIN; idx += 512) {
        int nb = idx / (TT * FIN);
        int r  = idx % (TT * FIN);
        int t  = r / FIN, f = r % FIN;
        xs[t * 80 + f * 16 + nb] = inputs[(size_t)(n0 + nb) * (TT * FIN) + t * FIN + f];
    }
    if (tid < 80) {
        int f = tid >> 4, nb = tid & 15;
        *(__half*)(smp + Z0A + nb * ZROWB + f * 2) =
            __float2half_rn(inputs[(size_t)(n0 + nb) * (TT * FIN) + f]);
    }
    __syncthreads();

    int nrow  = (lane & 7) + ((lane >> 4) << 3);
    int khalf = (lane >> 3) & 1;
    unsigned zrel = nrow * ZROWB + khalf * 16;

    float* hfin = (float*)(smp + XS_OFF);
    int jp  = 4 * wid + (q & 3);
    int nbA = (q < 4) ? 2 * s : 8 + 2 * s;
    int nbB = nbA + 1;
    float c00 = 0.f, c01 = 0.f;
    float c10 = 0.f, c11 = 0.f;

    #pragma unroll 1
    for (int u = 0; u <= TT; ++u) {
        int p = u & 1;
        unsigned z0r = Z0A + p * ZSTRIDE,        z0w = Z0A + (p ^ 1) * ZSTRIDE;
        unsigned z1r = Z1A + (p ^ 1) * ZSTRIDE,  z1w = Z1A + p * ZSTRIDE;

        if (u < TT) {
            float acc[2][4];
            acc[0][0] = bA0; acc[0][1] = bA0; acc[0][2] = bB0; acc[0][3] = bB0;
            acc[1][0] = bA0; acc[1][1] = bA0; acc[1][2] = bB0; acc[1][3] = bB0;
            unsigned zb = sbu + z0r + zrel;
            #pragma unroll
            for (int kt = 0; kt < 5; ++kt) {
                unsigned bh[4];
                ldmx4(zb + kt * 32, bh);
                mma_f16(acc[0], w0hi[kt], bh[0], bh[1]);
                mma_f16(acc[1], w0hi[kt], bh[2], bh[3]);
            }
            float pp[8];
            #pragma unroll
            for (int i = 0; i < 4; ++i) {
                pp[i]     = __shfl_xor_sync(~0u, acc[0][i], 16);
                pp[4 + i] = __shfl_xor_sync(~0u, acc[1][i], 16);
            }
            float iA, fA, gA, oA, iB, fB, gB, oB;
            if (q < 4) {
                iA = acc[0][0]; gA = acc[0][2]; fA = pp[0]; oA = pp[2];
                iB = acc[0][1]; gB = acc[0][3]; fB = pp[1]; oB = pp[3];
            } else {
                iA = pp[4]; gA = pp[6]; fA = acc[1][0]; oA = acc[1][2];
                iB = pp[5]; gB = pp[7]; fB = acc[1][1]; oB = acc[1][3];
            }
            c00 = sigm(fA) * c00 + sigm(iA) * tanh_f(gA);
            c01 = sigm(fB) * c01 + sigm(iB) * tanh_f(gB);
            float h0A = sigm(oA) * tanh_f(c00);
            float h0B = sigm(oB) * tanh_f(c01);
            __half h0Ah = __float2half_rn(h0A), h0Bh = __float2half_rn(h0B);
            *(__half*)(smp + z0w + nbA * ZROWB + (16 + jp) * 2) = h0Ah;
            *(__half*)(smp + z0w + nbB * ZROWB + (16 + jp) * 2) = h0Bh;
            *(__half*)(smp + z1w + nbA * ZROWB + jp * 2) = h0Ah;
            *(__half*)(smp + z1w + nbB * ZROWB + jp * 2) = h0Bh;
            if (u + 1 < TT && tid < 80) {
                int f = tid >> 4, nb = tid & 15;
                *(__half*)(smp + z0w + nb * ZROWB + f * 2) =
                    __float2half_rn(xs[(u + 1) * 80 + f * 16 + nb]);
            }
        }

        if (u >= 1) {
            float acc[2][4];
            acc[0][0] = bA1; acc[0][1] = bA1; acc[0][2] = bB1; acc[0][3] = bB1;
            acc[1][0] = bA1; acc[1][1] = bA1; acc[1][2] = bB1; acc[1][3] = bB1;
            unsigned zb = sbu + z1r + zrel;
            #pragma unroll
            for (int kt = 0; kt < 8; ++kt) {
                unsigned bh[4];
                ldmx4(zb + kt * 32, bh);
                mma_f16(acc[0], w1hi[kt], bh[0], bh[1]);
                mma_f16(acc[1], w1hi[kt], bh[2], bh[3]);
                mma_f16(acc[0], w1lo[kt], bh[0], bh[1]);
                mma_f16(acc[1], w1lo[kt], bh[2], bh[3]);
            }
            float pp[8];
            #pragma unroll
            for (int i = 0; i < 4; ++i) {
                pp[i]     = __shfl_xor_sync(~0u, acc[0][i], 16);
                pp[4 + i] = __shfl_xor_sync(~0u, acc[1][i], 16);
            }
            float iA, fA, gA, oA, iB, fB, gB, oB;
            if (q < 4) {
                iA = acc[0][0]; gA = acc[0][2]; fA = pp[0]; oA = pp[2];
                iB = acc[0][1]; gB = acc[0][3]; fB = pp[1]; oB = pp[3];
            } else {
                iA = pp[4]; gA = pp[6]; fA = acc[1][0]; oA = acc[1][2];
                iB = pp[5]; gB = pp[7]; fB = acc[1][1]; oB = acc[1][3];
            }
            c10 = sigm(fA) * c10 + sigm(iA) * tanh_f(gA);
            c11 = sigm(fB) * c11 + sigm(iB) * tanh_f(gB);
            float h1A = sigm(oA) * tanh_f(c10);
            float h1B = sigm(oB) * tanh_f(c11);
            if (u == TT) {
                hfin[jp * 16 + nbA] = h1A;
                hfin[jp * 16 + nbB] = h1B;
            } else {
                *(__half*)(smp + z1w + nbA * ZROWB + (64 + jp) * 2) = __float2half_rn(h1A);
                *(__half*)(smp + z1w + nbB * ZROWB + (64 + jp) * 2) = __float2half_rn(h1B);
            }
        }
        __syncthreads();
    }

    // ---- fused GAT1 projection ----
    float* W1s = (float*)(smp + W1S_OFF);
    float* asv = (float*)(smp + ASV_OFF);
    float* adv = (float*)(smp + ADV_OFF);
    float* h1b = (float*)(smp + H1B_OFF);
    for (int idx = tid; idx < HH * 16; idx += 512) W1s[idx] = gat1_W[idx];
    if (tid < 32) {
        if (tid < 16) asv[tid] = gat1_as[tid];
        else          adv[tid - 16] = gat1_ad[tid - 16];
    }
    __syncthreads();
    if (tid < 256) {
        int nb = tid & 15, jj = tid >> 4;
        float hv = 0.f;
        #pragma unroll
        for (int k = 0; k < HH; ++k) hv += hfin[k * 16 + nb] * W1s[k * 16 + jj];
        h1b[nb * 16 + jj] = hv;
        g_h1[(size_t)(n0 + nb) * 16 + jj] = hv;
    }
    __syncthreads();
    if (tid < 32) {
        int nb = tid & 15;
        const float* av = (tid < 16) ? asv : adv;
        float sv = 0.f;
        #pragma unroll
        for (int jj = 0; jj < 16; ++jj) sv += h1b[nb * 16 + jj] * av[jj];
        if (tid < 16) g_s1[n0 + nb] = sv; else g_d1[n0 + nb] = sv;
    }
}

// ================= adjacency bitmask =================
__global__ void k_adj(const float* __restrict__ rel_mask) {
    int j  = blockIdx.x * 256 + threadIdx.x;
    int c0 = blockIdx.y * 4;
    for (int c = c0; c < c0 + 4; ++c) {
        unsigned w = 0;
        #pragma unroll 8
        for (int b = 0; b < 32; ++b) {
            int i = c * 32 + b;
            float v = rel_mask[(size_t)i * NN + j];
            if (v > -1.f || i == j) w |= (1u << b);
        }
        g_adjT[j * NWRD + c] = w;
    }
}

// ================= GAT1 aggregate + fused GAT2 projection + FC fold =================
// 512 thr, 8 j per block; 2 warps per j; 1 adjacency word per lane. s1 in smem.
__global__ void __launch_bounds__(512) k_gmain1(const float* __restrict__ b1,
                                                const float* __restrict__ W2,
                                                const float* __restrict__ as2,
                                                const float* __restrict__ ad2,
                                                const float* __restrict__ fcW)
{
    __shared__ float s1s[NN];
    __shared__ float W2s[16 * 64], a2s[64], a2d[64], fws[64];
    __shared__ float red[8][2][17];
    __shared__ float ob[8][16];
    int tid = threadIdx.x;
    for (int i = tid; i < NN; i += 512) s1s[i] = g_s1[i];
    for (int i = tid; i < 16 * 64; i += 512) W2s[i] = W2[i];
    if (tid < 64) { a2s[tid] = as2[tid]; a2d[tid] = ad2[tid]; fws[tid] = fcW[tid]; }
    __syncthreads();

    int warp = tid >> 5, lane = tid & 31;
    int jloc = warp >> 1, wh = warp & 1;
    int j = blockIdx.x * 8 + jloc;
    float dj = g_d1[j];

    int word = wh * 32 + lane;
    unsigned w = g_adjT[j * NWRD + word];
    float sum = 0.f, acc[16];
    #pragma unroll
    for (int h = 0; h < 16; ++h) acc[h] = 0.f;
    while (w) {
        int b = __ffs(w) - 1; w &= w - 1;
        int i = word * 32 + b;
        float al = __expf(lrelu(s1s[i] + dj));
        sum += al;
        const float4* hp = (const float4*)&g_h1[i * 16];
        float4 v0 = hp[0], v1 = hp[1], v2 = hp[2], v3 = hp[3];
        acc[0] += al * v0.x; acc[1] += al * v0.y; acc[2]  += al * v0.z; acc[3]  += al * v0.w;
        acc[4] += al * v1.x; acc[5] += al * v1.y; acc[6]  += al * v1.z; acc[7]  += al * v1.w;
        acc[8] += al * v2.x; acc[9] += al * v2.y; acc[10] += al * v2.z; acc[11] += al * v2.w;
        acc[12] += al * v3.x; acc[13] += al * v3.y; acc[14] += al * v3.z; acc[15] += al * v3.w;
    }
    #pragma unroll
    for (int o = 16; o; o >>= 1) sum += __shfl_xor_sync(~0u, sum, o);
    #pragma unroll
    for (int h = 0; h < 16; ++h) {
        #pragma unroll
        for (int o = 16; o; o >>= 1) acc[h] += __shfl_xor_sync(~0u, acc[h], o);
    }
    {
        int hsel = lane & 15;
        float vsel = acc[0];
        #pragma unroll
        for (int h = 1; h < 16; ++h) if (hsel == h) vsel = acc[h];
        if (lane < 16) red[jloc][wh][lane] = vsel;
        if (lane == 16) red[jloc][wh][16] = sum;
    }
    __syncthreads();

    if (wh == 0 && lane < 16) {
        float tot = red[jloc][0][lane] + red[jloc][1][lane];
        float S   = red[jloc][0][16] + red[jloc][1][16];
        float v = tot / S + b1[lane];
        ob[jloc][lane] = v > 0.f ? v : 0.f;
    }
    __syncthreads();

    if (wh == 0) {
        float o[16];
        #pragma unroll
        for (int k = 0; k < 16; ++k) o[k] = ob[jloc][k];
        float hv0 = 0.f, hv1 = 0.f;
        #pragma unroll
        for (int k = 0; k < 16; ++k) {
            hv0 += o[k] * W2s[k * 64 + lane];
            hv1 += o[k] * W2s[k * 64 + lane + 32];
        }
        float sp = hv0 * a2s[lane] + hv1 * a2s[lane + 32];
        float dp = hv0 * a2d[lane] + hv1 * a2d[lane + 32];
        float yp = hv0 * fws[lane] + hv1 * fws[lane + 32];
        #pragma unroll
        for (int oo = 16; oo; oo >>= 1) {
            sp += __shfl_xor_sync(~0u, sp, oo);
            dp += __shfl_xor_sync(~0u, dp, oo);
            yp += __shfl_xor_sync(~0u, yp, oo);
        }
        if (lane == 0) { g_s2[j] = sp; g_d2[j] = dp; g_y[j] = yp; }
    }
}

// ================= GAT2 aggregate (scalar, FC-folded) =================
// 512 thr, warp per j, 16 j per block; per edge: 2 smem loads + exp + 2 fma.
__global__ void __launch_bounds__(512) k_gmain2(const float* __restrict__ b2,
                                                const float* __restrict__ fcW,
                                                const float* __restrict__ fcb,
                                                float* __restrict__ out)
{
    __shared__ float s2s[NN], ys[NN];
    __shared__ float bdot_s;
    int tid = threadIdx.x;
    for (int i = tid; i < NN; i += 512) { s2s[i] = g_s2[i]; ys[i] = g_y[i]; }
    if (tid < 32) {
        float v = b2[tid] * fcW[tid] + b2[tid + 32] * fcW[tid + 32];
        #pragma unroll
        for (int o = 16; o; o >>= 1) v += __shfl_xor_sync(~0u, v, o);
        if (tid == 0) bdot_s = v;
    }
    __syncthreads();

    int warp = tid >> 5, lane = tid & 31;
    int j = blockIdx.x * 16 + warp;
    float dj = g_d2[j];
    const unsigned* adjw = &g_adjT[j * NWRD];

    float num = 0.f, S = 0.f;
    #pragma unroll
    for (int cc = 0; cc < 2; ++cc) {
        unsigned w = adjw[lane * 2 + cc];
        int base = (lane * 2 + cc) * 32;
        while (w) {
            int b = __ffs(w) - 1; w &= w - 1;
            int i = base + b;
            float al = __expf(lrelu(s2s[i] + dj));
            S += al;
            num += al * ys[i];
        }
    }
    #pragma unroll
    for (int o = 16; o; o >>= 1) {
        num += __shfl_xor_sync(~0u, num, o);
        S   += __shfl_xor_sync(~0u, S, o);
    }
    if (lane == 0) out[j] = lrelu(num / S + bdot_s + fcb[0]);
}

// ================= launch =================
extern "C" void kernel_launch(void* const* d_in, const int* in_sizes, int n_in,
                              void* d_out, int out_size)
{
    const float* inputs   = (const float*)d_in[0];
    // d_in[1] relation, d_in[3] rel_w_W, d_in[4] rel_w_b: provably unused (adj = mask|diag)
    const float* rel_mask = (const float*)d_in[2];
    const float* w_ih0 = (const float*)d_in[5];
    const float* w_hh0 = (const float*)d_in[6];
    const float* b_ih0 = (const float*)d_in[7];
    const float* b_hh0 = (const float*)d_in[8];
    const float* w_ih1 = (const float*)d_in[9];
    const float* w_hh1 = (const float*)d_in[10];
    const float* b_ih1 = (const float*)d_in[11];
    const float* b_hh1 = (const float*)d_in[12];
    const float* gat1_W  = (const float*)d_in[13];
    const float* gat1_as = (const float*)d_in[14];
    const float* gat1_ad = (const float*)d_in[15];
    const float* gat1_b  = (const float*)d_in[16];
    const float* gat2_W  = (const float*)d_in[17];
    const float* gat2_as = (const float*)d_in[18];
    const float* gat2_ad = (const float*)d_in[19];
    const float* gat2_b  = (const float*)d_in[20];
    const float* fc_W    = (const float*)d_in[21];
    const float* fc_b    = (const float*)d_in[22];

    cudaFuncSetAttribute(k_lstm_fused, cudaFuncAttributeMaxDynamicSharedMemorySize, SMEM_REQ);

    k_adj<<<dim3(8, 16), 256>>>(rel_mask);
    k_lstm_fused<<<NBLK, 512, SMEM_REQ>>>(inputs, w_ih0, w_hh0, b_ih0, b_hh0,
                                          w_ih1, w_hh1, b_ih1, b_hh1,
                                          gat1_W, gat1_as, gat1_ad);
    k_gmain1<<<NN / 8, 512>>>(gat1_b, gat2_W, gat2_as, gat2_ad, fc_W);
    k_gmain2<<<NN / 16, 512>>>(gat2_b, fc_W, fc_b, (float*)d_out);
}